// round 5
// baseline (speedup 1.0000x reference)
#include <cuda_runtime.h>
#include <cuda_bf16.h>
#include <math.h>
#include <stdint.h>

// Problem constants
#define BATCH 4
#define SEQ   2048
#define EMB   1024     // H * Dk
#define HEADS 16
#define KDIM  64
#define PROJK 256
#define MROWS (BATCH * SEQ)   // 8192

// ---------------- scratch (allocation-free) ----------------
// g_k doubles as ctx: k is fully consumed by proj before attn writes ctx.
__device__ float g_q  [MROWS * EMB];
__device__ float g_k  [MROWS * EMB];
__device__ float g_v  [MROWS * EMB];
__device__ float g_kp [BATCH * PROJK * EMB];
__device__ float g_vp [BATCH * PROJK * EMB];

// ================================================================
// bf16x3 split tensor-core GEMM
//   C = (A @ B + bias) * alpha   with fp32-equivalent precision:
//   a = a_hi + a_lo (bf16), b = b_hi + b_lo (bf16)
//   C ~= sum a_hi*b_hi + a_hi*b_lo + a_lo*b_hi   (error ~2^-17)
// CTA tile 128x128, BK=32, 256 threads (8 warps, 2x4 warp grid,
// warp tile 64x32). mma.sync.m16n8k16.bf16, fp32 accum.
// A_TRANS: A[m][k] = A[k*ldA + m] (Linformer E matrix)
// BIAS_ROW: bias indexed by m instead of n.
// ================================================================
__device__ __forceinline__ uint32_t bf16bits(__nv_bfloat16 h) {
    return (uint32_t)__bfloat16_as_ushort(h);
}
__device__ __forceinline__ void split2(float v0, float v1, uint32_t& h, uint32_t& l) {
    __nv_bfloat16 h0 = __float2bfloat16(v0);
    __nv_bfloat16 h1 = __float2bfloat16(v1);
    __nv_bfloat16 l0 = __float2bfloat16(v0 - __bfloat162float(h0));
    __nv_bfloat16 l1 = __float2bfloat16(v1 - __bfloat162float(h1));
    h = (bf16bits(h1) << 16) | bf16bits(h0);
    l = (bf16bits(l1) << 16) | bf16bits(l0);
}
__device__ __forceinline__ void split1(float v, unsigned short& h, unsigned short& l) {
    __nv_bfloat16 hh = __float2bfloat16(v);
    __nv_bfloat16 ll = __float2bfloat16(v - __bfloat162float(hh));
    h = __bfloat16_as_ushort(hh);
    l = __bfloat16_as_ushort(ll);
}

#define MMA_BF16(d, a, b) asm volatile( \
    "mma.sync.aligned.m16n8k16.row.col.f32.bf16.bf16.f32 " \
    "{%0,%1,%2,%3}, {%4,%5,%6,%7}, {%8,%9}, {%0,%1,%2,%3};\n" \
    : "+f"((d)[0]), "+f"((d)[1]), "+f"((d)[2]), "+f"((d)[3]) \
    : "r"((a)[0]), "r"((a)[1]), "r"((a)[2]), "r"((a)[3]), \
      "r"((b)[0]), "r"((b)[1]))

#define SLD 20   // u32 stride of smem tiles (16 data words + 4 pad)

template<bool A_TRANS, bool BIAS_ROW>
__global__ __launch_bounds__(256)
void mma_gemm_kernel(const float* __restrict__ A, long long strideA, int ldA,
                     const float* __restrict__ B, long long strideB,
                     const float* __restrict__ bias,
                     float* __restrict__ C, long long strideC,
                     int N, int K, float alpha)
{
    __shared__ uint32_t As_hi[128 * SLD];
    __shared__ uint32_t As_lo[128 * SLD];
    __shared__ uint32_t Bs_hi[128 * SLD];
    __shared__ uint32_t Bs_lo[128 * SLD];

    const int tid  = threadIdx.x;
    const int wid  = tid >> 5;
    const int lane = tid & 31;
    const int gid  = lane >> 2;   // 0..7
    const int tig  = lane & 3;    // 0..3
    const int wm   = wid >> 2;    // 0..1
    const int wn   = wid & 3;     // 0..3
    const int m0   = blockIdx.y * 128;
    const int n0   = blockIdx.x * 128;

    const float* Ab = A + strideA * blockIdx.z;
    const float* Bb = B + strideB * blockIdx.z;
    float*       Cb = C + strideC * blockIdx.z;

    float c[4][4][4];
#pragma unroll
    for (int i = 0; i < 4; i++)
#pragma unroll
        for (int j = 0; j < 4; j++)
#pragma unroll
            for (int l = 0; l < 4; l++) c[i][j][l] = 0.f;

    float4 pa[4], pb[4];

    // ---- prologue: load first k-tile into registers ----
#pragma unroll
    for (int i = 0; i < 4; i++) {
        int f = i * 256 + tid;
        if (!A_TRANS) {
            int row = f >> 3, kq = (f & 7) * 4;
            pa[i] = *(const float4*)(Ab + (size_t)(m0 + row) * ldA + kq);
        } else {
            int kr = f >> 5, mq = (f & 31) * 4;
            pa[i] = *(const float4*)(Ab + (size_t)kr * ldA + m0 + mq);
        }
        int kr = f >> 5, nq = (f & 31) * 4;
        pb[i] = *(const float4*)(Bb + (size_t)kr * N + n0 + nq);
    }

    for (int k0 = 0; k0 < K; k0 += 32) {
        // ---- store current tile to smem with hi/lo split ----
        if (!A_TRANS) {
#pragma unroll
            for (int i = 0; i < 4; i++) {
                int f = i * 256 + tid;
                int row = f >> 3, kq = (f & 7) * 4;
                uint32_t h01, l01, h23, l23;
                split2(pa[i].x, pa[i].y, h01, l01);
                split2(pa[i].z, pa[i].w, h23, l23);
                As_hi[row * SLD + (kq >> 1)]     = h01;
                As_hi[row * SLD + (kq >> 1) + 1] = h23;
                As_lo[row * SLD + (kq >> 1)]     = l01;
                As_lo[row * SLD + (kq >> 1) + 1] = l23;
            }
        } else {
            unsigned short* ah = (unsigned short*)As_hi;
            unsigned short* al = (unsigned short*)As_lo;
#pragma unroll
            for (int i = 0; i < 4; i++) {
                int f = i * 256 + tid;
                int kr = f >> 5, mq = (f & 31) * 4;
                float v[4] = {pa[i].x, pa[i].y, pa[i].z, pa[i].w};
#pragma unroll
                for (int j = 0; j < 4; j++) {
                    unsigned short h, l;
                    split1(v[j], h, l);
                    ah[(mq + j) * (2 * SLD) + kr] = h;
                    al[(mq + j) * (2 * SLD) + kr] = l;
                }
            }
        }
        {
            unsigned short* bh = (unsigned short*)Bs_hi;
            unsigned short* bl = (unsigned short*)Bs_lo;
#pragma unroll
            for (int i = 0; i < 4; i++) {
                int f = i * 256 + tid;
                int kr = f >> 5, nq = (f & 31) * 4;
                float v[4] = {pb[i].x, pb[i].y, pb[i].z, pb[i].w};
#pragma unroll
                for (int j = 0; j < 4; j++) {
                    unsigned short h, l;
                    split1(v[j], h, l);
                    bh[(nq + j) * (2 * SLD) + kr] = h;
                    bl[(nq + j) * (2 * SLD) + kr] = l;
                }
            }
        }
        __syncthreads();

        // ---- prefetch next tile (overlaps tensor work) ----
        if (k0 + 32 < K) {
#pragma unroll
            for (int i = 0; i < 4; i++) {
                int f = i * 256 + tid;
                if (!A_TRANS) {
                    int row = f >> 3, kq = (f & 7) * 4;
                    pa[i] = *(const float4*)(Ab + (size_t)(m0 + row) * ldA + (k0 + 32) + kq);
                } else {
                    int kr = f >> 5, mq = (f & 31) * 4;
                    pa[i] = *(const float4*)(Ab + (size_t)(k0 + 32 + kr) * ldA + m0 + mq);
                }
                int kr = f >> 5, nq = (f & 31) * 4;
                pb[i] = *(const float4*)(Bb + (size_t)(k0 + 32 + kr) * N + n0 + nq);
            }
        }

        // ---- compute: 2 k16 steps, 3 mma per (mt,nt) ----
#pragma unroll
        for (int kt = 0; kt < 2; kt++) {
            const int kb = kt * 8;
            uint32_t ah[4][4], al2[4][4];
#pragma unroll
            for (int mt = 0; mt < 4; mt++) {
                int r0 = (wm * 64 + mt * 16 + gid) * SLD;
                ah[mt][0]  = As_hi[r0 + kb + tig];
                ah[mt][1]  = As_hi[r0 + 8 * SLD + kb + tig];
                ah[mt][2]  = As_hi[r0 + kb + 4 + tig];
                ah[mt][3]  = As_hi[r0 + 8 * SLD + kb + 4 + tig];
                al2[mt][0] = As_lo[r0 + kb + tig];
                al2[mt][1] = As_lo[r0 + 8 * SLD + kb + tig];
                al2[mt][2] = As_lo[r0 + kb + 4 + tig];
                al2[mt][3] = As_lo[r0 + 8 * SLD + kb + 4 + tig];
            }
            uint32_t bh[4][2], bl2[4][2];
#pragma unroll
            for (int nt = 0; nt < 4; nt++) {
                int c0i = (wn * 32 + nt * 8 + gid) * SLD;
                bh[nt][0]  = Bs_hi[c0i + kb + tig];
                bh[nt][1]  = Bs_hi[c0i + kb + 4 + tig];
                bl2[nt][0] = Bs_lo[c0i + kb + tig];
                bl2[nt][1] = Bs_lo[c0i + kb + 4 + tig];
            }
#pragma unroll
            for (int mt = 0; mt < 4; mt++)
#pragma unroll
                for (int nt = 0; nt < 4; nt++) {
                    MMA_BF16(c[mt][nt], ah[mt], bh[nt]);
                    MMA_BF16(c[mt][nt], ah[mt], bl2[nt]);
                    MMA_BF16(c[mt][nt], al2[mt], bh[nt]);
                }
        }
        __syncthreads();
    }

    // ---- epilogue: bias + alpha ----
#pragma unroll
    for (int mt = 0; mt < 4; mt++) {
        int row = m0 + wm * 64 + mt * 16 + gid;
#pragma unroll
        for (int nt = 0; nt < 4; nt++) {
            int col = n0 + wn * 32 + nt * 8 + tig * 2;
            float b00, b01, b10, b11;
            if (BIAS_ROW) {
                float br0 = bias[row], br8 = bias[row + 8];
                b00 = br0; b01 = br0; b10 = br8; b11 = br8;
            } else {
                b00 = bias[col]; b01 = bias[col + 1];
                b10 = b00; b11 = b01;
            }
            float2 o0, o1;
            o0.x = (c[mt][nt][0] + b00) * alpha;
            o0.y = (c[mt][nt][1] + b01) * alpha;
            o1.x = (c[mt][nt][2] + b10) * alpha;
            o1.y = (c[mt][nt][3] + b11) * alpha;
            *(float2*)(Cb + (size_t)row * N + col) = o0;
            *(float2*)(Cb + (size_t)(row + 8) * N + col) = o1;
        }
    }
}

// ================================================================
// Fused attention (unchanged from R3 passing version)
// ================================================================
#define KHT_STRIDE 257
__global__ __launch_bounds__(256)
void attn_kernel(const float* __restrict__ q,
                 const float* __restrict__ kproj,
                 const float* __restrict__ vproj,
                 float* __restrict__ ctx)
{
    extern __shared__ float sm[];
    float* khT = sm;                           // [64][257]
    float* vh  = khT + 64 * KHT_STRIDE;        // [256][64]
    float* qs  = vh + 256 * 64;                // [64][64]
    float* ps  = qs + 64 * 64;                 // [8][4][256]

    const int b    = blockIdx.z;
    const int h    = blockIdx.y;
    const int s0   = blockIdx.x * 64;
    const int tid  = threadIdx.x;
    const int w    = tid >> 5;
    const int lane = tid & 31;

    const float* kpB = kproj + ((size_t)b * PROJK) * EMB + h * KDIM;
    const float* vpB = vproj + ((size_t)b * PROJK) * EMB + h * KDIM;
    for (int i = tid; i < PROJK * KDIM; i += 256) {
        int kp = i >> 6, d = i & 63;
        khT[d * KHT_STRIDE + kp] = kpB[(size_t)kp * EMB + d];
        vh[i]                    = vpB[(size_t)kp * EMB + d];
    }
    const float* qB = q + ((size_t)(b * SEQ + s0)) * EMB + h * KDIM;
    for (int i = tid; i < 64 * 64; i += 256) {
        int r = i >> 6, d = i & 63;
        qs[i] = qB[(size_t)r * EMB + d];
    }
    __syncthreads();

    float* myp = ps + w * 4 * 256;

    for (int g = 0; g < 2; g++) {
        const int rbase = w * 8 + g * 4;

        float s[4][8];
#pragma unroll
        for (int r = 0; r < 4; r++)
#pragma unroll
            for (int j = 0; j < 8; j++) s[r][j] = 0.f;

#pragma unroll 4
        for (int d = 0; d < 64; d++) {
            float kv[8];
#pragma unroll
            for (int j = 0; j < 8; j++)
                kv[j] = khT[d * KHT_STRIDE + lane + 32 * j];
#pragma unroll
            for (int r = 0; r < 4; r++) {
                float qv = qs[(rbase + r) * 64 + d];
#pragma unroll
                for (int j = 0; j < 8; j++)
                    s[r][j] = fmaf(qv, kv[j], s[r][j]);
            }
        }

        float inv[4];
#pragma unroll
        for (int r = 0; r < 4; r++) {
            float m = s[r][0];
#pragma unroll
            for (int j = 1; j < 8; j++) m = fmaxf(m, s[r][j]);
#pragma unroll
            for (int o = 16; o > 0; o >>= 1)
                m = fmaxf(m, __shfl_xor_sync(0xFFFFFFFFu, m, o));
            float sum = 0.f;
#pragma unroll
            for (int j = 0; j < 8; j++) {
                s[r][j] = __expf(s[r][j] - m);
                sum += s[r][j];
            }
#pragma unroll
            for (int o = 16; o > 0; o >>= 1)
                sum += __shfl_xor_sync(0xFFFFFFFFu, sum, o);
            inv[r] = 1.f / sum;
#pragma unroll
            for (int j = 0; j < 8; j++)
                myp[r * 256 + lane + 32 * j] = s[r][j];
        }
        __syncwarp();

        float acc[4][2];
#pragma unroll
        for (int r = 0; r < 4; r++) { acc[r][0] = 0.f; acc[r][1] = 0.f; }

#pragma unroll 4
        for (int kp = 0; kp < 256; kp++) {
            float v0 = vh[kp * 64 + lane];
            float v1 = vh[kp * 64 + lane + 32];
#pragma unroll
            for (int r = 0; r < 4; r++) {
                float p = myp[r * 256 + kp];
                acc[r][0] = fmaf(p, v0, acc[r][0]);
                acc[r][1] = fmaf(p, v1, acc[r][1]);
            }
        }

#pragma unroll
        for (int r = 0; r < 4; r++) {
            size_t row = (size_t)(b * SEQ + s0 + rbase + r);
            ctx[row * EMB + h * KDIM + lane]      = acc[r][0] * inv[r];
            ctx[row * EMB + h * KDIM + lane + 32] = acc[r][1] * inv[r];
        }
        __syncwarp();
    }
}

// ================================================================
// Launch
// ================================================================
extern "C" void kernel_launch(void* const* d_in, const int* in_sizes, int n_in,
                              void* d_out, int out_size)
{
    const float* query = (const float*)d_in[0];
    const float* value = (const float*)d_in[1];
    const float* Wq    = (const float*)d_in[2];
    const float* bq    = (const float*)d_in[3];
    const float* Wk    = (const float*)d_in[4];
    const float* bk    = (const float*)d_in[5];
    const float* Wv    = (const float*)d_in[6];
    const float* bv    = (const float*)d_in[7];
    const float* Wo    = (const float*)d_in[8];
    const float* bo    = (const float*)d_in[9];
    const float* E     = (const float*)d_in[10];
    const float* Eb    = (const float*)d_in[11];
    const float* F     = (const float*)d_in[12];
    const float* Fb    = (const float*)d_in[13];
    float* out = (float*)d_out;

    float *gq, *gk, *gv, *gkp, *gvp;
    cudaGetSymbolAddress((void**)&gq,  g_q);
    cudaGetSymbolAddress((void**)&gk,  g_k);
    cudaGetSymbolAddress((void**)&gv,  g_v);
    cudaGetSymbolAddress((void**)&gkp, g_kp);
    cudaGetSymbolAddress((void**)&gvp, g_vp);
    float* gctx = gk;   // alias: k dead after proj, same stream

    const float scale = 1.0f / 8.0f;   // 64^-0.5

    // QKV projections: C[8192,1024] = A[8192,1024] @ W[1024,1024] + b
    dim3 g_big(EMB / 128, MROWS / 128, 1);   // (8, 64, 1)
    mma_gemm_kernel<false, false><<<g_big, 256>>>(query, 0, EMB, Wq, 0, bq, gq, 0, EMB, EMB, scale);
    mma_gemm_kernel<false, false><<<g_big, 256>>>(value, 0, EMB, Wk, 0, bk, gk, 0, EMB, EMB, 1.0f);
    mma_gemm_kernel<false, false><<<g_big, 256>>>(value, 0, EMB, Wv, 0, bv, gv, 0, EMB, EMB, 1.0f);

    // Linformer projections: C[b][256,1024] = E^T[256,2048] @ X[b][2048,1024] + Eb(row)
    dim3 g_proj(EMB / 128, PROJK / 128, BATCH);  // (8, 2, 4)
    mma_gemm_kernel<true, true><<<g_proj, 256>>>(E, 0, PROJK, gk, (long long)SEQ * EMB, Eb,
                                                 gkp, (long long)PROJK * EMB, EMB, SEQ, 1.0f);
    mma_gemm_kernel<true, true><<<g_proj, 256>>>(F, 0, PROJK, gv, (long long)SEQ * EMB, Fb,
                                                 gvp, (long long)PROJK * EMB, EMB, SEQ, 1.0f);

    // Fused attention
    size_t attn_smem = (size_t)(64 * KHT_STRIDE + 256 * 64 + 64 * 64 + 8 * 4 * 256) * sizeof(float);
    cudaFuncSetAttribute(attn_kernel, cudaFuncAttributeMaxDynamicSharedMemorySize, (int)attn_smem);
    dim3 attn_grid(SEQ / 64, HEADS, BATCH);       // (32, 16, 4)
    attn_kernel<<<attn_grid, 256, attn_smem>>>(gq, gkp, gvp, gctx);

    // Output projection
    mma_gemm_kernel<false, false><<<g_big, 256>>>(gctx, 0, EMB, Wo, 0, bo, out, 0, EMB, EMB, 1.0f);
}

// round 7
// speedup vs baseline: 1.8860x; 1.8860x over previous
#include <cuda_runtime.h>
#include <cuda_bf16.h>
#include <math.h>
#include <stdint.h>

// Problem constants
#define BATCH 4
#define SEQ   2048
#define EMB   1024     // H * Dk
#define HEADS 16
#define KDIM  64
#define PROJK 256
#define MROWS (BATCH * SEQ)   // 8192

// ---------------- scratch (allocation-free) ----------------
__device__ float g_q [MROWS * EMB];
__device__ float g_k [MROWS * EMB];
__device__ float g_v [MROWS * EMB];
__device__ float g_kp[BATCH * PROJK * EMB];
__device__ float g_vp[BATCH * PROJK * EMB];
// pre-split bf16 operands (hi/lo)
__device__ unsigned short g_qA_h[MROWS * EMB], g_qA_l[MROWS * EMB];   // query split
__device__ unsigned short g_vA_h[MROWS * EMB], g_vA_l[MROWS * EMB];   // value split
__device__ unsigned short g_ctx_h[MROWS * EMB], g_ctx_l[MROWS * EMB]; // attn output split
__device__ unsigned short g_wqT_h[EMB * EMB], g_wqT_l[EMB * EMB];     // W^T splits
__device__ unsigned short g_wkT_h[EMB * EMB], g_wkT_l[EMB * EMB];
__device__ unsigned short g_wvT_h[EMB * EMB], g_wvT_l[EMB * EMB];
__device__ unsigned short g_woT_h[EMB * EMB], g_woT_l[EMB * EMB];

// ---------------- helpers ----------------
__device__ __forceinline__ void split1(float v, unsigned short& h, unsigned short& l) {
    __nv_bfloat16 hh = __float2bfloat16(v);
    __nv_bfloat16 ll = __float2bfloat16(v - __bfloat162float(hh));
    h = __bfloat16_as_ushort(hh);
    l = __bfloat16_as_ushort(ll);
}

#define MMA_BF16(d, a, b0, b1) asm volatile( \
    "mma.sync.aligned.m16n8k16.row.col.f32.bf16.bf16.f32 " \
    "{%0,%1,%2,%3}, {%4,%5,%6,%7}, {%8,%9}, {%0,%1,%2,%3};\n" \
    : "+f"((d)[0]), "+f"((d)[1]), "+f"((d)[2]), "+f"((d)[3]) \
    : "r"((a)[0]), "r"((a)[1]), "r"((a)[2]), "r"((a)[3]), \
      "r"(b0), "r"(b1))

#define LDSM4(r0, r1, r2, r3, addr) asm volatile( \
    "ldmatrix.sync.aligned.m8n8.x4.shared.b16 {%0,%1,%2,%3}, [%4];\n" \
    : "=r"(r0), "=r"(r1), "=r"(r2), "=r"(r3) : "r"(addr))

__device__ __forceinline__ void cp16(uint32_t dst, const void* src) {
    asm volatile("cp.async.cg.shared.global [%0], [%1], 16;\n" :: "r"(dst), "l"(src));
}
#define CP_COMMIT() asm volatile("cp.async.commit_group;\n" ::: "memory")
#define CP_WAIT1()  asm volatile("cp.async.wait_group 1;\n" ::: "memory")

// ================================================================
// split_kernel: fp32 -> bf16 hi/lo, vectorized. n % 4 == 0
// ================================================================
__global__ __launch_bounds__(256)
void split_kernel(const float* __restrict__ src,
                  unsigned short* __restrict__ hi,
                  unsigned short* __restrict__ lo, int n)
{
    int i = (blockIdx.x * 256 + threadIdx.x) * 4;
    if (i >= n) return;
    float4 v = *(const float4*)(src + i);
    ushort4 h, l;
    split1(v.x, h.x, l.x);
    split1(v.y, h.y, l.y);
    split1(v.z, h.z, l.z);
    split1(v.w, h.w, l.w);
    *(ushort4*)(hi + i) = h;
    *(ushort4*)(lo + i) = l;
}

// ================================================================
// split_transpose_kernel: W[K][N] fp32 -> WT[N][K] bf16 hi/lo
// block (32,8), grid (N/32, K/32)
// ================================================================
__global__ __launch_bounds__(256)
void split_transpose_kernel(const float* __restrict__ W,
                            unsigned short* __restrict__ hiT,
                            unsigned short* __restrict__ loT,
                            int K, int N)
{
    __shared__ float t[32][33];
    int k0 = blockIdx.y * 32, n0 = blockIdx.x * 32;
    int tx = threadIdx.x, ty = threadIdx.y;
#pragma unroll
    for (int i = 0; i < 32; i += 8)
        t[ty + i][tx] = W[(size_t)(k0 + ty + i) * N + n0 + tx];
    __syncthreads();
#pragma unroll
    for (int i = 0; i < 32; i += 8) {
        float v = t[tx][ty + i];   // = W[k0+tx][n0+ty+i]
        unsigned short h, l;
        split1(v, h, l);
        hiT[(size_t)(n0 + ty + i) * K + k0 + tx] = h;
        loT[(size_t)(n0 + ty + i) * K + k0 + tx] = l;
    }
}

// ================================================================
// Tensor-core GEMM on pre-split bf16:
//   C[M][N] = (sum_k A[m][k]*B[n][k] + bias[n]) * alpha
// with bf16x3: Ah*Bh + Ah*Bl + Al*Bh (fp32 accum)
// A*: [M][K] k-contig, B*: [N][K] k-contig (pre-transposed weights)
// CTA 128x128, BK=32, 2-stage cp.async, 8 warps (2x4), warp 64x32
// ================================================================
#define SKS 40                         // smem row stride in shorts (80B)
#define ARR_B (128 * SKS * 2)          // 10240 bytes per array
#define STAGE_B (4 * ARR_B)            // 40960 bytes per stage

__global__ __launch_bounds__(256)
void mma_gemm_ts(const unsigned short* __restrict__ Agh,
                 const unsigned short* __restrict__ Agl,
                 const unsigned short* __restrict__ Bgh,
                 const unsigned short* __restrict__ Bgl,
                 const float* __restrict__ bias,
                 float* __restrict__ C,
                 int N, int K, float alpha)
{
    extern __shared__ unsigned char smraw[];
    const uint32_t smb = (uint32_t)__cvta_generic_to_shared(smraw);

    const int tid  = threadIdx.x;
    const int wid  = tid >> 5;
    const int lane = tid & 31;
    const int gid  = lane >> 2;
    const int tig  = lane & 3;
    const int wm   = wid >> 2;   // 0..1
    const int wn   = wid & 3;    // 0..3
    const int m0   = blockIdx.y * 128;
    const int n0   = blockIdx.x * 128;

    // cp.async mapping: per array each thread does 2 16B chunks
    const int lrow = tid >> 1;         // 0..127
    const int lk0  = (tid & 1) * 16;   // 0 or 16 (elements)

    auto issue = [&](int s, int kt) {
        const int k0 = kt * 32;
        const uint32_t so = smb + s * STAGE_B;
        const uint32_t ro = (uint32_t)(lrow * SKS + lk0) * 2;
        const size_t ga = (size_t)(m0 + lrow) * K + k0 + lk0;
        const size_t gb = (size_t)(n0 + lrow) * K + k0 + lk0;
        cp16(so + ro,                    Agh + ga);
        cp16(so + ro + 16,               Agh + ga + 8);
        cp16(so + ARR_B + ro,            Agl + ga);
        cp16(so + ARR_B + ro + 16,       Agl + ga + 8);
        cp16(so + 2 * ARR_B + ro,        Bgh + gb);
        cp16(so + 2 * ARR_B + ro + 16,   Bgh + gb + 8);
        cp16(so + 3 * ARR_B + ro,        Bgl + gb);
        cp16(so + 3 * ARR_B + ro + 16,   Bgl + gb + 8);
    };

    float c[4][4][4];
#pragma unroll
    for (int i = 0; i < 4; i++)
#pragma unroll
        for (int j = 0; j < 4; j++)
#pragma unroll
            for (int l = 0; l < 4; l++) c[i][j][l] = 0.f;

    const int nk = K / 32;
    issue(0, 0); CP_COMMIT();
    issue(1, 1); CP_COMMIT();

    const int arow = lane & 15;
    const int acol = (lane >> 4) << 3;   // 0 or 8

    for (int kt = 0; kt < nk; kt++) {
        CP_WAIT1();
        __syncthreads();
        const int s = kt & 1;
        const uint32_t so = smb + s * STAGE_B;

#pragma unroll
        for (int kb = 0; kb < 32; kb += 16) {
            const uint32_t koff = (uint32_t)(kb + acol) * 2;
            uint32_t ah[4][4], al[4][4];
#pragma unroll
            for (int mt = 0; mt < 4; mt++) {
                uint32_t ad = so + (uint32_t)((wm * 64 + mt * 16 + arow) * SKS) * 2 + koff;
                LDSM4(ah[mt][0], ah[mt][1], ah[mt][2], ah[mt][3], ad);
                LDSM4(al[mt][0], al[mt][1], al[mt][2], al[mt][3], ad + ARR_B);
            }
            uint32_t bh[2][4], bl[2][4];
#pragma unroll
            for (int p = 0; p < 2; p++) {
                uint32_t bd = so + 2 * ARR_B +
                              (uint32_t)((wn * 32 + p * 16 + arow) * SKS) * 2 + koff;
                LDSM4(bh[p][0], bh[p][1], bh[p][2], bh[p][3], bd);
                LDSM4(bl[p][0], bl[p][1], bl[p][2], bl[p][3], bd + ARR_B);
            }
#pragma unroll
            for (int mt = 0; mt < 4; mt++)
#pragma unroll
                for (int nt = 0; nt < 4; nt++) {
                    const int p = nt >> 1, q = nt & 1;
                    MMA_BF16(c[mt][nt], ah[mt], bh[p][q], bh[p][q + 2]);
                    MMA_BF16(c[mt][nt], ah[mt], bl[p][q], bl[p][q + 2]);
                    MMA_BF16(c[mt][nt], al[mt], bh[p][q], bh[p][q + 2]);
                }
        }
        __syncthreads();
        if (kt + 2 < nk) issue(s, kt + 2);
        CP_COMMIT();
    }

    // epilogue: (acc + bias[col]) * alpha
#pragma unroll
    for (int mt = 0; mt < 4; mt++) {
        int row = m0 + wm * 64 + mt * 16 + gid;
#pragma unroll
        for (int nt = 0; nt < 4; nt++) {
            int col = n0 + wn * 32 + nt * 8 + tig * 2;
            float b0 = bias[col], b1 = bias[col + 1];
            float2 o0, o1;
            o0.x = (c[mt][nt][0] + b0) * alpha;
            o0.y = (c[mt][nt][1] + b1) * alpha;
            o1.x = (c[mt][nt][2] + b0) * alpha;
            o1.y = (c[mt][nt][3] + b1) * alpha;
            *(float2*)(C + (size_t)row * N + col) = o0;
            *(float2*)(C + (size_t)(row + 8) * N + col) = o1;
        }
    }
}

// ================================================================
// Sequence projection (FFMA, R3-proven — 137us each)
// ================================================================
__global__ __launch_bounds__(256)
void proj_kernel(const float* __restrict__ E,
                 const float* __restrict__ X,
                 const float* __restrict__ bias,
                 float* __restrict__ C)
{
    __shared__ float As[16][64];
    __shared__ float Bs[16][64];

    const int tid = threadIdx.x;
    const int tx  = tid % 16;
    const int ty  = tid / 16;
    const int b   = blockIdx.z;
    const int m0  = blockIdx.y * 64;
    const int n0  = blockIdx.x * 64;

    const float* Xb = X + (size_t)b * SEQ * EMB;
    const int lk = tid >> 4;
    const int l4 = (tid & 15) * 4;

    float acc[4][4];
#pragma unroll
    for (int i = 0; i < 4; i++)
#pragma unroll
        for (int j = 0; j < 4; j++) acc[i][j] = 0.f;

    float4 av = *(const float4*)(E  + (size_t)lk * PROJK + m0 + l4);
    float4 bv = *(const float4*)(Xb + (size_t)lk * EMB   + n0 + l4);

    for (int k0 = 0; k0 < SEQ; k0 += 16) {
        *(float4*)(&As[lk][l4]) = av;
        *(float4*)(&Bs[lk][l4]) = bv;
        __syncthreads();

        if (k0 + 16 < SEQ) {
            av = *(const float4*)(E  + (size_t)(k0 + 16 + lk) * PROJK + m0 + l4);
            bv = *(const float4*)(Xb + (size_t)(k0 + 16 + lk) * EMB   + n0 + l4);
        }

#pragma unroll
        for (int kk = 0; kk < 16; kk++) {
            float a[4], b2[4];
#pragma unroll
            for (int i = 0; i < 4; i++) a[i]  = As[kk][ty * 4 + i];
#pragma unroll
            for (int j = 0; j < 4; j++) b2[j] = Bs[kk][tx * 4 + j];
#pragma unroll
            for (int i = 0; i < 4; i++)
#pragma unroll
                for (int j = 0; j < 4; j++)
                    acc[i][j] = fmaf(a[i], b2[j], acc[i][j]);
        }
        __syncthreads();
    }

#pragma unroll
    for (int i = 0; i < 4; i++) {
        int m = m0 + ty * 4 + i;
        float bm = bias[m];
        float4 o;
        o.x = acc[i][0] + bm;
        o.y = acc[i][1] + bm;
        o.z = acc[i][2] + bm;
        o.w = acc[i][3] + bm;
        *(float4*)(&C[((size_t)b * PROJK + m) * EMB + n0 + tx * 4]) = o;
    }
}

// ================================================================
// Fused attention — writes ctx directly as bf16 hi/lo split
// ================================================================
#define KHT_STRIDE 257
__global__ __launch_bounds__(256)
void attn_kernel(const float* __restrict__ q,
                 const float* __restrict__ kproj,
                 const float* __restrict__ vproj,
                 unsigned short* __restrict__ ctx_h,
                 unsigned short* __restrict__ ctx_l)
{
    extern __shared__ float sm[];
    float* khT = sm;                           // [64][257]
    float* vh  = khT + 64 * KHT_STRIDE;        // [256][64]
    float* qs  = vh + 256 * 64;                // [64][64]
    float* ps  = qs + 64 * 64;                 // [8][4][256]

    const int b    = blockIdx.z;
    const int h    = blockIdx.y;
    const int s0   = blockIdx.x * 64;
    const int tid  = threadIdx.x;
    const int w    = tid >> 5;
    const int lane = tid & 31;

    const float* kpB = kproj + ((size_t)b * PROJK) * EMB + h * KDIM;
    const float* vpB = vproj + ((size_t)b * PROJK) * EMB + h * KDIM;
    for (int i = tid; i < PROJK * KDIM; i += 256) {
        int kp = i >> 6, d = i & 63;
        khT[d * KHT_STRIDE + kp] = kpB[(size_t)kp * EMB + d];
        vh[i]                    = vpB[(size_t)kp * EMB + d];
    }
    const float* qB = q + ((size_t)(b * SEQ + s0)) * EMB + h * KDIM;
    for (int i = tid; i < 64 * 64; i += 256) {
        int r = i >> 6, d = i & 63;
        qs[i] = qB[(size_t)r * EMB + d];
    }
    __syncthreads();

    float* myp = ps + w * 4 * 256;

    for (int g = 0; g < 2; g++) {
        const int rbase = w * 8 + g * 4;

        float s[4][8];
#pragma unroll
        for (int r = 0; r < 4; r++)
#pragma unroll
            for (int j = 0; j < 8; j++) s[r][j] = 0.f;

#pragma unroll 4
        for (int d = 0; d < 64; d++) {
            float kv[8];
#pragma unroll
            for (int j = 0; j < 8; j++)
                kv[j] = khT[d * KHT_STRIDE + lane + 32 * j];
#pragma unroll
            for (int r = 0; r < 4; r++) {
                float qv = qs[(rbase + r) * 64 + d];
#pragma unroll
                for (int j = 0; j < 8; j++)
                    s[r][j] = fmaf(qv, kv[j], s[r][j]);
            }
        }

        float inv[4];
#pragma unroll
        for (int r = 0; r < 4; r++) {
            float m = s[r][0];
#pragma unroll
            for (int j = 1; j < 8; j++) m = fmaxf(m, s[r][j]);
#pragma unroll
            for (int o = 16; o > 0; o >>= 1)
                m = fmaxf(m, __shfl_xor_sync(0xFFFFFFFFu, m, o));
            float sum = 0.f;
#pragma unroll
            for (int j = 0; j < 8; j++) {
                s[r][j] = __expf(s[r][j] - m);
                sum += s[r][j];
            }
#pragma unroll
            for (int o = 16; o > 0; o >>= 1)
                sum += __shfl_xor_sync(0xFFFFFFFFu, sum, o);
            inv[r] = 1.f / sum;
#pragma unroll
            for (int j = 0; j < 8; j++)
                myp[r * 256 + lane + 32 * j] = s[r][j];
        }
        __syncwarp();

        float acc[4][2];
#pragma unroll
        for (int r = 0; r < 4; r++) { acc[r][0] = 0.f; acc[r][1] = 0.f; }

#pragma unroll 4
        for (int kp = 0; kp < 256; kp++) {
            float v0 = vh[kp * 64 + lane];
            float v1 = vh[kp * 64 + lane + 32];
#pragma unroll
            for (int r = 0; r < 4; r++) {
                float p = myp[r * 256 + kp];
                acc[r][0] = fmaf(p, v0, acc[r][0]);
                acc[r][1] = fmaf(p, v1, acc[r][1]);
            }
        }

#pragma unroll
        for (int r = 0; r < 4; r++) {
            size_t row = (size_t)(b * SEQ + s0 + rbase + r);
            unsigned short h0, l0, h1, l1;
            split1(acc[r][0] * inv[r], h0, l0);
            split1(acc[r][1] * inv[r], h1, l1);
            size_t base = row * EMB + h * KDIM;
            ctx_h[base + lane]      = h0;
            ctx_l[base + lane]      = l0;
            ctx_h[base + lane + 32] = h1;
            ctx_l[base + lane + 32] = l1;
        }
        __syncwarp();
    }
}

// ================================================================
// Launch
// ================================================================
extern "C" void kernel_launch(void* const* d_in, const int* in_sizes, int n_in,
                              void* d_out, int out_size)
{
    const float* query = (const float*)d_in[0];
    const float* value = (const float*)d_in[1];
    const float* Wq    = (const float*)d_in[2];
    const float* bq    = (const float*)d_in[3];
    const float* Wk    = (const float*)d_in[4];
    const float* bk    = (const float*)d_in[5];
    const float* Wv    = (const float*)d_in[6];
    const float* bv    = (const float*)d_in[7];
    const float* Wo    = (const float*)d_in[8];
    const float* bo    = (const float*)d_in[9];
    const float* E     = (const float*)d_in[10];
    const float* Eb    = (const float*)d_in[11];
    const float* F     = (const float*)d_in[12];
    const float* Fb    = (const float*)d_in[13];
    float* out = (float*)d_out;

    float *gq, *gk, *gv, *gkp, *gvp;
    unsigned short *qah, *qal, *vah, *val_, *cth, *ctl;
    unsigned short *wqh, *wql, *wkh, *wkl, *wvh, *wvl, *woh, *wol;
    cudaGetSymbolAddress((void**)&gq,  g_q);
    cudaGetSymbolAddress((void**)&gk,  g_k);
    cudaGetSymbolAddress((void**)&gv,  g_v);
    cudaGetSymbolAddress((void**)&gkp, g_kp);
    cudaGetSymbolAddress((void**)&gvp, g_vp);
    cudaGetSymbolAddress((void**)&qah, g_qA_h);
    cudaGetSymbolAddress((void**)&qal, g_qA_l);
    cudaGetSymbolAddress((void**)&vah, g_vA_h);
    cudaGetSymbolAddress((void**)&val_, g_vA_l);
    cudaGetSymbolAddress((void**)&cth, g_ctx_h);
    cudaGetSymbolAddress((void**)&ctl, g_ctx_l);
    cudaGetSymbolAddress((void**)&wqh, g_wqT_h);
    cudaGetSymbolAddress((void**)&wql, g_wqT_l);
    cudaGetSymbolAddress((void**)&wkh, g_wkT_h);
    cudaGetSymbolAddress((void**)&wkl, g_wkT_l);
    cudaGetSymbolAddress((void**)&wvh, g_wvT_h);
    cudaGetSymbolAddress((void**)&wvl, g_wvT_l);
    cudaGetSymbolAddress((void**)&woh, g_woT_h);
    cudaGetSymbolAddress((void**)&wol, g_woT_l);

    const float scale = 1.0f / 8.0f;   // 64^-0.5
    const int nbig = MROWS * EMB;      // 8388608

    // 1) split inputs
    split_kernel<<<nbig / 1024, 256>>>(query, qah, qal, nbig);
    split_kernel<<<nbig / 1024, 256>>>(value, vah, val_, nbig);
    // 2) split+transpose weights
    dim3 tg(EMB / 32, EMB / 32), tb(32, 8);
    split_transpose_kernel<<<tg, tb>>>(Wq, wqh, wql, EMB, EMB);
    split_transpose_kernel<<<tg, tb>>>(Wk, wkh, wkl, EMB, EMB);
    split_transpose_kernel<<<tg, tb>>>(Wv, wvh, wvl, EMB, EMB);
    split_transpose_kernel<<<tg, tb>>>(Wo, woh, wol, EMB, EMB);

    // 3) QKV GEMMs (tensor cores)
    cudaFuncSetAttribute(mma_gemm_ts, cudaFuncAttributeMaxDynamicSharedMemorySize, 2 * STAGE_B);
    dim3 g_big(EMB / 128, MROWS / 128);   // (8, 64)
    mma_gemm_ts<<<g_big, 256, 2 * STAGE_B>>>(qah, qal, wqh, wql, bq, gq, EMB, EMB, scale);
    mma_gemm_ts<<<g_big, 256, 2 * STAGE_B>>>(vah, val_, wkh, wkl, bk, gk, EMB, EMB, 1.0f);
    mma_gemm_ts<<<g_big, 256, 2 * STAGE_B>>>(vah, val_, wvh, wvl, bv, gv, EMB, EMB, 1.0f);

    // 4) Linformer projections (FFMA)
    dim3 g_proj(EMB / 64, PROJK / 64, BATCH);
    proj_kernel<<<g_proj, 256>>>(E, gk, Eb, gkp);
    proj_kernel<<<g_proj, 256>>>(F, gv, Fb, gvp);

    // 5) fused attention -> ctx (bf16 split)
    size_t attn_smem = (size_t)(64 * KHT_STRIDE + 256 * 64 + 64 * 64 + 8 * 4 * 256) * sizeof(float);
    cudaFuncSetAttribute(attn_kernel, cudaFuncAttributeMaxDynamicSharedMemorySize, (int)attn_smem);
    dim3 attn_grid(SEQ / 64, HEADS, BATCH);
    attn_kernel<<<attn_grid, 256, attn_smem>>>(gq, gkp, gvp, cth, ctl);

    // 6) output projection (tensor cores)
    mma_gemm_ts<<<g_big, 256, 2 * STAGE_B>>>(cth, ctl, woh, wol, bo, out, EMB, EMB, 1.0f);
}

// round 8
// speedup vs baseline: 1.8994x; 1.0071x over previous
#include <cuda_runtime.h>
#include <cuda_bf16.h>
#include <math.h>
#include <stdint.h>

// Problem constants
#define BATCH 4
#define SEQ   2048
#define EMB   1024     // H * Dk
#define HEADS 16
#define KDIM  64
#define PROJK 256
#define MROWS (BATCH * SEQ)   // 8192

typedef unsigned short ushort_t;

// ---------------- scratch (allocation-free) ----------------
__device__ float g_q [MROWS * EMB];
__device__ float g_kp[BATCH * PROJK * EMB];
__device__ float g_vp[BATCH * PROJK * EMB];
// pre-split bf16 operands (hi/lo)
__device__ ushort_t g_qA_h[MROWS * EMB], g_qA_l[MROWS * EMB];   // query split
__device__ ushort_t g_vA_h[MROWS * EMB], g_vA_l[MROWS * EMB];   // value split
__device__ ushort_t g_ctx_h[MROWS * EMB], g_ctx_l[MROWS * EMB]; // attn output split
__device__ ushort_t g_kb_h[MROWS * EMB], g_kb_l[MROWS * EMB];   // k (post-GEMM) split
__device__ ushort_t g_vb_h[MROWS * EMB], g_vb_l[MROWS * EMB];   // v (post-GEMM) split
__device__ ushort_t g_wqT_h[EMB * EMB], g_wqT_l[EMB * EMB];     // W^T splits
__device__ ushort_t g_wkT_h[EMB * EMB], g_wkT_l[EMB * EMB];
__device__ ushort_t g_wvT_h[EMB * EMB], g_wvT_l[EMB * EMB];
__device__ ushort_t g_woT_h[EMB * EMB], g_woT_l[EMB * EMB];
__device__ ushort_t g_ETh[PROJK * SEQ], g_ETl[PROJK * SEQ];     // E^T split
__device__ ushort_t g_FTh[PROJK * SEQ], g_FTl[PROJK * SEQ];     // F^T split

// ---------------- helpers ----------------
__device__ __forceinline__ void split1(float v, ushort_t& h, ushort_t& l) {
    __nv_bfloat16 hh = __float2bfloat16(v);
    __nv_bfloat16 ll = __float2bfloat16(v - __bfloat162float(hh));
    h = __bfloat16_as_ushort(hh);
    l = __bfloat16_as_ushort(ll);
}

#define MMA_BF16(d, a, b0, b1) asm volatile( \
    "mma.sync.aligned.m16n8k16.row.col.f32.bf16.bf16.f32 " \
    "{%0,%1,%2,%3}, {%4,%5,%6,%7}, {%8,%9}, {%0,%1,%2,%3};\n" \
    : "+f"((d)[0]), "+f"((d)[1]), "+f"((d)[2]), "+f"((d)[3]) \
    : "r"((a)[0]), "r"((a)[1]), "r"((a)[2]), "r"((a)[3]), \
      "r"(b0), "r"(b1))

#define LDSM4(r0, r1, r2, r3, addr) asm volatile( \
    "ldmatrix.sync.aligned.m8n8.x4.shared.b16 {%0,%1,%2,%3}, [%4];\n" \
    : "=r"(r0), "=r"(r1), "=r"(r2), "=r"(r3) : "r"(addr))

#define LDSM4T(r0, r1, r2, r3, addr) asm volatile( \
    "ldmatrix.sync.aligned.m8n8.x4.trans.shared.b16 {%0,%1,%2,%3}, [%4];\n" \
    : "=r"(r0), "=r"(r1), "=r"(r2), "=r"(r3) : "r"(addr))

__device__ __forceinline__ void cp16(uint32_t dst, const void* src) {
    asm volatile("cp.async.cg.shared.global [%0], [%1], 16;\n" :: "r"(dst), "l"(src));
}
#define CP_COMMIT() asm volatile("cp.async.commit_group;\n" ::: "memory")
#define CP_WAIT2()  asm volatile("cp.async.wait_group 2;\n" ::: "memory")

// ================================================================
// split_kernel: fp32 -> bf16 hi/lo, vectorized. n % 4 == 0
// ================================================================
__global__ __launch_bounds__(256)
void split_kernel(const float* __restrict__ src,
                  ushort_t* __restrict__ hi,
                  ushort_t* __restrict__ lo, int n)
{
    int i = (blockIdx.x * 256 + threadIdx.x) * 4;
    if (i >= n) return;
    float4 v = *(const float4*)(src + i);
    ushort4 h, l;
    split1(v.x, h.x, l.x);
    split1(v.y, h.y, l.y);
    split1(v.z, h.z, l.z);
    split1(v.w, h.w, l.w);
    *(ushort4*)(hi + i) = h;
    *(ushort4*)(lo + i) = l;
}

// ================================================================
// split_transpose_kernel: W[K][N] fp32 -> WT[N][K] bf16 hi/lo
// block (32,8), grid (N/32, K/32)
// ================================================================
__global__ __launch_bounds__(256)
void split_transpose_kernel(const float* __restrict__ W,
                            ushort_t* __restrict__ hiT,
                            ushort_t* __restrict__ loT,
                            int K, int N)
{
    __shared__ float t[32][33];
    int k0 = blockIdx.y * 32, n0 = blockIdx.x * 32;
    int tx = threadIdx.x, ty = threadIdx.y;
#pragma unroll
    for (int i = 0; i < 32; i += 8)
        t[ty + i][tx] = W[(size_t)(k0 + ty + i) * N + n0 + tx];
    __syncthreads();
#pragma unroll
    for (int i = 0; i < 32; i += 8) {
        float v = t[tx][ty + i];   // = W[k0+tx][n0+ty+i]
        ushort_t h, l;
        split1(v, h, l);
        hiT[(size_t)(n0 + ty + i) * K + k0 + tx] = h;
        loT[(size_t)(n0 + ty + i) * K + k0 + tx] = l;
    }
}

// ================================================================
// Big tensor-core GEMM on pre-split bf16 (bf16x3):
//   C[M][N] = (sum_k A[m][k]*B[n][k] + bias[n]) * alpha
// A: [M][K] k-contig, B: [N][K] k-contig. CTA 128x128, BK=32,
// 3-stage cp.async, 8 warps (2x4), warp 64x32.
// SPLIT_OUT: write bf16 hi/lo split instead of fp32 (alpha=1).
// ================================================================
#define SKS 40                         // smem row stride in shorts (80B)
#define ARR_B (128 * SKS * 2)          // 10240 bytes per array
#define STAGE_B (4 * ARR_B)            // 40960 bytes per stage
#define NSTAGE 3

template<bool SPLIT_OUT>
__global__ __launch_bounds__(256)
void mma_gemm_ts(const ushort_t* __restrict__ Agh,
                 const ushort_t* __restrict__ Agl,
                 const ushort_t* __restrict__ Bgh,
                 const ushort_t* __restrict__ Bgl,
                 const float* __restrict__ bias,
                 float* __restrict__ C,
                 ushort_t* __restrict__ Ch,
                 ushort_t* __restrict__ Cl,
                 int N, int K, float alpha)
{
    extern __shared__ unsigned char smraw[];
    const uint32_t smb = (uint32_t)__cvta_generic_to_shared(smraw);

    const int tid  = threadIdx.x;
    const int wid  = tid >> 5;
    const int lane = tid & 31;
    const int gid  = lane >> 2;
    const int tig  = lane & 3;
    const int wm   = wid >> 2;   // 0..1
    const int wn   = wid & 3;    // 0..3
    const int m0   = blockIdx.y * 128;
    const int n0   = blockIdx.x * 128;

    const int lrow = tid >> 1;         // 0..127
    const int lk0  = (tid & 1) * 16;   // 0 or 16 (elements)

    auto issue = [&](int s, int kt) {
        const int k0 = kt * 32;
        const uint32_t so = smb + s * STAGE_B;
        const uint32_t ro = (uint32_t)(lrow * SKS + lk0) * 2;
        const size_t ga = (size_t)(m0 + lrow) * K + k0 + lk0;
        const size_t gb = (size_t)(n0 + lrow) * K + k0 + lk0;
        cp16(so + ro,                    Agh + ga);
        cp16(so + ro + 16,               Agh + ga + 8);
        cp16(so + ARR_B + ro,            Agl + ga);
        cp16(so + ARR_B + ro + 16,       Agl + ga + 8);
        cp16(so + 2 * ARR_B + ro,        Bgh + gb);
        cp16(so + 2 * ARR_B + ro + 16,   Bgh + gb + 8);
        cp16(so + 3 * ARR_B + ro,        Bgl + gb);
        cp16(so + 3 * ARR_B + ro + 16,   Bgl + gb + 8);
    };

    float c[4][4][4];
#pragma unroll
    for (int i = 0; i < 4; i++)
#pragma unroll
        for (int j = 0; j < 4; j++)
#pragma unroll
            for (int l = 0; l < 4; l++) c[i][j][l] = 0.f;

    const int nk = K / 32;
    issue(0, 0); CP_COMMIT();
    issue(1, 1); CP_COMMIT();

    const int arow = lane & 15;
    const int acol = (lane >> 4) << 3;   // 0 or 8

    for (int kt = 0; kt < nk; kt++) {
        if (kt + 2 < nk) issue((kt + 2) % NSTAGE, kt + 2);
        CP_COMMIT();
        CP_WAIT2();
        __syncthreads();
        const uint32_t so = smb + (kt % NSTAGE) * STAGE_B;

#pragma unroll
        for (int kb = 0; kb < 32; kb += 16) {
            const uint32_t koff = (uint32_t)(kb + acol) * 2;
            uint32_t ah[4][4], al[4][4];
#pragma unroll
            for (int mt = 0; mt < 4; mt++) {
                uint32_t ad = so + (uint32_t)((wm * 64 + mt * 16 + arow) * SKS) * 2 + koff;
                LDSM4(ah[mt][0], ah[mt][1], ah[mt][2], ah[mt][3], ad);
                LDSM4(al[mt][0], al[mt][1], al[mt][2], al[mt][3], ad + ARR_B);
            }
            uint32_t bh[2][4], bl[2][4];
#pragma unroll
            for (int p = 0; p < 2; p++) {
                uint32_t bd = so + 2 * ARR_B +
                              (uint32_t)((wn * 32 + p * 16 + arow) * SKS) * 2 + koff;
                LDSM4(bh[p][0], bh[p][1], bh[p][2], bh[p][3], bd);
                LDSM4(bl[p][0], bl[p][1], bl[p][2], bl[p][3], bd + ARR_B);
            }
#pragma unroll
            for (int mt = 0; mt < 4; mt++)
#pragma unroll
                for (int nt = 0; nt < 4; nt++) {
                    const int p = nt >> 1, q = nt & 1;
                    MMA_BF16(c[mt][nt], ah[mt], bh[p][q], bh[p][q + 2]);
                    MMA_BF16(c[mt][nt], ah[mt], bl[p][q], bl[p][q + 2]);
                    MMA_BF16(c[mt][nt], al[mt], bh[p][q], bh[p][q + 2]);
                }
        }
        __syncthreads();
    }

    // epilogue
#pragma unroll
    for (int mt = 0; mt < 4; mt++) {
        int row = m0 + wm * 64 + mt * 16 + gid;
#pragma unroll
        for (int nt = 0; nt < 4; nt++) {
            int col = n0 + wn * 32 + nt * 8 + tig * 2;
            float b0 = bias[col], b1 = bias[col + 1];
            float v00 = (c[mt][nt][0] + b0) * alpha;
            float v01 = (c[mt][nt][1] + b1) * alpha;
            float v10 = (c[mt][nt][2] + b0) * alpha;
            float v11 = (c[mt][nt][3] + b1) * alpha;
            if (SPLIT_OUT) {
                ushort2 h0, l0, h1, l1;
                split1(v00, h0.x, l0.x); split1(v01, h0.y, l0.y);
                split1(v10, h1.x, l1.x); split1(v11, h1.y, l1.y);
                *(ushort2*)(Ch + (size_t)row * N + col)       = h0;
                *(ushort2*)(Cl + (size_t)row * N + col)       = l0;
                *(ushort2*)(Ch + (size_t)(row + 8) * N + col) = h1;
                *(ushort2*)(Cl + (size_t)(row + 8) * N + col) = l1;
            } else {
                float2 o0 = {v00, v01}, o1 = {v10, v11};
                *(float2*)(C + (size_t)row * N + col)       = o0;
                *(float2*)(C + (size_t)(row + 8) * N + col) = o1;
            }
        }
    }
}

// ================================================================
// Projection MMA: C[b][m][n] = sum_s ET[m][s]*X[b][s][n] + bias[m]
// ET: [PROJK][SEQ] k-contig split. X: [SEQ][EMB] emb-contig split
// (B loaded with ldmatrix.trans). CTA 64m x 128n, BK=32, 3-stage.
// grid (EMB/128, PROJK/64, BATCH). Output fp32.
// ================================================================
#define PA_B (64 * SKS * 2)            // 5120 bytes (A array, 64 rows)
#define PB_RS 272                      // B row stride bytes (256 + 16 pad)
#define PB_B (32 * PB_RS)              // 8704 bytes (B array)
#define PSTAGE_B (2 * PA_B + 2 * PB_B) // 27648 bytes

__global__ __launch_bounds__(256)
void proj_mma(const ushort_t* __restrict__ ETh,
              const ushort_t* __restrict__ ETl,
              const ushort_t* __restrict__ Xh,
              const ushort_t* __restrict__ Xl,
              const float* __restrict__ bias,
              float* __restrict__ C)
{
    extern __shared__ unsigned char smraw[];
    const uint32_t smb = (uint32_t)__cvta_generic_to_shared(smraw);

    const int tid  = threadIdx.x;
    const int wid  = tid >> 5;
    const int lane = tid & 31;
    const int gid  = lane >> 2;
    const int tig  = lane & 3;
    const int wm   = wid >> 2;   // 0..1
    const int wn   = wid & 3;    // 0..3
    const int b    = blockIdx.z;
    const int m0   = blockIdx.y * 64;
    const int n0   = blockIdx.x * 128;

    const ushort_t* Xbh = Xh + (size_t)b * SEQ * EMB;
    const ushort_t* Xbl = Xl + (size_t)b * SEQ * EMB;

    auto issue = [&](int s, int kt) {
        const int k0 = kt * 32;
        const uint32_t so = smb + s * PSTAGE_B;
        // A: 64 rows x 64B = 256 chunks per array, 1 chunk/thread
        {
            int row = tid >> 2, cf = (tid & 3);
            uint32_t sa = so + (uint32_t)(row * SKS) * 2 + cf * 16;
            size_t ga = (size_t)(m0 + row) * SEQ + k0 + cf * 8;
            cp16(sa,        ETh + ga);
            cp16(sa + PA_B, ETl + ga);
        }
        // B: 32 rows x 256B = 512 chunks per array, 2 chunks/thread
#pragma unroll
        for (int half = 0; half < 2; half++) {
            int cidx = half * 256 + tid;
            int row = cidx >> 4, cf = cidx & 15;
            uint32_t sb = so + 2 * PA_B + (uint32_t)(row * PB_RS) + cf * 16;
            size_t gb = (size_t)(k0 + row) * EMB + n0 + cf * 8;
            cp16(sb,        Xbh + gb);
            cp16(sb + PB_B, Xbl + gb);
        }
    };

    float c[2][4][4];
#pragma unroll
    for (int i = 0; i < 2; i++)
#pragma unroll
        for (int j = 0; j < 4; j++)
#pragma unroll
            for (int l = 0; l < 4; l++) c[i][j][l] = 0.f;

    const int nk = SEQ / 32;   // 64
    issue(0, 0); CP_COMMIT();
    issue(1, 1); CP_COMMIT();

    const int arow = lane & 15;
    const int acol = (lane >> 4) << 3;

    for (int kt = 0; kt < nk; kt++) {
        if (kt + 2 < nk) issue((kt + 2) % NSTAGE, kt + 2);
        CP_COMMIT();
        CP_WAIT2();
        __syncthreads();
        const uint32_t so = smb + (kt % NSTAGE) * PSTAGE_B;

#pragma unroll
        for (int kb = 0; kb < 32; kb += 16) {
            uint32_t ah[2][4], al[2][4];
#pragma unroll
            for (int mt = 0; mt < 2; mt++) {
                uint32_t ad = so + (uint32_t)((wm * 32 + mt * 16 + arow) * SKS) * 2
                              + (uint32_t)(kb + acol) * 2;
                LDSM4(ah[mt][0], ah[mt][1], ah[mt][2], ah[mt][3], ad);
                LDSM4(al[mt][0], al[mt][1], al[mt][2], al[mt][3], ad + PA_B);
            }
            // B via ldmatrix.trans on [k][n] tile:
            // r0,r1 = b-pair for first 8 n cols; r2,r3 for next 8
            uint32_t bh[2][4], bl[2][4];
#pragma unroll
            for (int p = 0; p < 2; p++) {
                uint32_t bd = so + 2 * PA_B
                              + (uint32_t)((kb + (lane & 15)) * PB_RS)
                              + (uint32_t)(wn * 32 + p * 16 + ((lane >> 4) << 3)) * 2;
                LDSM4T(bh[p][0], bh[p][1], bh[p][2], bh[p][3], bd);
                LDSM4T(bl[p][0], bl[p][1], bl[p][2], bl[p][3], bd + PB_B);
            }
#pragma unroll
            for (int mt = 0; mt < 2; mt++)
#pragma unroll
                for (int nt = 0; nt < 4; nt++) {
                    const int p = nt >> 1, q = (nt & 1) * 2;
                    MMA_BF16(c[mt][nt], ah[mt], bh[p][q], bh[p][q + 1]);
                    MMA_BF16(c[mt][nt], ah[mt], bl[p][q], bl[p][q + 1]);
                    MMA_BF16(c[mt][nt], al[mt], bh[p][q], bh[p][q + 1]);
                }
        }
        __syncthreads();
    }

    // epilogue: + bias[m] (row bias), fp32 out
#pragma unroll
    for (int mt = 0; mt < 2; mt++) {
        int row = m0 + wm * 32 + mt * 16 + gid;
        float br0 = bias[row], br8 = bias[row + 8];
#pragma unroll
        for (int nt = 0; nt < 4; nt++) {
            int col = n0 + wn * 32 + nt * 8 + tig * 2;
            float2 o0 = {c[mt][nt][0] + br0, c[mt][nt][1] + br0};
            float2 o1 = {c[mt][nt][2] + br8, c[mt][nt][3] + br8};
            *(float2*)(C + ((size_t)b * PROJK + row) * EMB + col)       = o0;
            *(float2*)(C + ((size_t)b * PROJK + row + 8) * EMB + col)   = o1;
        }
    }
}

// ================================================================
// Fused attention — writes ctx directly as bf16 hi/lo split
// ================================================================
#define KHT_STRIDE 257
__global__ __launch_bounds__(256)
void attn_kernel(const float* __restrict__ q,
                 const float* __restrict__ kproj,
                 const float* __restrict__ vproj,
                 ushort_t* __restrict__ ctx_h,
                 ushort_t* __restrict__ ctx_l)
{
    extern __shared__ float sm[];
    float* khT = sm;                           // [64][257]
    float* vh  = khT + 64 * KHT_STRIDE;        // [256][64]
    float* qs  = vh + 256 * 64;                // [64][64]
    float* ps  = qs + 64 * 64;                 // [8][4][256]

    const int b    = blockIdx.z;
    const int h    = blockIdx.y;
    const int s0   = blockIdx.x * 64;
    const int tid  = threadIdx.x;
    const int w    = tid >> 5;
    const int lane = tid & 31;

    const float* kpB = kproj + ((size_t)b * PROJK) * EMB + h * KDIM;
    const float* vpB = vproj + ((size_t)b * PROJK) * EMB + h * KDIM;
    for (int i = tid; i < PROJK * KDIM; i += 256) {
        int kp = i >> 6, d = i & 63;
        khT[d * KHT_STRIDE + kp] = kpB[(size_t)kp * EMB + d];
        vh[i]                    = vpB[(size_t)kp * EMB + d];
    }
    const float* qB = q + ((size_t)(b * SEQ + s0)) * EMB + h * KDIM;
    for (int i = tid; i < 64 * 64; i += 256) {
        int r = i >> 6, d = i & 63;
        qs[i] = qB[(size_t)r * EMB + d];
    }
    __syncthreads();

    float* myp = ps + w * 4 * 256;

    for (int g = 0; g < 2; g++) {
        const int rbase = w * 8 + g * 4;

        float s[4][8];
#pragma unroll
        for (int r = 0; r < 4; r++)
#pragma unroll
            for (int j = 0; j < 8; j++) s[r][j] = 0.f;

#pragma unroll 4
        for (int d = 0; d < 64; d++) {
            float kv[8];
#pragma unroll
            for (int j = 0; j < 8; j++)
                kv[j] = khT[d * KHT_STRIDE + lane + 32 * j];
#pragma unroll
            for (int r = 0; r < 4; r++) {
                float qv = qs[(rbase + r) * 64 + d];
#pragma unroll
                for (int j = 0; j < 8; j++)
                    s[r][j] = fmaf(qv, kv[j], s[r][j]);
            }
        }

        float inv[4];
#pragma unroll
        for (int r = 0; r < 4; r++) {
            float m = s[r][0];
#pragma unroll
            for (int j = 1; j < 8; j++) m = fmaxf(m, s[r][j]);
#pragma unroll
            for (int o = 16; o > 0; o >>= 1)
                m = fmaxf(m, __shfl_xor_sync(0xFFFFFFFFu, m, o));
            float sum = 0.f;
#pragma unroll
            for (int j = 0; j < 8; j++) {
                s[r][j] = __expf(s[r][j] - m);
                sum += s[r][j];
            }
#pragma unroll
            for (int o = 16; o > 0; o >>= 1)
                sum += __shfl_xor_sync(0xFFFFFFFFu, sum, o);
            inv[r] = 1.f / sum;
#pragma unroll
            for (int j = 0; j < 8; j++)
                myp[r * 256 + lane + 32 * j] = s[r][j];
        }
        __syncwarp();

        float acc[4][2];
#pragma unroll
        for (int r = 0; r < 4; r++) { acc[r][0] = 0.f; acc[r][1] = 0.f; }

#pragma unroll 4
        for (int kp = 0; kp < 256; kp++) {
            float v0 = vh[kp * 64 + lane];
            float v1 = vh[kp * 64 + lane + 32];
#pragma unroll
            for (int r = 0; r < 4; r++) {
                float p = myp[r * 256 + kp];
                acc[r][0] = fmaf(p, v0, acc[r][0]);
                acc[r][1] = fmaf(p, v1, acc[r][1]);
            }
        }

#pragma unroll
        for (int r = 0; r < 4; r++) {
            size_t row = (size_t)(b * SEQ + s0 + rbase + r);
            ushort_t h0, l0, h1, l1;
            split1(acc[r][0] * inv[r], h0, l0);
            split1(acc[r][1] * inv[r], h1, l1);
            size_t base = row * EMB + h * KDIM;
            ctx_h[base + lane]      = h0;
            ctx_l[base + lane]      = l0;
            ctx_h[base + lane + 32] = h1;
            ctx_l[base + lane + 32] = l1;
        }
        __syncwarp();
    }
}

// ================================================================
// Launch
// ================================================================
extern "C" void kernel_launch(void* const* d_in, const int* in_sizes, int n_in,
                              void* d_out, int out_size)
{
    const float* query = (const float*)d_in[0];
    const float* value = (const float*)d_in[1];
    const float* Wq    = (const float*)d_in[2];
    const float* bq    = (const float*)d_in[3];
    const float* Wk    = (const float*)d_in[4];
    const float* bk    = (const float*)d_in[5];
    const float* Wv    = (const float*)d_in[6];
    const float* bv    = (const float*)d_in[7];
    const float* Wo    = (const float*)d_in[8];
    const float* bo    = (const float*)d_in[9];
    const float* E     = (const float*)d_in[10];
    const float* Eb    = (const float*)d_in[11];
    const float* F     = (const float*)d_in[12];
    const float* Fb    = (const float*)d_in[13];
    float* out = (float*)d_out;

    float *gq, *gkp, *gvp;
    ushort_t *qah, *qal, *vah, *val_, *cth, *ctl;
    ushort_t *kbh, *kbl, *vbh, *vbl;
    ushort_t *wqh, *wql, *wkh, *wkl, *wvh, *wvl, *woh, *wol;
    ushort_t *eth, *etl, *fth, *ftl;
    cudaGetSymbolAddress((void**)&gq,  g_q);
    cudaGetSymbolAddress((void**)&gkp, g_kp);
    cudaGetSymbolAddress((void**)&gvp, g_vp);
    cudaGetSymbolAddress((void**)&qah, g_qA_h);
    cudaGetSymbolAddress((void**)&qal, g_qA_l);
    cudaGetSymbolAddress((void**)&vah, g_vA_h);
    cudaGetSymbolAddress((void**)&val_, g_vA_l);
    cudaGetSymbolAddress((void**)&cth, g_ctx_h);
    cudaGetSymbolAddress((void**)&ctl, g_ctx_l);
    cudaGetSymbolAddress((void**)&kbh, g_kb_h);
    cudaGetSymbolAddress((void**)&kbl, g_kb_l);
    cudaGetSymbolAddress((void**)&vbh, g_vb_h);
    cudaGetSymbolAddress((void**)&vbl, g_vb_l);
    cudaGetSymbolAddress((void**)&wqh, g_wqT_h);
    cudaGetSymbolAddress((void**)&wql, g_wqT_l);
    cudaGetSymbolAddress((void**)&wkh, g_wkT_h);
    cudaGetSymbolAddress((void**)&wkl, g_wkT_l);
    cudaGetSymbolAddress((void**)&wvh, g_wvT_h);
    cudaGetSymbolAddress((void**)&wvl, g_wvT_l);
    cudaGetSymbolAddress((void**)&woh, g_woT_h);
    cudaGetSymbolAddress((void**)&wol, g_woT_l);
    cudaGetSymbolAddress((void**)&eth, g_ETh);
    cudaGetSymbolAddress((void**)&etl, g_ETl);
    cudaGetSymbolAddress((void**)&fth, g_FTh);
    cudaGetSymbolAddress((void**)&ftl, g_FTl);

    const float scale = 1.0f / 8.0f;   // 64^-0.5
    const int nbig = MROWS * EMB;      // 8388608

    // 1) split inputs
    split_kernel<<<nbig / 1024, 256>>>(query, qah, qal, nbig);
    split_kernel<<<nbig / 1024, 256>>>(value, vah, val_, nbig);
    // 2) split+transpose weights and Linformer matrices
    dim3 tg(EMB / 32, EMB / 32), tb(32, 8);
    split_transpose_kernel<<<tg, tb>>>(Wq, wqh, wql, EMB, EMB);
    split_transpose_kernel<<<tg, tb>>>(Wk, wkh, wkl, EMB, EMB);
    split_transpose_kernel<<<tg, tb>>>(Wv, wvh, wvl, EMB, EMB);
    split_transpose_kernel<<<tg, tb>>>(Wo, woh, wol, EMB, EMB);
    dim3 eg(PROJK / 32, SEQ / 32);
    split_transpose_kernel<<<eg, tb>>>(E, eth, etl, SEQ, PROJK);
    split_transpose_kernel<<<eg, tb>>>(F, fth, ftl, SEQ, PROJK);

    // 3) QKV GEMMs (tensor cores, 3-stage)
    cudaFuncSetAttribute(mma_gemm_ts<false>, cudaFuncAttributeMaxDynamicSharedMemorySize, NSTAGE * STAGE_B);
    cudaFuncSetAttribute(mma_gemm_ts<true>,  cudaFuncAttributeMaxDynamicSharedMemorySize, NSTAGE * STAGE_B);
    dim3 g_big(EMB / 128, MROWS / 128);   // (8, 64)
    mma_gemm_ts<false><<<g_big, 256, NSTAGE * STAGE_B>>>(qah, qal, wqh, wql, bq, gq, 0, 0, EMB, EMB, scale);
    mma_gemm_ts<true ><<<g_big, 256, NSTAGE * STAGE_B>>>(vah, val_, wkh, wkl, bk, 0, kbh, kbl, EMB, EMB, 1.0f);
    mma_gemm_ts<true ><<<g_big, 256, NSTAGE * STAGE_B>>>(vah, val_, wvh, wvl, bv, 0, vbh, vbl, EMB, EMB, 1.0f);

    // 4) Linformer projections (tensor cores)
    cudaFuncSetAttribute(proj_mma, cudaFuncAttributeMaxDynamicSharedMemorySize, NSTAGE * PSTAGE_B);
    dim3 g_proj(EMB / 128, PROJK / 64, BATCH);  // (8, 4, 4)
    proj_mma<<<g_proj, 256, NSTAGE * PSTAGE_B>>>(eth, etl, kbh, kbl, Eb, gkp);
    proj_mma<<<g_proj, 256, NSTAGE * PSTAGE_B>>>(fth, ftl, vbh, vbl, Fb, gvp);

    // 5) fused attention -> ctx (bf16 split)
    size_t attn_smem = (size_t)(64 * KHT_STRIDE + 256 * 64 + 64 * 64 + 8 * 4 * 256) * sizeof(float);
    cudaFuncSetAttribute(attn_kernel, cudaFuncAttributeMaxDynamicSharedMemorySize, (int)attn_smem);
    dim3 attn_grid(SEQ / 64, HEADS, BATCH);
    attn_kernel<<<attn_grid, 256, attn_smem>>>(gq, gkp, gvp, cth, ctl);

    // 6) output projection (tensor cores)
    mma_gemm_ts<false><<<g_big, 256, NSTAGE * STAGE_B>>>(cth, ctl, woh, wol, bo, out, 0, 0, EMB, EMB, 1.0f);
}

// round 10
// speedup vs baseline: 2.1143x; 1.1131x over previous
#include <cuda_runtime.h>
#include <cuda_bf16.h>
#include <math.h>
#include <stdint.h>

// Problem constants
#define BATCH 4
#define SEQ   2048
#define EMB   1024     // H * Dk
#define HEADS 16
#define KDIM  64
#define PROJK 256
#define MROWS (BATCH * SEQ)   // 8192

typedef unsigned short ushort_t;

// ---------------- scratch (allocation-free) ----------------
__device__ float g_q [MROWS * EMB];
__device__ float g_kp[BATCH * PROJK * EMB];
__device__ float g_vp[BATCH * PROJK * EMB];
__device__ ushort_t g_qA_h[MROWS * EMB], g_qA_l[MROWS * EMB];
__device__ ushort_t g_vA_h[MROWS * EMB], g_vA_l[MROWS * EMB];
__device__ ushort_t g_ctx_h[MROWS * EMB], g_ctx_l[MROWS * EMB];
__device__ ushort_t g_kb_h[MROWS * EMB], g_kb_l[MROWS * EMB];
__device__ ushort_t g_vb_h[MROWS * EMB], g_vb_l[MROWS * EMB];
__device__ ushort_t g_wqT_h[EMB * EMB], g_wqT_l[EMB * EMB];
__device__ ushort_t g_wkT_h[EMB * EMB], g_wkT_l[EMB * EMB];
__device__ ushort_t g_wvT_h[EMB * EMB], g_wvT_l[EMB * EMB];
__device__ ushort_t g_woT_h[EMB * EMB], g_woT_l[EMB * EMB];
__device__ ushort_t g_ETh[PROJK * SEQ], g_ETl[PROJK * SEQ];
__device__ ushort_t g_FTh[PROJK * SEQ], g_FTl[PROJK * SEQ];

// ---------------- helpers ----------------
__device__ __forceinline__ void split1(float v, ushort_t& h, ushort_t& l) {
    __nv_bfloat16 hh = __float2bfloat16(v);
    __nv_bfloat16 ll = __float2bfloat16(v - __bfloat162float(hh));
    h = __bfloat16_as_ushort(hh);
    l = __bfloat16_as_ushort(ll);
}

#define MMA_BF16(d, a, b0, b1) asm volatile( \
    "mma.sync.aligned.m16n8k16.row.col.f32.bf16.bf16.f32 " \
    "{%0,%1,%2,%3}, {%4,%5,%6,%7}, {%8,%9}, {%0,%1,%2,%3};\n" \
    : "+f"((d)[0]), "+f"((d)[1]), "+f"((d)[2]), "+f"((d)[3]) \
    : "r"((a)[0]), "r"((a)[1]), "r"((a)[2]), "r"((a)[3]), \
      "r"(b0), "r"(b1))

#define LDSM4(r0, r1, r2, r3, addr) asm volatile( \
    "ldmatrix.sync.aligned.m8n8.x4.shared.b16 {%0,%1,%2,%3}, [%4];\n" \
    : "=r"(r0), "=r"(r1), "=r"(r2), "=r"(r3) : "r"(addr))

#define LDSM4T(r0, r1, r2, r3, addr) asm volatile( \
    "ldmatrix.sync.aligned.m8n8.x4.trans.shared.b16 {%0,%1,%2,%3}, [%4];\n" \
    : "=r"(r0), "=r"(r1), "=r"(r2), "=r"(r3) : "r"(addr))

__device__ __forceinline__ void cp16(uint32_t dst, const void* src) {
    asm volatile("cp.async.cg.shared.global [%0], [%1], 16;\n" :: "r"(dst), "l"(src));
}
#define CP_COMMIT() asm volatile("cp.async.commit_group;\n" ::: "memory")
#define CP_WAIT2()  asm volatile("cp.async.wait_group 2;\n" ::: "memory")

// ================================================================
// split_kernel: fp32 -> bf16 hi/lo, vectorized. n % 4 == 0
// ================================================================
__global__ __launch_bounds__(256)
void split_kernel(const float* __restrict__ src,
                  ushort_t* __restrict__ hi,
                  ushort_t* __restrict__ lo, int n)
{
    int i = (blockIdx.x * 256 + threadIdx.x) * 4;
    if (i >= n) return;
    float4 v = *(const float4*)(src + i);
    ushort4 h, l;
    split1(v.x, h.x, l.x);
    split1(v.y, h.y, l.y);
    split1(v.z, h.z, l.z);
    split1(v.w, h.w, l.w);
    *(ushort4*)(hi + i) = h;
    *(ushort4*)(lo + i) = l;
}

// ================================================================
// Batched split+transpose: W[K][N] fp32 -> WT[N][K] bf16 hi/lo
// grid (N/32, K/32, njobs), block (32,8)
// ================================================================
struct TransJob { const float* W; ushort_t* hi; ushort_t* lo; };
struct TransJobs { TransJob j[4]; };

__global__ __launch_bounds__(256)
void split_transpose_b(TransJobs jobs, int K, int N)
{
    __shared__ float t[32][33];
    const TransJob jb = jobs.j[blockIdx.z];
    int k0 = blockIdx.y * 32, n0 = blockIdx.x * 32;
    int tx = threadIdx.x, ty = threadIdx.y;
#pragma unroll
    for (int i = 0; i < 32; i += 8)
        t[ty + i][tx] = jb.W[(size_t)(k0 + ty + i) * N + n0 + tx];
    __syncthreads();
#pragma unroll
    for (int i = 0; i < 32; i += 8) {
        float v = t[tx][ty + i];
        ushort_t h, l;
        split1(v, h, l);
        jb.hi[(size_t)(n0 + ty + i) * K + k0 + tx] = h;
        jb.lo[(size_t)(n0 + ty + i) * K + k0 + tx] = l;
    }
}

// ================================================================
// Big tensor-core GEMM (bf16x3, mma.sync), 512 threads:
//   C[M][N] = (sum_k A[m][k]*B[n][k] + bias[n]) * alpha
// A,B pre-split bf16 hi/lo, [rows][K] k-contig.
// CTA 128x128, BK=32, 3-stage cp.async, 16 warps (4x4), warp 32x32.
// DUAL: grid.z selects (B0,bias0,out0)/(B1,bias1,out1) — fuses K+V.
// SPLIT_OUT: write bf16 hi/lo split (alpha must be 1).
// ================================================================
#define SKS 40                         // smem row stride in shorts (80B)
#define ARR_B (128 * SKS * 2)          // 10240 bytes per array
#define STAGE_B (4 * ARR_B)            // 40960 bytes per stage
#define NSTAGE 3

template<bool SPLIT_OUT, bool DUAL>
__global__ __launch_bounds__(512)
void mma_gemm5(const ushort_t* __restrict__ Agh,
               const ushort_t* __restrict__ Agl,
               const ushort_t* __restrict__ B0h,
               const ushort_t* __restrict__ B0l,
               const ushort_t* __restrict__ B1h,
               const ushort_t* __restrict__ B1l,
               const float* __restrict__ bias0,
               const float* __restrict__ bias1,
               float* __restrict__ C,
               ushort_t* __restrict__ C0h, ushort_t* __restrict__ C0l,
               ushort_t* __restrict__ C1h, ushort_t* __restrict__ C1l,
               int N, int K, float alpha)
{
    extern __shared__ unsigned char smraw[];
    const uint32_t smb = (uint32_t)__cvta_generic_to_shared(smraw);

    const int tid  = threadIdx.x;
    const int wid  = tid >> 5;
    const int lane = tid & 31;
    const int gid  = lane >> 2;
    const int tig  = lane & 3;
    const int wm   = wid >> 2;   // 0..3
    const int wn   = wid & 3;    // 0..3
    const int m0   = blockIdx.y * 128;
    const int n0   = blockIdx.x * 128;

    const int z = DUAL ? (int)blockIdx.z : 0;
    const ushort_t* Bgh = (DUAL && z) ? B1h : B0h;
    const ushort_t* Bgl = (DUAL && z) ? B1l : B0l;
    const float*   bias = (DUAL && z) ? bias1 : bias0;
    ushort_t* Ch = (DUAL && z) ? C1h : C0h;
    ushort_t* Cl = (DUAL && z) ? C1l : C0l;

    // cp.async mapping: 512 threads, 1 x 16B chunk per array each
    const int lrow = tid >> 2;          // 0..127
    const int lcf  = (tid & 3) * 8;     // element offset (8 shorts = 16B)

    auto issue = [&](int s, int kt) {
        const int k0 = kt * 32;
        const uint32_t so = smb + s * STAGE_B;
        const uint32_t ro = (uint32_t)(lrow * SKS + lcf) * 2;
        const size_t ga = (size_t)(m0 + lrow) * K + k0 + lcf;
        const size_t gb = (size_t)(n0 + lrow) * K + k0 + lcf;
        cp16(so + ro,             Agh + ga);
        cp16(so + ARR_B + ro,     Agl + ga);
        cp16(so + 2 * ARR_B + ro, Bgh + gb);
        cp16(so + 3 * ARR_B + ro, Bgl + gb);
    };

    float c[2][4][4];
#pragma unroll
    for (int i = 0; i < 2; i++)
#pragma unroll
        for (int j = 0; j < 4; j++)
#pragma unroll
            for (int l = 0; l < 4; l++) c[i][j][l] = 0.f;

    const int nk = K / 32;
    issue(0, 0); CP_COMMIT();
    issue(1, 1); CP_COMMIT();

    const int arow = lane & 15;
    const int acol = (lane >> 4) << 3;   // 0 or 8

    for (int kt = 0; kt < nk; kt++) {
        if (kt + 2 < nk) issue((kt + 2) % NSTAGE, kt + 2);
        CP_COMMIT();
        CP_WAIT2();
        __syncthreads();
        const uint32_t so = smb + (kt % NSTAGE) * STAGE_B;

#pragma unroll
        for (int kb = 0; kb < 32; kb += 16) {
            const uint32_t koff = (uint32_t)(kb + acol) * 2;
            uint32_t ah[2][4], al[2][4];
#pragma unroll
            for (int mt = 0; mt < 2; mt++) {
                uint32_t ad = so + (uint32_t)((wm * 32 + mt * 16 + arow) * SKS) * 2 + koff;
                LDSM4(ah[mt][0], ah[mt][1], ah[mt][2], ah[mt][3], ad);
                LDSM4(al[mt][0], al[mt][1], al[mt][2], al[mt][3], ad + ARR_B);
            }
            uint32_t bh[2][4], bl[2][4];
#pragma unroll
            for (int p = 0; p < 2; p++) {
                uint32_t bd = so + 2 * ARR_B +
                              (uint32_t)((wn * 32 + p * 16 + arow) * SKS) * 2 + koff;
                LDSM4(bh[p][0], bh[p][1], bh[p][2], bh[p][3], bd);
                LDSM4(bl[p][0], bl[p][1], bl[p][2], bl[p][3], bd + ARR_B);
            }
#pragma unroll
            for (int mt = 0; mt < 2; mt++)
#pragma unroll
                for (int nt = 0; nt < 4; nt++) {
                    const int p = nt >> 1, q = nt & 1;
                    MMA_BF16(c[mt][nt], ah[mt], bh[p][q], bh[p][q + 2]);
                    MMA_BF16(c[mt][nt], ah[mt], bl[p][q], bl[p][q + 2]);
                    MMA_BF16(c[mt][nt], al[mt], bh[p][q], bh[p][q + 2]);
                }
        }
        __syncthreads();
    }

    // epilogue
#pragma unroll
    for (int mt = 0; mt < 2; mt++) {
        int row = m0 + wm * 32 + mt * 16 + gid;
#pragma unroll
        for (int nt = 0; nt < 4; nt++) {
            int col = n0 + wn * 32 + nt * 8 + tig * 2;
            float b0 = bias[col], b1 = bias[col + 1];
            float v00 = (c[mt][nt][0] + b0) * alpha;
            float v01 = (c[mt][nt][1] + b1) * alpha;
            float v10 = (c[mt][nt][2] + b0) * alpha;
            float v11 = (c[mt][nt][3] + b1) * alpha;
            if (SPLIT_OUT) {
                ushort2 h0, l0, h1, l1;
                split1(v00, h0.x, l0.x); split1(v01, h0.y, l0.y);
                split1(v10, h1.x, l1.x); split1(v11, h1.y, l1.y);
                *(ushort2*)(Ch + (size_t)row * N + col)       = h0;
                *(ushort2*)(Cl + (size_t)row * N + col)       = l0;
                *(ushort2*)(Ch + (size_t)(row + 8) * N + col) = h1;
                *(ushort2*)(Cl + (size_t)(row + 8) * N + col) = l1;
            } else {
                float2 o0 = {v00, v01}, o1 = {v10, v11};
                *(float2*)(C + (size_t)row * N + col)       = o0;
                *(float2*)(C + (size_t)(row + 8) * N + col) = o1;
            }
        }
    }
}

// ================================================================
// Projection MMA (unchanged, proven): C = ET @ X + bias(row)
// ================================================================
#define PA_B (64 * SKS * 2)
#define PB_RS 272
#define PB_B (32 * PB_RS)
#define PSTAGE_B (2 * PA_B + 2 * PB_B)

__global__ __launch_bounds__(256)
void proj_mma(const ushort_t* __restrict__ ETh,
              const ushort_t* __restrict__ ETl,
              const ushort_t* __restrict__ Xh,
              const ushort_t* __restrict__ Xl,
              const float* __restrict__ bias,
              float* __restrict__ C)
{
    extern __shared__ unsigned char smraw[];
    const uint32_t smb = (uint32_t)__cvta_generic_to_shared(smraw);

    const int tid  = threadIdx.x;
    const int wid  = tid >> 5;
    const int lane = tid & 31;
    const int gid  = lane >> 2;
    const int tig  = lane & 3;
    const int wm   = wid >> 2;
    const int wn   = wid & 3;
    const int b    = blockIdx.z;
    const int m0   = blockIdx.y * 64;
    const int n0   = blockIdx.x * 128;

    const ushort_t* Xbh = Xh + (size_t)b * SEQ * EMB;
    const ushort_t* Xbl = Xl + (size_t)b * SEQ * EMB;

    auto issue = [&](int s, int kt) {
        const int k0 = kt * 32;
        const uint32_t so = smb + s * PSTAGE_B;
        {
            int row = tid >> 2, cf = (tid & 3);
            uint32_t sa = so + (uint32_t)(row * SKS) * 2 + cf * 16;
            size_t ga = (size_t)(m0 + row) * SEQ + k0 + cf * 8;
            cp16(sa,        ETh + ga);
            cp16(sa + PA_B, ETl + ga);
        }
#pragma unroll
        for (int half = 0; half < 2; half++) {
            int cidx = half * 256 + tid;
            int row = cidx >> 4, cf = cidx & 15;
            uint32_t sb = so + 2 * PA_B + (uint32_t)(row * PB_RS) + cf * 16;
            size_t gb = (size_t)(k0 + row) * EMB + n0 + cf * 8;
            cp16(sb,        Xbh + gb);
            cp16(sb + PB_B, Xbl + gb);
        }
    };

    float c[2][4][4];
#pragma unroll
    for (int i = 0; i < 2; i++)
#pragma unroll
        for (int j = 0; j < 4; j++)
#pragma unroll
            for (int l = 0; l < 4; l++) c[i][j][l] = 0.f;

    const int nk = SEQ / 32;
    issue(0, 0); CP_COMMIT();
    issue(1, 1); CP_COMMIT();

    const int arow = lane & 15;
    const int acol = (lane >> 4) << 3;

    for (int kt = 0; kt < nk; kt++) {
        if (kt + 2 < nk) issue((kt + 2) % NSTAGE, kt + 2);
        CP_COMMIT();
        CP_WAIT2();
        __syncthreads();
        const uint32_t so = smb + (kt % NSTAGE) * PSTAGE_B;

#pragma unroll
        for (int kb = 0; kb < 32; kb += 16) {
            uint32_t ah[2][4], al[2][4];
#pragma unroll
            for (int mt = 0; mt < 2; mt++) {
                uint32_t ad = so + (uint32_t)((wm * 32 + mt * 16 + arow) * SKS) * 2
                              + (uint32_t)(kb + acol) * 2;
                LDSM4(ah[mt][0], ah[mt][1], ah[mt][2], ah[mt][3], ad);
                LDSM4(al[mt][0], al[mt][1], al[mt][2], al[mt][3], ad + PA_B);
            }
            uint32_t bh[2][4], bl[2][4];
#pragma unroll
            for (int p = 0; p < 2; p++) {
                uint32_t bd = so + 2 * PA_B
                              + (uint32_t)((kb + (lane & 15)) * PB_RS)
                              + (uint32_t)(wn * 32 + p * 16 + ((lane >> 4) << 3)) * 2;
                LDSM4T(bh[p][0], bh[p][1], bh[p][2], bh[p][3], bd);
                LDSM4T(bl[p][0], bl[p][1], bl[p][2], bl[p][3], bd + PB_B);
            }
#pragma unroll
            for (int mt = 0; mt < 2; mt++)
#pragma unroll
                for (int nt = 0; nt < 4; nt++) {
                    const int p = nt >> 1, q = (nt & 1) * 2;
                    MMA_BF16(c[mt][nt], ah[mt], bh[p][q], bh[p][q + 1]);
                    MMA_BF16(c[mt][nt], ah[mt], bl[p][q], bl[p][q + 1]);
                    MMA_BF16(c[mt][nt], al[mt], bh[p][q], bh[p][q + 1]);
                }
        }
        __syncthreads();
    }

#pragma unroll
    for (int mt = 0; mt < 2; mt++) {
        int row = m0 + wm * 32 + mt * 16 + gid;
        float br0 = bias[row], br8 = bias[row + 8];
#pragma unroll
        for (int nt = 0; nt < 4; nt++) {
            int col = n0 + wn * 32 + nt * 8 + tig * 2;
            float2 o0 = {c[mt][nt][0] + br0, c[mt][nt][1] + br0};
            float2 o1 = {c[mt][nt][2] + br8, c[mt][nt][3] + br8};
            *(float2*)(C + ((size_t)b * PROJK + row) * EMB + col)     = o0;
            *(float2*)(C + ((size_t)b * PROJK + row + 8) * EMB + col) = o1;
        }
    }
}

// ================================================================
// Fused attention — writes ctx as bf16 hi/lo split (unchanged)
// ================================================================
#define KHT_STRIDE 257
__global__ __launch_bounds__(256)
void attn_kernel(const float* __restrict__ q,
                 const float* __restrict__ kproj,
                 const float* __restrict__ vproj,
                 ushort_t* __restrict__ ctx_h,
                 ushort_t* __restrict__ ctx_l)
{
    extern __shared__ float sm[];
    float* khT = sm;
    float* vh  = khT + 64 * KHT_STRIDE;
    float* qs  = vh + 256 * 64;
    float* ps  = qs + 64 * 64;

    const int b    = blockIdx.z;
    const int h    = blockIdx.y;
    const int s0   = blockIdx.x * 64;
    const int tid  = threadIdx.x;
    const int w    = tid >> 5;
    const int lane = tid & 31;

    const float* kpB = kproj + ((size_t)b * PROJK) * EMB + h * KDIM;
    const float* vpB = vproj + ((size_t)b * PROJK) * EMB + h * KDIM;
    for (int i = tid; i < PROJK * KDIM; i += 256) {
        int kp = i >> 6, d = i & 63;
        khT[d * KHT_STRIDE + kp] = kpB[(size_t)kp * EMB + d];
        vh[i]                    = vpB[(size_t)kp * EMB + d];
    }
    const float* qB = q + ((size_t)(b * SEQ + s0)) * EMB + h * KDIM;
    for (int i = tid; i < 64 * 64; i += 256) {
        int r = i >> 6, d = i & 63;
        qs[i] = qB[(size_t)r * EMB + d];
    }
    __syncthreads();

    float* myp = ps + w * 4 * 256;

    for (int g = 0; g < 2; g++) {
        const int rbase = w * 8 + g * 4;

        float s[4][8];
#pragma unroll
        for (int r = 0; r < 4; r++)
#pragma unroll
            for (int j = 0; j < 8; j++) s[r][j] = 0.f;

#pragma unroll 4
        for (int d = 0; d < 64; d++) {
            float kv[8];
#pragma unroll
            for (int j = 0; j < 8; j++)
                kv[j] = khT[d * KHT_STRIDE + lane + 32 * j];
#pragma unroll
            for (int r = 0; r < 4; r++) {
                float qv = qs[(rbase + r) * 64 + d];
#pragma unroll
                for (int j = 0; j < 8; j++)
                    s[r][j] = fmaf(qv, kv[j], s[r][j]);
            }
        }

        float inv[4];
#pragma unroll
        for (int r = 0; r < 4; r++) {
            float m = s[r][0];
#pragma unroll
            for (int j = 1; j < 8; j++) m = fmaxf(m, s[r][j]);
#pragma unroll
            for (int o = 16; o > 0; o >>= 1)
                m = fmaxf(m, __shfl_xor_sync(0xFFFFFFFFu, m, o));
            float sum = 0.f;
#pragma unroll
            for (int j = 0; j < 8; j++) {
                s[r][j] = __expf(s[r][j] - m);
                sum += s[r][j];
            }
#pragma unroll
            for (int o = 16; o > 0; o >>= 1)
                sum += __shfl_xor_sync(0xFFFFFFFFu, sum, o);
            inv[r] = 1.f / sum;
#pragma unroll
            for (int j = 0; j < 8; j++)
                myp[r * 256 + lane + 32 * j] = s[r][j];
        }
        __syncwarp();

        float acc[4][2];
#pragma unroll
        for (int r = 0; r < 4; r++) { acc[r][0] = 0.f; acc[r][1] = 0.f; }

#pragma unroll 4
        for (int kp = 0; kp < 256; kp++) {
            float v0 = vh[kp * 64 + lane];
            float v1 = vh[kp * 64 + lane + 32];
#pragma unroll
            for (int r = 0; r < 4; r++) {
                float p = myp[r * 256 + kp];
                acc[r][0] = fmaf(p, v0, acc[r][0]);
                acc[r][1] = fmaf(p, v1, acc[r][1]);
            }
        }

#pragma unroll
        for (int r = 0; r < 4; r++) {
            size_t row = (size_t)(b * SEQ + s0 + rbase + r);
            ushort_t h0, l0, h1, l1;
            split1(acc[r][0] * inv[r], h0, l0);
            split1(acc[r][1] * inv[r], h1, l1);
            size_t base = row * EMB + h * KDIM;
            ctx_h[base + lane]      = h0;
            ctx_l[base + lane]      = l0;
            ctx_h[base + lane + 32] = h1;
            ctx_l[base + lane + 32] = l1;
        }
        __syncwarp();
    }
}

// ================================================================
// Launch
// ================================================================
extern "C" void kernel_launch(void* const* d_in, const int* in_sizes, int n_in,
                              void* d_out, int out_size)
{
    const float* query = (const float*)d_in[0];
    const float* value = (const float*)d_in[1];
    const float* Wq    = (const float*)d_in[2];
    const float* bq    = (const float*)d_in[3];
    const float* Wk    = (const float*)d_in[4];
    const float* bk    = (const float*)d_in[5];
    const float* Wv    = (const float*)d_in[6];
    const float* bv    = (const float*)d_in[7];
    const float* Wo    = (const float*)d_in[8];
    const float* bo    = (const float*)d_in[9];
    const float* E     = (const float*)d_in[10];
    const float* Eb    = (const float*)d_in[11];
    const float* F     = (const float*)d_in[12];
    const float* Fb    = (const float*)d_in[13];
    float* out = (float*)d_out;

    float *gq, *gkp, *gvp;
    ushort_t *qah, *qal, *vah, *val_, *cth, *ctl;
    ushort_t *kbh, *kbl, *vbh, *vbl;
    ushort_t *wqh, *wql, *wkh, *wkl, *wvh, *wvl, *woh, *wol;
    ushort_t *eth, *etl, *fth, *ftl;
    cudaGetSymbolAddress((void**)&gq,  g_q);
    cudaGetSymbolAddress((void**)&gkp, g_kp);
    cudaGetSymbolAddress((void**)&gvp, g_vp);
    cudaGetSymbolAddress((void**)&qah, g_qA_h);
    cudaGetSymbolAddress((void**)&qal, g_qA_l);
    cudaGetSymbolAddress((void**)&vah, g_vA_h);
    cudaGetSymbolAddress((void**)&val_, g_vA_l);
    cudaGetSymbolAddress((void**)&cth, g_ctx_h);
    cudaGetSymbolAddress((void**)&ctl, g_ctx_l);
    cudaGetSymbolAddress((void**)&kbh, g_kb_h);
    cudaGetSymbolAddress((void**)&kbl, g_kb_l);
    cudaGetSymbolAddress((void**)&vbh, g_vb_h);
    cudaGetSymbolAddress((void**)&vbl, g_vb_l);
    cudaGetSymbolAddress((void**)&wqh, g_wqT_h);
    cudaGetSymbolAddress((void**)&wql, g_wqT_l);
    cudaGetSymbolAddress((void**)&wkh, g_wkT_h);
    cudaGetSymbolAddress((void**)&wkl, g_wkT_l);
    cudaGetSymbolAddress((void**)&wvh, g_wvT_h);
    cudaGetSymbolAddress((void**)&wvl, g_wvT_l);
    cudaGetSymbolAddress((void**)&woh, g_woT_h);
    cudaGetSymbolAddress((void**)&wol, g_woT_l);
    cudaGetSymbolAddress((void**)&eth, g_ETh);
    cudaGetSymbolAddress((void**)&etl, g_ETl);
    cudaGetSymbolAddress((void**)&fth, g_FTh);
    cudaGetSymbolAddress((void**)&ftl, g_FTl);

    const float scale = 1.0f / 8.0f;
    const int nbig = MROWS * EMB;

    // 0-1) split inputs
    split_kernel<<<nbig / 1024, 256>>>(query, qah, qal, nbig);
    split_kernel<<<nbig / 1024, 256>>>(value, vah, val_, nbig);

    // 2) batched weight transposes (4 jobs)
    TransJobs wjobs;
    wjobs.j[0] = {Wq, wqh, wql};
    wjobs.j[1] = {Wk, wkh, wkl};
    wjobs.j[2] = {Wv, wvh, wvl};
    wjobs.j[3] = {Wo, woh, wol};
    dim3 tb(32, 8);
    split_transpose_b<<<dim3(EMB / 32, EMB / 32, 4), tb>>>(wjobs, EMB, EMB);

    // 3) batched E/F transposes (2 jobs)
    TransJobs ejobs;
    ejobs.j[0] = {E, eth, etl};
    ejobs.j[1] = {F, fth, ftl};
    ejobs.j[2] = {E, eth, etl};   // unused (grid.z = 2)
    ejobs.j[3] = {F, fth, ftl};
    split_transpose_b<<<dim3(PROJK / 32, SEQ / 32, 2), tb>>>(ejobs, SEQ, PROJK);

    // 4) Q GEMM; 5) fused K+V GEMM  (launch 5 = profiled window)
    cudaFuncSetAttribute(mma_gemm5<false, false>, cudaFuncAttributeMaxDynamicSharedMemorySize, NSTAGE * STAGE_B);
    cudaFuncSetAttribute(mma_gemm5<true,  true >, cudaFuncAttributeMaxDynamicSharedMemorySize, NSTAGE * STAGE_B);
    dim3 g_big(EMB / 128, MROWS / 128, 1);   // (8, 64)
    dim3 g_kv (EMB / 128, MROWS / 128, 2);   // (8, 64, 2)
    mma_gemm5<false, false><<<g_big, 512, NSTAGE * STAGE_B>>>(
        qah, qal, wqh, wql, 0, 0, bq, 0, gq, 0, 0, 0, 0, EMB, EMB, scale);
    mma_gemm5<true, true><<<g_kv, 512, NSTAGE * STAGE_B>>>(
        vah, val_, wkh, wkl, wvh, wvl, bk, bv, 0, kbh, kbl, vbh, vbl, EMB, EMB, 1.0f);

    // 6-7) Linformer projections
    cudaFuncSetAttribute(proj_mma, cudaFuncAttributeMaxDynamicSharedMemorySize, NSTAGE * PSTAGE_B);
    dim3 g_proj(EMB / 128, PROJK / 64, BATCH);
    proj_mma<<<g_proj, 256, NSTAGE * PSTAGE_B>>>(eth, etl, kbh, kbl, Eb, gkp);
    proj_mma<<<g_proj, 256, NSTAGE * PSTAGE_B>>>(fth, ftl, vbh, vbl, Fb, gvp);

    // 8) fused attention
    size_t attn_smem = (size_t)(64 * KHT_STRIDE + 256 * 64 + 64 * 64 + 8 * 4 * 256) * sizeof(float);
    cudaFuncSetAttribute(attn_kernel, cudaFuncAttributeMaxDynamicSharedMemorySize, (int)attn_smem);
    dim3 attn_grid(SEQ / 64, HEADS, BATCH);
    attn_kernel<<<attn_grid, 256, attn_smem>>>(gq, gkp, gvp, cth, ctl);

    // 9) output projection
    mma_gemm5<false, false><<<g_big, 512, NSTAGE * STAGE_B>>>(
        cth, ctl, woh, wol, 0, 0, bo, 0, out, 0, 0, 0, 0, EMB, EMB, 1.0f);
}

// round 11
// speedup vs baseline: 2.3461x; 1.1096x over previous
#include <cuda_runtime.h>
#include <cuda_bf16.h>
#include <math.h>
#include <stdint.h>

// Problem constants
#define BATCH 4
#define SEQ   2048
#define EMB   1024     // H * Dk
#define HEADS 16
#define KDIM  64
#define PROJK 256
#define MROWS (BATCH * SEQ)   // 8192

typedef unsigned short ushort_t;

// ---------------- scratch (allocation-free) ----------------
__device__ float g_q [MROWS * EMB];
__device__ float g_kp[BATCH * PROJK * EMB];
__device__ float g_vp[BATCH * PROJK * EMB];
__device__ ushort_t g_qA_h[MROWS * EMB], g_qA_l[MROWS * EMB];
__device__ ushort_t g_vA_h[MROWS * EMB], g_vA_l[MROWS * EMB];
__device__ ushort_t g_ctx_h[MROWS * EMB], g_ctx_l[MROWS * EMB];
__device__ ushort_t g_kb_h[MROWS * EMB], g_kb_l[MROWS * EMB];
__device__ ushort_t g_vb_h[MROWS * EMB], g_vb_l[MROWS * EMB];
__device__ ushort_t g_wqT_h[EMB * EMB], g_wqT_l[EMB * EMB];
__device__ ushort_t g_wkT_h[EMB * EMB], g_wkT_l[EMB * EMB];
__device__ ushort_t g_wvT_h[EMB * EMB], g_wvT_l[EMB * EMB];
__device__ ushort_t g_woT_h[EMB * EMB], g_woT_l[EMB * EMB];
__device__ ushort_t g_ETh[PROJK * SEQ], g_ETl[PROJK * SEQ];
__device__ ushort_t g_FTh[PROJK * SEQ], g_FTl[PROJK * SEQ];

// ---------------- helpers ----------------
__device__ __forceinline__ void split1(float v, ushort_t& h, ushort_t& l) {
    __nv_bfloat16 hh = __float2bfloat16(v);
    __nv_bfloat16 ll = __float2bfloat16(v - __bfloat162float(hh));
    h = __bfloat16_as_ushort(hh);
    l = __bfloat16_as_ushort(ll);
}

#define MMA_BF16(d, a, b0, b1) asm volatile( \
    "mma.sync.aligned.m16n8k16.row.col.f32.bf16.bf16.f32 " \
    "{%0,%1,%2,%3}, {%4,%5,%6,%7}, {%8,%9}, {%0,%1,%2,%3};\n" \
    : "+f"((d)[0]), "+f"((d)[1]), "+f"((d)[2]), "+f"((d)[3]) \
    : "r"((a)[0]), "r"((a)[1]), "r"((a)[2]), "r"((a)[3]), \
      "r"(b0), "r"(b1))

#define LDSM4(r0, r1, r2, r3, addr) asm volatile( \
    "ldmatrix.sync.aligned.m8n8.x4.shared.b16 {%0,%1,%2,%3}, [%4];\n" \
    : "=r"(r0), "=r"(r1), "=r"(r2), "=r"(r3) : "r"(addr))

#define LDSM4T(r0, r1, r2, r3, addr) asm volatile( \
    "ldmatrix.sync.aligned.m8n8.x4.trans.shared.b16 {%0,%1,%2,%3}, [%4];\n" \
    : "=r"(r0), "=r"(r1), "=r"(r2), "=r"(r3) : "r"(addr))

__device__ __forceinline__ void cp16(uint32_t dst, const void* src) {
    asm volatile("cp.async.cg.shared.global [%0], [%1], 16;\n" :: "r"(dst), "l"(src));
}
#define CP_COMMIT() asm volatile("cp.async.commit_group;\n" ::: "memory")
#define CP_WAIT2()  asm volatile("cp.async.wait_group 2;\n" ::: "memory")

// ================================================================
// split_kernel: fp32 -> bf16 hi/lo, vectorized
// ================================================================
__global__ __launch_bounds__(256)
void split_kernel(const float* __restrict__ src,
                  ushort_t* __restrict__ hi,
                  ushort_t* __restrict__ lo, int n)
{
    int i = (blockIdx.x * 256 + threadIdx.x) * 4;
    if (i >= n) return;
    float4 v = *(const float4*)(src + i);
    ushort4 h, l;
    split1(v.x, h.x, l.x);
    split1(v.y, h.y, l.y);
    split1(v.z, h.z, l.z);
    split1(v.w, h.w, l.w);
    *(ushort4*)(hi + i) = h;
    *(ushort4*)(lo + i) = l;
}

// ================================================================
// Batched split+transpose: W[K][N] fp32 -> WT[N][K] bf16 hi/lo
// ================================================================
struct TransJob { const float* W; ushort_t* hi; ushort_t* lo; };
struct TransJobs { TransJob j[4]; };

__global__ __launch_bounds__(256)
void split_transpose_b(TransJobs jobs, int K, int N)
{
    __shared__ float t[32][33];
    const TransJob jb = jobs.j[blockIdx.z];
    int k0 = blockIdx.y * 32, n0 = blockIdx.x * 32;
    int tx = threadIdx.x, ty = threadIdx.y;
#pragma unroll
    for (int i = 0; i < 32; i += 8)
        t[ty + i][tx] = jb.W[(size_t)(k0 + ty + i) * N + n0 + tx];
    __syncthreads();
#pragma unroll
    for (int i = 0; i < 32; i += 8) {
        float v = t[tx][ty + i];
        ushort_t h, l;
        split1(v, h, l);
        jb.hi[(size_t)(n0 + ty + i) * K + k0 + tx] = h;
        jb.lo[(size_t)(n0 + ty + i) * K + k0 + tx] = l;
    }
}

// ================================================================
// Big GEMM (bf16x3, mma.sync), 512 threads, 16 warps, warp 32x32
// (unchanged from R10 winner)
// ================================================================
#define SKS 40
#define ARR_B (128 * SKS * 2)
#define STAGE_B (4 * ARR_B)
#define NSTAGE 3

template<bool SPLIT_OUT, bool DUAL>
__global__ __launch_bounds__(512)
void mma_gemm5(const ushort_t* __restrict__ Agh,
               const ushort_t* __restrict__ Agl,
               const ushort_t* __restrict__ B0h,
               const ushort_t* __restrict__ B0l,
               const ushort_t* __restrict__ B1h,
               const ushort_t* __restrict__ B1l,
               const float* __restrict__ bias0,
               const float* __restrict__ bias1,
               float* __restrict__ C,
               ushort_t* __restrict__ C0h, ushort_t* __restrict__ C0l,
               ushort_t* __restrict__ C1h, ushort_t* __restrict__ C1l,
               int N, int K, float alpha)
{
    extern __shared__ unsigned char smraw[];
    const uint32_t smb = (uint32_t)__cvta_generic_to_shared(smraw);

    const int tid  = threadIdx.x;
    const int wid  = tid >> 5;
    const int lane = tid & 31;
    const int gid  = lane >> 2;
    const int tig  = lane & 3;
    const int wm   = wid >> 2;
    const int wn   = wid & 3;
    const int m0   = blockIdx.y * 128;
    const int n0   = blockIdx.x * 128;

    const int z = DUAL ? (int)blockIdx.z : 0;
    const ushort_t* Bgh = (DUAL && z) ? B1h : B0h;
    const ushort_t* Bgl = (DUAL && z) ? B1l : B0l;
    const float*   bias = (DUAL && z) ? bias1 : bias0;
    ushort_t* Ch = (DUAL && z) ? C1h : C0h;
    ushort_t* Cl = (DUAL && z) ? C1l : C0l;

    const int lrow = tid >> 2;
    const int lcf  = (tid & 3) * 8;

    auto issue = [&](int s, int kt) {
        const int k0 = kt * 32;
        const uint32_t so = smb + s * STAGE_B;
        const uint32_t ro = (uint32_t)(lrow * SKS + lcf) * 2;
        const size_t ga = (size_t)(m0 + lrow) * K + k0 + lcf;
        const size_t gb = (size_t)(n0 + lrow) * K + k0 + lcf;
        cp16(so + ro,             Agh + ga);
        cp16(so + ARR_B + ro,     Agl + ga);
        cp16(so + 2 * ARR_B + ro, Bgh + gb);
        cp16(so + 3 * ARR_B + ro, Bgl + gb);
    };

    float c[2][4][4];
#pragma unroll
    for (int i = 0; i < 2; i++)
#pragma unroll
        for (int j = 0; j < 4; j++)
#pragma unroll
            for (int l = 0; l < 4; l++) c[i][j][l] = 0.f;

    const int nk = K / 32;
    issue(0, 0); CP_COMMIT();
    issue(1, 1); CP_COMMIT();

    const int arow = lane & 15;
    const int acol = (lane >> 4) << 3;

    for (int kt = 0; kt < nk; kt++) {
        if (kt + 2 < nk) issue((kt + 2) % NSTAGE, kt + 2);
        CP_COMMIT();
        CP_WAIT2();
        __syncthreads();
        const uint32_t so = smb + (kt % NSTAGE) * STAGE_B;

#pragma unroll
        for (int kb = 0; kb < 32; kb += 16) {
            const uint32_t koff = (uint32_t)(kb + acol) * 2;
            uint32_t ah[2][4], al[2][4];
#pragma unroll
            for (int mt = 0; mt < 2; mt++) {
                uint32_t ad = so + (uint32_t)((wm * 32 + mt * 16 + arow) * SKS) * 2 + koff;
                LDSM4(ah[mt][0], ah[mt][1], ah[mt][2], ah[mt][3], ad);
                LDSM4(al[mt][0], al[mt][1], al[mt][2], al[mt][3], ad + ARR_B);
            }
            uint32_t bh[2][4], bl[2][4];
#pragma unroll
            for (int p = 0; p < 2; p++) {
                uint32_t bd = so + 2 * ARR_B +
                              (uint32_t)((wn * 32 + p * 16 + arow) * SKS) * 2 + koff;
                LDSM4(bh[p][0], bh[p][1], bh[p][2], bh[p][3], bd);
                LDSM4(bl[p][0], bl[p][1], bl[p][2], bl[p][3], bd + ARR_B);
            }
#pragma unroll
            for (int mt = 0; mt < 2; mt++)
#pragma unroll
                for (int nt = 0; nt < 4; nt++) {
                    const int p = nt >> 1, q = nt & 1;
                    MMA_BF16(c[mt][nt], ah[mt], bh[p][q], bh[p][q + 2]);
                    MMA_BF16(c[mt][nt], ah[mt], bl[p][q], bl[p][q + 2]);
                    MMA_BF16(c[mt][nt], al[mt], bh[p][q], bh[p][q + 2]);
                }
        }
        __syncthreads();
    }

#pragma unroll
    for (int mt = 0; mt < 2; mt++) {
        int row = m0 + wm * 32 + mt * 16 + gid;
#pragma unroll
        for (int nt = 0; nt < 4; nt++) {
            int col = n0 + wn * 32 + nt * 8 + tig * 2;
            float b0 = bias[col], b1 = bias[col + 1];
            float v00 = (c[mt][nt][0] + b0) * alpha;
            float v01 = (c[mt][nt][1] + b1) * alpha;
            float v10 = (c[mt][nt][2] + b0) * alpha;
            float v11 = (c[mt][nt][3] + b1) * alpha;
            if (SPLIT_OUT) {
                ushort2 h0, l0, h1, l1;
                split1(v00, h0.x, l0.x); split1(v01, h0.y, l0.y);
                split1(v10, h1.x, l1.x); split1(v11, h1.y, l1.y);
                *(ushort2*)(Ch + (size_t)row * N + col)       = h0;
                *(ushort2*)(Cl + (size_t)row * N + col)       = l0;
                *(ushort2*)(Ch + (size_t)(row + 8) * N + col) = h1;
                *(ushort2*)(Cl + (size_t)(row + 8) * N + col) = l1;
            } else {
                float2 o0 = {v00, v01}, o1 = {v10, v11};
                *(float2*)(C + (size_t)row * N + col)       = o0;
                *(float2*)(C + (size_t)(row + 8) * N + col) = o1;
            }
        }
    }
}

// ================================================================
// Projection MMA (unchanged, proven)
// ================================================================
#define PA_B (64 * SKS * 2)
#define PB_RS 272
#define PB_B (32 * PB_RS)
#define PSTAGE_B (2 * PA_B + 2 * PB_B)

__global__ __launch_bounds__(256)
void proj_mma(const ushort_t* __restrict__ ETh,
              const ushort_t* __restrict__ ETl,
              const ushort_t* __restrict__ Xh,
              const ushort_t* __restrict__ Xl,
              const float* __restrict__ bias,
              float* __restrict__ C)
{
    extern __shared__ unsigned char smraw[];
    const uint32_t smb = (uint32_t)__cvta_generic_to_shared(smraw);

    const int tid  = threadIdx.x;
    const int wid  = tid >> 5;
    const int lane = tid & 31;
    const int gid  = lane >> 2;
    const int tig  = lane & 3;
    const int wm   = wid >> 2;
    const int wn   = wid & 3;
    const int b    = blockIdx.z;
    const int m0   = blockIdx.y * 64;
    const int n0   = blockIdx.x * 128;

    const ushort_t* Xbh = Xh + (size_t)b * SEQ * EMB;
    const ushort_t* Xbl = Xl + (size_t)b * SEQ * EMB;

    auto issue = [&](int s, int kt) {
        const int k0 = kt * 32;
        const uint32_t so = smb + s * PSTAGE_B;
        {
            int row = tid >> 2, cf = (tid & 3);
            uint32_t sa = so + (uint32_t)(row * SKS) * 2 + cf * 16;
            size_t ga = (size_t)(m0 + row) * SEQ + k0 + cf * 8;
            cp16(sa,        ETh + ga);
            cp16(sa + PA_B, ETl + ga);
        }
#pragma unroll
        for (int half = 0; half < 2; half++) {
            int cidx = half * 256 + tid;
            int row = cidx >> 4, cf = cidx & 15;
            uint32_t sb = so + 2 * PA_B + (uint32_t)(row * PB_RS) + cf * 16;
            size_t gb = (size_t)(k0 + row) * EMB + n0 + cf * 8;
            cp16(sb,        Xbh + gb);
            cp16(sb + PB_B, Xbl + gb);
        }
    };

    float c[2][4][4];
#pragma unroll
    for (int i = 0; i < 2; i++)
#pragma unroll
        for (int j = 0; j < 4; j++)
#pragma unroll
            for (int l = 0; l < 4; l++) c[i][j][l] = 0.f;

    const int nk = SEQ / 32;
    issue(0, 0); CP_COMMIT();
    issue(1, 1); CP_COMMIT();

    const int arow = lane & 15;
    const int acol = (lane >> 4) << 3;

    for (int kt = 0; kt < nk; kt++) {
        if (kt + 2 < nk) issue((kt + 2) % NSTAGE, kt + 2);
        CP_COMMIT();
        CP_WAIT2();
        __syncthreads();
        const uint32_t so = smb + (kt % NSTAGE) * PSTAGE_B;

#pragma unroll
        for (int kb = 0; kb < 32; kb += 16) {
            uint32_t ah[2][4], al[2][4];
#pragma unroll
            for (int mt = 0; mt < 2; mt++) {
                uint32_t ad = so + (uint32_t)((wm * 32 + mt * 16 + arow) * SKS) * 2
                              + (uint32_t)(kb + acol) * 2;
                LDSM4(ah[mt][0], ah[mt][1], ah[mt][2], ah[mt][3], ad);
                LDSM4(al[mt][0], al[mt][1], al[mt][2], al[mt][3], ad + PA_B);
            }
            uint32_t bh[2][4], bl[2][4];
#pragma unroll
            for (int p = 0; p < 2; p++) {
                uint32_t bd = so + 2 * PA_B
                              + (uint32_t)((kb + (lane & 15)) * PB_RS)
                              + (uint32_t)(wn * 32 + p * 16 + ((lane >> 4) << 3)) * 2;
                LDSM4T(bh[p][0], bh[p][1], bh[p][2], bh[p][3], bd);
                LDSM4T(bl[p][0], bl[p][1], bl[p][2], bl[p][3], bd + PB_B);
            }
#pragma unroll
            for (int mt = 0; mt < 2; mt++)
#pragma unroll
                for (int nt = 0; nt < 4; nt++) {
                    const int p = nt >> 1, q = (nt & 1) * 2;
                    MMA_BF16(c[mt][nt], ah[mt], bh[p][q], bh[p][q + 1]);
                    MMA_BF16(c[mt][nt], ah[mt], bl[p][q], bl[p][q + 1]);
                    MMA_BF16(c[mt][nt], al[mt], bh[p][q], bh[p][q + 1]);
                }
        }
        __syncthreads();
    }

#pragma unroll
    for (int mt = 0; mt < 2; mt++) {
        int row = m0 + wm * 32 + mt * 16 + gid;
        float br0 = bias[row], br8 = bias[row + 8];
#pragma unroll
        for (int nt = 0; nt < 4; nt++) {
            int col = n0 + wn * 32 + nt * 8 + tig * 2;
            float2 o0 = {c[mt][nt][0] + br0, c[mt][nt][1] + br0};
            float2 o1 = {c[mt][nt][2] + br8, c[mt][nt][3] + br8};
            *(float2*)(C + ((size_t)b * PROJK + row) * EMB + col)     = o0;
            *(float2*)(C + ((size_t)b * PROJK + row + 8) * EMB + col) = o1;
        }
    }
}

// ================================================================
// Fused attention v2: single-pass 8 rows/warp, float4 smem access.
// smem: k[256][68] rows | vT[64][260] | (qs[64][64] ∪ myp[8][2048])
// ================================================================
#define KST 68
#define VTST 260
#define SM_K    0
#define SM_VT   (256 * KST)                 // 17408
#define SM_QV   (SM_VT + 64 * VTST)         // 34048
#define ATTN_FLOATS (SM_QV + 8 * 2048)      // 50432 (myp > qs)

__global__ __launch_bounds__(256)
void attn_kernel2(const float* __restrict__ q,
                  const float* __restrict__ kproj,
                  const float* __restrict__ vproj,
                  ushort_t* __restrict__ ctx_h,
                  ushort_t* __restrict__ ctx_l)
{
    extern __shared__ float sm[];
    float* sk  = sm + SM_K;     // [256][KST]
    float* svT = sm + SM_VT;    // [64][VTST]
    float* sq  = sm + SM_QV;    // [64][64] (dead after scores)
    float* smyp = sm + SM_QV;   // [8 warps][8 r][256] overlaps sq

    const int b    = blockIdx.z;
    const int h    = blockIdx.y;
    const int s0   = blockIdx.x * 64;
    const int tid  = threadIdx.x;
    const int w    = tid >> 5;
    const int lane = tid & 31;

    // ---- load phase (vectorized) ----
    const float* kpB = kproj + ((size_t)b * PROJK) * EMB + h * KDIM;
    const float* vpB = vproj + ((size_t)b * PROJK) * EMB + h * KDIM;
    const float* qB  = q + ((size_t)(b * SEQ + s0)) * EMB + h * KDIM;

    for (int i = tid; i < 256 * 16; i += 256) {
        int kp = i >> 4, d4 = (i & 15) * 4;
        float4 kv4 = *(const float4*)(kpB + (size_t)kp * EMB + d4);
        *(float4*)(sk + kp * KST + d4) = kv4;
        float4 vv4 = *(const float4*)(vpB + (size_t)kp * EMB + d4);
        svT[(d4 + 0) * VTST + kp] = vv4.x;
        svT[(d4 + 1) * VTST + kp] = vv4.y;
        svT[(d4 + 2) * VTST + kp] = vv4.z;
        svT[(d4 + 3) * VTST + kp] = vv4.w;
    }
    for (int i = tid; i < 64 * 16; i += 256) {
        int r = i >> 4, d4 = (i & 15) * 4;
        *(float4*)(sq + r * 64 + d4) = *(const float4*)(qB + (size_t)r * EMB + d4);
    }
    __syncthreads();

    const int rbase = w * 8;

    // ---- scores: s[r][j], kp = lane + 32*j ----
    float s[8][8];
#pragma unroll
    for (int r = 0; r < 8; r++)
#pragma unroll
        for (int j = 0; j < 8; j++) s[r][j] = 0.f;

#pragma unroll 2
    for (int d4 = 0; d4 < 64; d4 += 4) {
        float4 kv[8];
#pragma unroll
        for (int j = 0; j < 8; j++)
            kv[j] = *(float4*)(sk + (lane + 32 * j) * KST + d4);
#pragma unroll
        for (int r = 0; r < 8; r++) {
            float4 q4 = *(float4*)(sq + (rbase + r) * 64 + d4);
#pragma unroll
            for (int j = 0; j < 8; j++) {
                s[r][j] = fmaf(q4.x, kv[j].x, s[r][j]);
                s[r][j] = fmaf(q4.y, kv[j].y, s[r][j]);
                s[r][j] = fmaf(q4.z, kv[j].z, s[r][j]);
                s[r][j] = fmaf(q4.w, kv[j].w, s[r][j]);
            }
        }
    }
    __syncthreads();   // all warps done with sq before myp overwrites it

    // ---- softmax per row; write probs ----
    float* myp = smyp + w * 2048;
    float inv[8];
#pragma unroll
    for (int r = 0; r < 8; r++) {
        float m = s[r][0];
#pragma unroll
        for (int j = 1; j < 8; j++) m = fmaxf(m, s[r][j]);
#pragma unroll
        for (int o = 16; o > 0; o >>= 1)
            m = fmaxf(m, __shfl_xor_sync(0xFFFFFFFFu, m, o));
        float sum = 0.f;
#pragma unroll
        for (int j = 0; j < 8; j++) {
            s[r][j] = __expf(s[r][j] - m);
            sum += s[r][j];
        }
#pragma unroll
        for (int o = 16; o > 0; o >>= 1)
            sum += __shfl_xor_sync(0xFFFFFFFFu, sum, o);
        inv[r] = 1.f / sum;
#pragma unroll
        for (int j = 0; j < 8; j++)
            myp[r * 256 + lane + 32 * j] = s[r][j];
    }
    __syncwarp();

    // ---- ctx: acc[r][0] for d=lane, acc[r][1] for d=lane+32 ----
    float acc[8][2];
#pragma unroll
    for (int r = 0; r < 8; r++) { acc[r][0] = 0.f; acc[r][1] = 0.f; }

    const float* vA = svT + lane * VTST;
    const float* vB = svT + (lane + 32) * VTST;
#pragma unroll 2
    for (int kp4 = 0; kp4 < 256; kp4 += 4) {
        float4 va = *(const float4*)(vA + kp4);
        float4 vb = *(const float4*)(vB + kp4);
#pragma unroll
        for (int r = 0; r < 8; r++) {
            float4 p4 = *(const float4*)(myp + r * 256 + kp4);
            acc[r][0] = fmaf(p4.x, va.x, acc[r][0]);
            acc[r][0] = fmaf(p4.y, va.y, acc[r][0]);
            acc[r][0] = fmaf(p4.z, va.z, acc[r][0]);
            acc[r][0] = fmaf(p4.w, va.w, acc[r][0]);
            acc[r][1] = fmaf(p4.x, vb.x, acc[r][1]);
            acc[r][1] = fmaf(p4.y, vb.y, acc[r][1]);
            acc[r][1] = fmaf(p4.z, vb.z, acc[r][1]);
            acc[r][1] = fmaf(p4.w, vb.w, acc[r][1]);
        }
    }

    // ---- output: bf16 hi/lo split ----
#pragma unroll
    for (int r = 0; r < 8; r++) {
        size_t row = (size_t)(b * SEQ + s0 + rbase + r);
        ushort_t h0, l0, h1, l1;
        split1(acc[r][0] * inv[r], h0, l0);
        split1(acc[r][1] * inv[r], h1, l1);
        size_t base = row * EMB + h * KDIM;
        ctx_h[base + lane]      = h0;
        ctx_l[base + lane]      = l0;
        ctx_h[base + lane + 32] = h1;
        ctx_l[base + lane + 32] = l1;
    }
}

// ================================================================
// Launch
// ================================================================
extern "C" void kernel_launch(void* const* d_in, const int* in_sizes, int n_in,
                              void* d_out, int out_size)
{
    const float* query = (const float*)d_in[0];
    const float* value = (const float*)d_in[1];
    const float* Wq    = (const float*)d_in[2];
    const float* bq    = (const float*)d_in[3];
    const float* Wk    = (const float*)d_in[4];
    const float* bk    = (const float*)d_in[5];
    const float* Wv    = (const float*)d_in[6];
    const float* bv    = (const float*)d_in[7];
    const float* Wo    = (const float*)d_in[8];
    const float* bo    = (const float*)d_in[9];
    const float* E     = (const float*)d_in[10];
    const float* Eb    = (const float*)d_in[11];
    const float* F     = (const float*)d_in[12];
    const float* Fb    = (const float*)d_in[13];
    float* out = (float*)d_out;

    float *gq, *gkp, *gvp;
    ushort_t *qah, *qal, *vah, *val_, *cth, *ctl;
    ushort_t *kbh, *kbl, *vbh, *vbl;
    ushort_t *wqh, *wql, *wkh, *wkl, *wvh, *wvl, *woh, *wol;
    ushort_t *eth, *etl, *fth, *ftl;
    cudaGetSymbolAddress((void**)&gq,  g_q);
    cudaGetSymbolAddress((void**)&gkp, g_kp);
    cudaGetSymbolAddress((void**)&gvp, g_vp);
    cudaGetSymbolAddress((void**)&qah, g_qA_h);
    cudaGetSymbolAddress((void**)&qal, g_qA_l);
    cudaGetSymbolAddress((void**)&vah, g_vA_h);
    cudaGetSymbolAddress((void**)&val_, g_vA_l);
    cudaGetSymbolAddress((void**)&cth, g_ctx_h);
    cudaGetSymbolAddress((void**)&ctl, g_ctx_l);
    cudaGetSymbolAddress((void**)&kbh, g_kb_h);
    cudaGetSymbolAddress((void**)&kbl, g_kb_l);
    cudaGetSymbolAddress((void**)&vbh, g_vb_h);
    cudaGetSymbolAddress((void**)&vbl, g_vb_l);
    cudaGetSymbolAddress((void**)&wqh, g_wqT_h);
    cudaGetSymbolAddress((void**)&wql, g_wqT_l);
    cudaGetSymbolAddress((void**)&wkh, g_wkT_h);
    cudaGetSymbolAddress((void**)&wkl, g_wkT_l);
    cudaGetSymbolAddress((void**)&wvh, g_wvT_h);
    cudaGetSymbolAddress((void**)&wvl, g_wvT_l);
    cudaGetSymbolAddress((void**)&woh, g_woT_h);
    cudaGetSymbolAddress((void**)&wol, g_woT_l);
    cudaGetSymbolAddress((void**)&eth, g_ETh);
    cudaGetSymbolAddress((void**)&etl, g_ETl);
    cudaGetSymbolAddress((void**)&fth, g_FTh);
    cudaGetSymbolAddress((void**)&ftl, g_FTl);

    const float scale = 1.0f / 8.0f;
    const int nbig = MROWS * EMB;

    // splits
    split_kernel<<<nbig / 1024, 256>>>(query, qah, qal, nbig);
    split_kernel<<<nbig / 1024, 256>>>(value, vah, val_, nbig);

    // batched transposes
    TransJobs wjobs;
    wjobs.j[0] = {Wq, wqh, wql};
    wjobs.j[1] = {Wk, wkh, wkl};
    wjobs.j[2] = {Wv, wvh, wvl};
    wjobs.j[3] = {Wo, woh, wol};
    dim3 tb(32, 8);
    split_transpose_b<<<dim3(EMB / 32, EMB / 32, 4), tb>>>(wjobs, EMB, EMB);

    TransJobs ejobs;
    ejobs.j[0] = {E, eth, etl};
    ejobs.j[1] = {F, fth, ftl};
    ejobs.j[2] = {E, eth, etl};
    ejobs.j[3] = {F, fth, ftl};
    split_transpose_b<<<dim3(PROJK / 32, SEQ / 32, 2), tb>>>(ejobs, SEQ, PROJK);

    // Q GEMM + fused K/V GEMM
    cudaFuncSetAttribute(mma_gemm5<false, false>, cudaFuncAttributeMaxDynamicSharedMemorySize, NSTAGE * STAGE_B);
    cudaFuncSetAttribute(mma_gemm5<true,  true >, cudaFuncAttributeMaxDynamicSharedMemorySize, NSTAGE * STAGE_B);
    dim3 g_big(EMB / 128, MROWS / 128, 1);
    dim3 g_kv (EMB / 128, MROWS / 128, 2);
    mma_gemm5<false, false><<<g_big, 512, NSTAGE * STAGE_B>>>(
        qah, qal, wqh, wql, 0, 0, bq, 0, gq, 0, 0, 0, 0, EMB, EMB, scale);
    mma_gemm5<true, true><<<g_kv, 512, NSTAGE * STAGE_B>>>(
        vah, val_, wkh, wkl, wvh, wvl, bk, bv, 0, kbh, kbl, vbh, vbl, EMB, EMB, 1.0f);

    // projections
    cudaFuncSetAttribute(proj_mma, cudaFuncAttributeMaxDynamicSharedMemorySize, NSTAGE * PSTAGE_B);
    dim3 g_proj(EMB / 128, PROJK / 64, BATCH);
    proj_mma<<<g_proj, 256, NSTAGE * PSTAGE_B>>>(eth, etl, kbh, kbl, Eb, gkp);
    proj_mma<<<g_proj, 256, NSTAGE * PSTAGE_B>>>(fth, ftl, vbh, vbl, Fb, gvp);

    // fused attention v2
    size_t attn_smem = (size_t)ATTN_FLOATS * sizeof(float);   // ~201.7 KB
    cudaFuncSetAttribute(attn_kernel2, cudaFuncAttributeMaxDynamicSharedMemorySize, (int)attn_smem);
    dim3 attn_grid(SEQ / 64, HEADS, BATCH);
    attn_kernel2<<<attn_grid, 256, attn_smem>>>(gq, gkp, gvp, cth, ctl);

    // output projection
    mma_gemm5<false, false><<<g_big, 512, NSTAGE * STAGE_B>>>(
        cth, ctl, woh, wol, 0, 0, bo, 0, out, 0, 0, 0, 0, EMB, EMB, 1.0f);
}

// round 13
// speedup vs baseline: 2.3868x; 1.0174x over previous
#include <cuda_runtime.h>
#include <cuda_fp16.h>
#include <math.h>
#include <stdint.h>

// Problem constants
#define BATCH 4
#define SEQ   2048
#define EMB   1024     // H * Dk
#define HEADS 16
#define KDIM  64
#define PROJK 256
#define MROWS (BATCH * SEQ)   // 8192

typedef unsigned short ushort_t;

// ---------------- scratch (allocation-free) ----------------
__device__ float g_q [MROWS * EMB];
__device__ float g_kp[BATCH * PROJK * EMB];
__device__ float g_vp[BATCH * PROJK * EMB];
// fp16 2-term representations (h1 + h2 ~ fp32 to 2^-22)
__device__ ushort_t g_qA_1[MROWS * EMB], g_qA_2[MROWS * EMB];
__device__ ushort_t g_vA_1[MROWS * EMB], g_vA_2[MROWS * EMB];
__device__ ushort_t g_ctx_1[MROWS * EMB], g_ctx_2[MROWS * EMB];
__device__ ushort_t g_kb_1[MROWS * EMB], g_kb_2[MROWS * EMB];
__device__ ushort_t g_vb_1[MROWS * EMB], g_vb_2[MROWS * EMB];
__device__ ushort_t g_wqT_1[EMB * EMB], g_wqT_2[EMB * EMB];
__device__ ushort_t g_wkT_1[EMB * EMB], g_wkT_2[EMB * EMB];
__device__ ushort_t g_wvT_1[EMB * EMB], g_wvT_2[EMB * EMB];
__device__ ushort_t g_woT_1[EMB * EMB], g_woT_2[EMB * EMB];
__device__ ushort_t g_ET1[PROJK * SEQ], g_ET2[PROJK * SEQ];
__device__ ushort_t g_FT1[PROJK * SEQ], g_FT2[PROJK * SEQ];

// ---------------- helpers ----------------
__device__ __forceinline__ void split1h(float v, ushort_t& h, ushort_t& l) {
    __half a = __float2half_rn(v);
    __half b = __float2half_rn(v - __half2float(a));
    h = __half_as_ushort(a);
    l = __half_as_ushort(b);
}

#define MMA_F16(d, a, b0, b1) asm volatile( \
    "mma.sync.aligned.m16n8k16.row.col.f32.f16.f16.f32 " \
    "{%0,%1,%2,%3}, {%4,%5,%6,%7}, {%8,%9}, {%0,%1,%2,%3};\n" \
    : "+f"((d)[0]), "+f"((d)[1]), "+f"((d)[2]), "+f"((d)[3]) \
    : "r"((a)[0]), "r"((a)[1]), "r"((a)[2]), "r"((a)[3]), \
      "r"(b0), "r"(b1))

#define LDSM4(r0, r1, r2, r3, addr) asm volatile( \
    "ldmatrix.sync.aligned.m8n8.x4.shared.b16 {%0,%1,%2,%3}, [%4];\n" \
    : "=r"(r0), "=r"(r1), "=r"(r2), "=r"(r3) : "r"(addr))

#define LDSM4T(r0, r1, r2, r3, addr) asm volatile( \
    "ldmatrix.sync.aligned.m8n8.x4.trans.shared.b16 {%0,%1,%2,%3}, [%4];\n" \
    : "=r"(r0), "=r"(r1), "=r"(r2), "=r"(r3) : "r"(addr))

__device__ __forceinline__ void cp16(uint32_t dst, const void* src) {
    asm volatile("cp.async.cg.shared.global [%0], [%1], 16;\n" :: "r"(dst), "l"(src));
}
#define CP_COMMIT() asm volatile("cp.async.commit_group;\n" ::: "memory")
#define CP_WAIT2()  asm volatile("cp.async.wait_group 2;\n" ::: "memory")

// ================================================================
// split_kernel: fp32 -> fp16 2-term, vectorized
// ================================================================
__global__ __launch_bounds__(256)
void split_kernel(const float* __restrict__ src,
                  ushort_t* __restrict__ h1,
                  ushort_t* __restrict__ h2, int n)
{
    int i = (blockIdx.x * 256 + threadIdx.x) * 4;
    if (i >= n) return;
    float4 v = *(const float4*)(src + i);
    ushort4 a, b;
    split1h(v.x, a.x, b.x);
    split1h(v.y, a.y, b.y);
    split1h(v.z, a.z, b.z);
    split1h(v.w, a.w, b.w);
    *(ushort4*)(h1 + i) = a;
    *(ushort4*)(h2 + i) = b;
}

// ================================================================
// Batched split+transpose: W[K][N] fp32 -> WT[N][K] fp16 2-term
// ================================================================
struct TransJob { const float* W; ushort_t* h1; ushort_t* h2; };
struct TransJobs { TransJob j[4]; };

__global__ __launch_bounds__(256)
void split_transpose_b(TransJobs jobs, int K, int N)
{
    __shared__ float t[32][33];
    const TransJob jb = jobs.j[blockIdx.z];
    int k0 = blockIdx.y * 32, n0 = blockIdx.x * 32;
    int tx = threadIdx.x, ty = threadIdx.y;
#pragma unroll
    for (int i = 0; i < 32; i += 8)
        t[ty + i][tx] = jb.W[(size_t)(k0 + ty + i) * N + n0 + tx];
    __syncthreads();
#pragma unroll
    for (int i = 0; i < 32; i += 8) {
        float v = t[tx][ty + i];
        ushort_t a, b;
        split1h(v, a, b);
        jb.h1[(size_t)(n0 + ty + i) * K + k0 + tx] = a;
        jb.h2[(size_t)(n0 + ty + i) * K + k0 + tx] = b;
    }
}

// ================================================================
// Big GEMM (fp16 3-term: A1B1 + A2B1 + A1B2, err ~2^-22), 512 thr,
// 16 warps, warp tile 32x32, CTA 128x128, BK=32, 3-stage cp.async.
// Jobs via struct; grid.z selects job (QKV fused in one launch).
// ================================================================
#define SKS 40
#define ARR_B (128 * SKS * 2)
#define GSTG (4 * ARR_B)
#define NSTAGE 3

struct GJob {
    const ushort_t *A1, *A2, *B1, *B2;
    const float* bias;
    float* C;
    ushort_t *C1, *C2;
    float alpha;
    int split_out;
};
struct GJobs { GJob j[3]; };

__global__ __launch_bounds__(512)
void mma_gemm7(GJobs jobs, int N, int K)
{
    extern __shared__ unsigned char smraw[];
    const uint32_t smb = (uint32_t)__cvta_generic_to_shared(smraw);

    const GJob job = jobs.j[blockIdx.z];

    const int tid  = threadIdx.x;
    const int wid  = tid >> 5;
    const int lane = tid & 31;
    const int gid  = lane >> 2;
    const int tig  = lane & 3;
    const int wm   = wid >> 2;
    const int wn   = wid & 3;
    const int m0   = blockIdx.y * 128;
    const int n0   = blockIdx.x * 128;

    const int lrow = tid >> 2;
    const int lcf  = (tid & 3) * 8;

    auto issue = [&](int s, int kt) {
        const int k0 = kt * 32;
        const uint32_t so = smb + s * GSTG;
        const uint32_t ro = (uint32_t)(lrow * SKS + lcf) * 2;
        const size_t ga = (size_t)(m0 + lrow) * K + k0 + lcf;
        const size_t gb = (size_t)(n0 + lrow) * K + k0 + lcf;
        cp16(so + ro,             job.A1 + ga);
        cp16(so + ARR_B + ro,     job.A2 + ga);
        cp16(so + 2 * ARR_B + ro, job.B1 + gb);
        cp16(so + 3 * ARR_B + ro, job.B2 + gb);
    };

    float c[2][4][4];
#pragma unroll
    for (int i = 0; i < 2; i++)
#pragma unroll
        for (int j = 0; j < 4; j++)
#pragma unroll
            for (int l = 0; l < 4; l++) c[i][j][l] = 0.f;

    const int nk = K / 32;
    issue(0, 0); CP_COMMIT();
    issue(1, 1); CP_COMMIT();

    const int arow = lane & 15;
    const int acol = (lane >> 4) << 3;

    for (int kt = 0; kt < nk; kt++) {
        if (kt + 2 < nk) issue((kt + 2) % NSTAGE, kt + 2);
        CP_COMMIT();
        CP_WAIT2();
        __syncthreads();
        const uint32_t so = smb + (kt % NSTAGE) * GSTG;

#pragma unroll
        for (int kb = 0; kb < 32; kb += 16) {
            const uint32_t koff = (uint32_t)(kb + acol) * 2;
            uint32_t a1f[2][4], a2f[2][4];
#pragma unroll
            for (int mt = 0; mt < 2; mt++) {
                uint32_t ad = so + (uint32_t)((wm * 32 + mt * 16 + arow) * SKS) * 2 + koff;
                LDSM4(a1f[mt][0], a1f[mt][1], a1f[mt][2], a1f[mt][3], ad);
                LDSM4(a2f[mt][0], a2f[mt][1], a2f[mt][2], a2f[mt][3], ad + ARR_B);
            }
            uint32_t b1f[2][4], b2f[2][4];
#pragma unroll
            for (int p = 0; p < 2; p++) {
                uint32_t bd = so + 2 * ARR_B +
                              (uint32_t)((wn * 32 + p * 16 + arow) * SKS) * 2 + koff;
                LDSM4(b1f[p][0], b1f[p][1], b1f[p][2], b1f[p][3], bd);
                LDSM4(b2f[p][0], b2f[p][1], b2f[p][2], b2f[p][3], bd + ARR_B);
            }
#pragma unroll
            for (int mt = 0; mt < 2; mt++)
#pragma unroll
                for (int nt = 0; nt < 4; nt++) {
                    const int p = nt >> 1, q = nt & 1;
                    MMA_F16(c[mt][nt], a1f[mt], b1f[p][q], b1f[p][q + 2]);
                    MMA_F16(c[mt][nt], a2f[mt], b1f[p][q], b1f[p][q + 2]);
                    MMA_F16(c[mt][nt], a1f[mt], b2f[p][q], b2f[p][q + 2]);
                }
        }
        __syncthreads();
    }

#pragma unroll
    for (int mt = 0; mt < 2; mt++) {
        int row = m0 + wm * 32 + mt * 16 + gid;
#pragma unroll
        for (int nt = 0; nt < 4; nt++) {
            int col = n0 + wn * 32 + nt * 8 + tig * 2;
            float b0 = job.bias[col], b1 = job.bias[col + 1];
            float v00 = (c[mt][nt][0] + b0) * job.alpha;
            float v01 = (c[mt][nt][1] + b1) * job.alpha;
            float v10 = (c[mt][nt][2] + b0) * job.alpha;
            float v11 = (c[mt][nt][3] + b1) * job.alpha;
            if (job.split_out) {
                ushort2 h0, l0, h1, l1;
                split1h(v00, h0.x, l0.x); split1h(v01, h0.y, l0.y);
                split1h(v10, h1.x, l1.x); split1h(v11, h1.y, l1.y);
                *(ushort2*)(job.C1 + (size_t)row * N + col)       = h0;
                *(ushort2*)(job.C2 + (size_t)row * N + col)       = l0;
                *(ushort2*)(job.C1 + (size_t)(row + 8) * N + col) = h1;
                *(ushort2*)(job.C2 + (size_t)(row + 8) * N + col) = l1;
            } else {
                float2 o0 = {v00, v01}, o1 = {v10, v11};
                *(float2*)(job.C + (size_t)row * N + col)       = o0;
                *(float2*)(job.C + (size_t)(row + 8) * N + col) = o1;
            }
        }
    }
}

// ================================================================
// Projection MMA (fp16 3-term: A1B1 + A2B1 + A1B2), fused K/V+batch:
// C[b][m][n] = sum_s ET[m][s] * X[b][s][n] + bias[m]
// grid (EMB/128, PROJK/64, 8): z>>2 = job (K or V), z&3 = batch
// ================================================================
#define PA_B (64 * SKS * 2)
#define PB_RS 272
#define PB_B (32 * PB_RS)
#define PSTG (2 * PA_B + 2 * PB_B)

struct PJob { const ushort_t *A1, *A2, *B1, *B2; const float* bias; float* C; };
struct PJobs { PJob j[2]; };

__global__ __launch_bounds__(256)
void proj_mma7(PJobs jobs)
{
    extern __shared__ unsigned char smraw[];
    const uint32_t smb = (uint32_t)__cvta_generic_to_shared(smraw);

    const int tid  = threadIdx.x;
    const int wid  = tid >> 5;
    const int lane = tid & 31;
    const int gid  = lane >> 2;
    const int tig  = lane & 3;
    const int wm   = wid >> 2;
    const int wn   = wid & 3;
    const int sel  = blockIdx.z >> 2;
    const int b    = blockIdx.z & 3;
    const int m0   = blockIdx.y * 64;
    const int n0   = blockIdx.x * 128;

    const PJob job = jobs.j[sel];
    const ushort_t* Xb1 = job.B1 + (size_t)b * SEQ * EMB;
    const ushort_t* Xb2 = job.B2 + (size_t)b * SEQ * EMB;

    auto issue = [&](int s, int kt) {
        const int k0 = kt * 32;
        const uint32_t so = smb + s * PSTG;
        {
            int row = tid >> 2, cf = (tid & 3);
            uint32_t sa = so + (uint32_t)(row * SKS) * 2 + cf * 16;
            size_t ga = (size_t)(m0 + row) * SEQ + k0 + cf * 8;
            cp16(sa,        job.A1 + ga);
            cp16(sa + PA_B, job.A2 + ga);
        }
#pragma unroll
        for (int half = 0; half < 2; half++) {
            int cidx = half * 256 + tid;
            int row = cidx >> 4, cf = cidx & 15;
            uint32_t sb = so + 2 * PA_B + (uint32_t)(row * PB_RS) + cf * 16;
            size_t gb = (size_t)(k0 + row) * EMB + n0 + cf * 8;
            cp16(sb,        Xb1 + gb);
            cp16(sb + PB_B, Xb2 + gb);
        }
    };

    float c[2][4][4];
#pragma unroll
    for (int i = 0; i < 2; i++)
#pragma unroll
        for (int j = 0; j < 4; j++)
#pragma unroll
            for (int l = 0; l < 4; l++) c[i][j][l] = 0.f;

    const int nk = SEQ / 32;
    issue(0, 0); CP_COMMIT();
    issue(1, 1); CP_COMMIT();

    const int arow = lane & 15;
    const int acol = (lane >> 4) << 3;

    for (int kt = 0; kt < nk; kt++) {
        if (kt + 2 < nk) issue((kt + 2) % NSTAGE, kt + 2);
        CP_COMMIT();
        CP_WAIT2();
        __syncthreads();
        const uint32_t so = smb + (kt % NSTAGE) * PSTG;

#pragma unroll
        for (int kb = 0; kb < 32; kb += 16) {
            uint32_t a1f[2][4], a2f[2][4];
#pragma unroll
            for (int mt = 0; mt < 2; mt++) {
                uint32_t ad = so + (uint32_t)((wm * 32 + mt * 16 + arow) * SKS) * 2
                              + (uint32_t)(kb + acol) * 2;
                LDSM4(a1f[mt][0], a1f[mt][1], a1f[mt][2], a1f[mt][3], ad);
                LDSM4(a2f[mt][0], a2f[mt][1], a2f[mt][2], a2f[mt][3], ad + PA_B);
            }
            uint32_t b1f[2][4], b2f[2][4];
#pragma unroll
            for (int p = 0; p < 2; p++) {
                uint32_t bd = so + 2 * PA_B
                              + (uint32_t)((kb + (lane & 15)) * PB_RS)
                              + (uint32_t)(wn * 32 + p * 16 + ((lane >> 4) << 3)) * 2;
                LDSM4T(b1f[p][0], b1f[p][1], b1f[p][2], b1f[p][3], bd);
                LDSM4T(b2f[p][0], b2f[p][1], b2f[p][2], b2f[p][3], bd + PB_B);
            }
#pragma unroll
            for (int mt = 0; mt < 2; mt++)
#pragma unroll
                for (int nt = 0; nt < 4; nt++) {
                    const int p = nt >> 1, q = (nt & 1) * 2;
                    MMA_F16(c[mt][nt], a1f[mt], b1f[p][q], b1f[p][q + 1]);
                    MMA_F16(c[mt][nt], a2f[mt], b1f[p][q], b1f[p][q + 1]);
                    MMA_F16(c[mt][nt], a1f[mt], b2f[p][q], b2f[p][q + 1]);
                }
        }
        __syncthreads();
    }

#pragma unroll
    for (int mt = 0; mt < 2; mt++) {
        int row = m0 + wm * 32 + mt * 16 + gid;
        float br0 = job.bias[row], br8 = job.bias[row + 8];
#pragma unroll
        for (int nt = 0; nt < 4; nt++) {
            int col = n0 + wn * 32 + nt * 8 + tig * 2;
            float2 o0 = {c[mt][nt][0] + br0, c[mt][nt][1] + br0};
            float2 o1 = {c[mt][nt][2] + br8, c[mt][nt][3] + br8};
            *(float2*)(job.C + ((size_t)b * PROJK + row) * EMB + col)     = o0;
            *(float2*)(job.C + ((size_t)b * PROJK + row + 8) * EMB + col) = o1;
        }
    }
}

// ================================================================
// Fused attention v2 (R11 winner, output fp16 2-term)
// ================================================================
#define KST 68
#define VTST 260
#define SM_K    0
#define SM_VT   (256 * KST)
#define SM_QV   (SM_VT + 64 * VTST)
#define ATTN_FLOATS (SM_QV + 8 * 2048)

__global__ __launch_bounds__(256)
void attn_kernel2(const float* __restrict__ q,
                  const float* __restrict__ kproj,
                  const float* __restrict__ vproj,
                  ushort_t* __restrict__ ctx_1,
                  ushort_t* __restrict__ ctx_2)
{
    extern __shared__ float sm[];
    float* sk  = sm + SM_K;
    float* svT = sm + SM_VT;
    float* sq  = sm + SM_QV;
    float* smyp = sm + SM_QV;

    const int b    = blockIdx.z;
    const int h    = blockIdx.y;
    const int s0   = blockIdx.x * 64;
    const int tid  = threadIdx.x;
    const int w    = tid >> 5;
    const int lane = tid & 31;

    const float* kpB = kproj + ((size_t)b * PROJK) * EMB + h * KDIM;
    const float* vpB = vproj + ((size_t)b * PROJK) * EMB + h * KDIM;
    const float* qB  = q + ((size_t)(b * SEQ + s0)) * EMB + h * KDIM;

    for (int i = tid; i < 256 * 16; i += 256) {
        int kp = i >> 4, d4 = (i & 15) * 4;
        float4 kv4 = *(const float4*)(kpB + (size_t)kp * EMB + d4);
        *(float4*)(sk + kp * KST + d4) = kv4;
        float4 vv4 = *(const float4*)(vpB + (size_t)kp * EMB + d4);
        svT[(d4 + 0) * VTST + kp] = vv4.x;
        svT[(d4 + 1) * VTST + kp] = vv4.y;
        svT[(d4 + 2) * VTST + kp] = vv4.z;
        svT[(d4 + 3) * VTST + kp] = vv4.w;
    }
    for (int i = tid; i < 64 * 16; i += 256) {
        int r = i >> 4, d4 = (i & 15) * 4;
        *(float4*)(sq + r * 64 + d4) = *(const float4*)(qB + (size_t)r * EMB + d4);
    }
    __syncthreads();

    const int rbase = w * 8;

    float s[8][8];
#pragma unroll
    for (int r = 0; r < 8; r++)
#pragma unroll
        for (int j = 0; j < 8; j++) s[r][j] = 0.f;

#pragma unroll 2
    for (int d4 = 0; d4 < 64; d4 += 4) {
        float4 kv[8];
#pragma unroll
        for (int j = 0; j < 8; j++)
            kv[j] = *(float4*)(sk + (lane + 32 * j) * KST + d4);
#pragma unroll
        for (int r = 0; r < 8; r++) {
            float4 q4 = *(float4*)(sq + (rbase + r) * 64 + d4);
#pragma unroll
            for (int j = 0; j < 8; j++) {
                s[r][j] = fmaf(q4.x, kv[j].x, s[r][j]);
                s[r][j] = fmaf(q4.y, kv[j].y, s[r][j]);
                s[r][j] = fmaf(q4.z, kv[j].z, s[r][j]);
                s[r][j] = fmaf(q4.w, kv[j].w, s[r][j]);
            }
        }
    }
    __syncthreads();

    float* myp = smyp + w * 2048;
    float inv[8];
#pragma unroll
    for (int r = 0; r < 8; r++) {
        float m = s[r][0];
#pragma unroll
        for (int j = 1; j < 8; j++) m = fmaxf(m, s[r][j]);
#pragma unroll
        for (int o = 16; o > 0; o >>= 1)
            m = fmaxf(m, __shfl_xor_sync(0xFFFFFFFFu, m, o));
        float sum = 0.f;
#pragma unroll
        for (int j = 0; j < 8; j++) {
            s[r][j] = __expf(s[r][j] - m);
            sum += s[r][j];
        }
#pragma unroll
        for (int o = 16; o > 0; o >>= 1)
            sum += __shfl_xor_sync(0xFFFFFFFFu, sum, o);
        inv[r] = 1.f / sum;
#pragma unroll
        for (int j = 0; j < 8; j++)
            myp[r * 256 + lane + 32 * j] = s[r][j];
    }
    __syncwarp();

    float acc[8][2];
#pragma unroll
    for (int r = 0; r < 8; r++) { acc[r][0] = 0.f; acc[r][1] = 0.f; }

    const float* vA = svT + lane * VTST;
    const float* vB = svT + (lane + 32) * VTST;
#pragma unroll 2
    for (int kp4 = 0; kp4 < 256; kp4 += 4) {
        float4 va = *(const float4*)(vA + kp4);
        float4 vb = *(const float4*)(vB + kp4);
#pragma unroll
        for (int r = 0; r < 8; r++) {
            float4 p4 = *(const float4*)(myp + r * 256 + kp4);
            acc[r][0] = fmaf(p4.x, va.x, acc[r][0]);
            acc[r][0] = fmaf(p4.y, va.y, acc[r][0]);
            acc[r][0] = fmaf(p4.z, va.z, acc[r][0]);
            acc[r][0] = fmaf(p4.w, va.w, acc[r][0]);
            acc[r][1] = fmaf(p4.x, vb.x, acc[r][1]);
            acc[r][1] = fmaf(p4.y, vb.y, acc[r][1]);
            acc[r][1] = fmaf(p4.z, vb.z, acc[r][1]);
            acc[r][1] = fmaf(p4.w, vb.w, acc[r][1]);
        }
    }

#pragma unroll
    for (int r = 0; r < 8; r++) {
        size_t row = (size_t)(b * SEQ + s0 + rbase + r);
        ushort_t h0, l0, h1, l1;
        split1h(acc[r][0] * inv[r], h0, l0);
        split1h(acc[r][1] * inv[r], h1, l1);
        size_t base = row * EMB + h * KDIM;
        ctx_1[base + lane]      = h0;
        ctx_2[base + lane]      = l0;
        ctx_1[base + lane + 32] = h1;
        ctx_2[base + lane + 32] = l1;
    }
}

// ================================================================
// Launch
// ================================================================
extern "C" void kernel_launch(void* const* d_in, const int* in_sizes, int n_in,
                              void* d_out, int out_size)
{
    const float* query = (const float*)d_in[0];
    const float* value = (const float*)d_in[1];
    const float* Wq    = (const float*)d_in[2];
    const float* bq    = (const float*)d_in[3];
    const float* Wk    = (const float*)d_in[4];
    const float* bk    = (const float*)d_in[5];
    const float* Wv    = (const float*)d_in[6];
    const float* bv    = (const float*)d_in[7];
    const float* Wo    = (const float*)d_in[8];
    const float* bo    = (const float*)d_in[9];
    const float* E     = (const float*)d_in[10];
    const float* Eb    = (const float*)d_in[11];
    const float* F     = (const float*)d_in[12];
    const float* Fb    = (const float*)d_in[13];
    float* out = (float*)d_out;

    float *gq, *gkp, *gvp;
    ushort_t *qa1, *qa2, *va1, *va2, *ct1, *ct2;
    ushort_t *kb1, *kb2, *vb1, *vb2;
    ushort_t *wq1, *wq2, *wk1, *wk2, *wv1, *wv2, *wo1, *wo2;
    ushort_t *et1, *et2, *ft1, *ft2;
    cudaGetSymbolAddress((void**)&gq,  g_q);
    cudaGetSymbolAddress((void**)&gkp, g_kp);
    cudaGetSymbolAddress((void**)&gvp, g_vp);
    cudaGetSymbolAddress((void**)&qa1, g_qA_1);
    cudaGetSymbolAddress((void**)&qa2, g_qA_2);
    cudaGetSymbolAddress((void**)&va1, g_vA_1);
    cudaGetSymbolAddress((void**)&va2, g_vA_2);
    cudaGetSymbolAddress((void**)&ct1, g_ctx_1);
    cudaGetSymbolAddress((void**)&ct2, g_ctx_2);
    cudaGetSymbolAddress((void**)&kb1, g_kb_1);
    cudaGetSymbolAddress((void**)&kb2, g_kb_2);
    cudaGetSymbolAddress((void**)&vb1, g_vb_1);
    cudaGetSymbolAddress((void**)&vb2, g_vb_2);
    cudaGetSymbolAddress((void**)&wq1, g_wqT_1);
    cudaGetSymbolAddress((void**)&wq2, g_wqT_2);
    cudaGetSymbolAddress((void**)&wk1, g_wkT_1);
    cudaGetSymbolAddress((void**)&wk2, g_wkT_2);
    cudaGetSymbolAddress((void**)&wv1, g_wvT_1);
    cudaGetSymbolAddress((void**)&wv2, g_wvT_2);
    cudaGetSymbolAddress((void**)&wo1, g_woT_1);
    cudaGetSymbolAddress((void**)&wo2, g_woT_2);
    cudaGetSymbolAddress((void**)&et1, g_ET1);
    cudaGetSymbolAddress((void**)&et2, g_ET2);
    cudaGetSymbolAddress((void**)&ft1, g_FT1);
    cudaGetSymbolAddress((void**)&ft2, g_FT2);

    const float scale = 1.0f / 8.0f;
    const int nbig = MROWS * EMB;

    // splits
    split_kernel<<<nbig / 1024, 256>>>(query, qa1, qa2, nbig);
    split_kernel<<<nbig / 1024, 256>>>(value, va1, va2, nbig);

    // batched transposes
    TransJobs wjobs;
    wjobs.j[0] = {Wq, wq1, wq2};
    wjobs.j[1] = {Wk, wk1, wk2};
    wjobs.j[2] = {Wv, wv1, wv2};
    wjobs.j[3] = {Wo, wo1, wo2};
    dim3 tb(32, 8);
    split_transpose_b<<<dim3(EMB / 32, EMB / 32, 4), tb>>>(wjobs, EMB, EMB);

    TransJobs ejobs;
    ejobs.j[0] = {E, et1, et2};
    ejobs.j[1] = {F, ft1, ft2};
    ejobs.j[2] = {E, et1, et2};
    ejobs.j[3] = {F, ft1, ft2};
    split_transpose_b<<<dim3(PROJK / 32, SEQ / 32, 2), tb>>>(ejobs, SEQ, PROJK);

    // fused Q+K+V GEMM (fp16 3-term)
    GJobs qkv;
    qkv.j[0] = {qa1, qa2, wq1, wq2, bq, gq, 0, 0, scale, 0};
    qkv.j[1] = {va1, va2, wk1, wk2, bk, 0, kb1, kb2, 1.0f, 1};
    qkv.j[2] = {va1, va2, wv1, wv2, bv, 0, vb1, vb2, 1.0f, 1};
    cudaFuncSetAttribute(mma_gemm7, cudaFuncAttributeMaxDynamicSharedMemorySize, NSTAGE * GSTG);
    dim3 g_qkv(EMB / 128, MROWS / 128, 3);
    mma_gemm7<<<g_qkv, 512, NSTAGE * GSTG>>>(qkv, EMB, EMB);

    // fused projections (K & V, all batches, one launch; fp16 3-term)
    PJobs pj;
    pj.j[0] = {et1, et2, kb1, kb2, Eb, gkp};
    pj.j[1] = {ft1, ft2, vb1, vb2, Fb, gvp};
    cudaFuncSetAttribute(proj_mma7, cudaFuncAttributeMaxDynamicSharedMemorySize, NSTAGE * PSTG);
    dim3 g_proj(EMB / 128, PROJK / 64, 8);
    proj_mma7<<<g_proj, 256, NSTAGE * PSTG>>>(pj);

    // fused attention
    size_t attn_smem = (size_t)ATTN_FLOATS * sizeof(float);
    cudaFuncSetAttribute(attn_kernel2, cudaFuncAttributeMaxDynamicSharedMemorySize, (int)attn_smem);
    dim3 attn_grid(SEQ / 64, HEADS, BATCH);
    attn_kernel2<<<attn_grid, 256, attn_smem>>>(gq, gkp, gvp, ct1, ct2);

    // output projection (fp16 3-term)
    GJobs oj;
    oj.j[0] = {ct1, ct2, wo1, wo2, bo, out, 0, 0, 1.0f, 0};
    oj.j[1] = oj.j[0];
    oj.j[2] = oj.j[0];
    dim3 g_out(EMB / 128, MROWS / 128, 1);
    mma_gemm7<<<g_out, 512, NSTAGE * GSTG>>>(oj, EMB, EMB);
}

// round 14
// speedup vs baseline: 2.4634x; 1.0321x over previous
#include <cuda_runtime.h>
#include <cuda_fp16.h>
#include <math.h>
#include <stdint.h>

// Problem constants
#define BATCH 4
#define SEQ   2048
#define EMB   1024     // H * Dk
#define HEADS 16
#define KDIM  64
#define PROJK 256
#define MROWS (BATCH * SEQ)   // 8192

typedef unsigned short ushort_t;

// ---------------- scratch (allocation-free) ----------------
__device__ float g_q [MROWS * EMB];
__device__ float g_kp[BATCH * PROJK * EMB];
__device__ float g_vp[BATCH * PROJK * EMB];
// fp16 2-term representations (h1 + h2 ~ fp32 to 2^-22)
__device__ ushort_t g_qA_1[MROWS * EMB], g_qA_2[MROWS * EMB];
__device__ ushort_t g_vA_1[MROWS * EMB], g_vA_2[MROWS * EMB];
__device__ ushort_t g_ctx_1[MROWS * EMB], g_ctx_2[MROWS * EMB];
__device__ ushort_t g_kb_1[MROWS * EMB], g_kb_2[MROWS * EMB];
__device__ ushort_t g_vb_1[MROWS * EMB], g_vb_2[MROWS * EMB];
__device__ ushort_t g_wqT_1[EMB * EMB], g_wqT_2[EMB * EMB];
__device__ ushort_t g_wkT_1[EMB * EMB], g_wkT_2[EMB * EMB];
__device__ ushort_t g_wvT_1[EMB * EMB], g_wvT_2[EMB * EMB];
__device__ ushort_t g_woT_1[EMB * EMB], g_woT_2[EMB * EMB];
__device__ ushort_t g_ET1[PROJK * SEQ], g_ET2[PROJK * SEQ];
__device__ ushort_t g_FT1[PROJK * SEQ], g_FT2[PROJK * SEQ];

// ---------------- helpers ----------------
__device__ __forceinline__ void split1h(float v, ushort_t& h, ushort_t& l) {
    __half a = __float2half_rn(v);
    __half b = __float2half_rn(v - __half2float(a));
    h = __half_as_ushort(a);
    l = __half_as_ushort(b);
}

#define MMA_F16(d, a, b0, b1) asm volatile( \
    "mma.sync.aligned.m16n8k16.row.col.f32.f16.f16.f32 " \
    "{%0,%1,%2,%3}, {%4,%5,%6,%7}, {%8,%9}, {%0,%1,%2,%3};\n" \
    : "+f"((d)[0]), "+f"((d)[1]), "+f"((d)[2]), "+f"((d)[3]) \
    : "r"((a)[0]), "r"((a)[1]), "r"((a)[2]), "r"((a)[3]), \
      "r"(b0), "r"(b1))

#define LDSM4(r0, r1, r2, r3, addr) asm volatile( \
    "ldmatrix.sync.aligned.m8n8.x4.shared.b16 {%0,%1,%2,%3}, [%4];\n" \
    : "=r"(r0), "=r"(r1), "=r"(r2), "=r"(r3) : "r"(addr))

#define LDSM4T(r0, r1, r2, r3, addr) asm volatile( \
    "ldmatrix.sync.aligned.m8n8.x4.trans.shared.b16 {%0,%1,%2,%3}, [%4];\n" \
    : "=r"(r0), "=r"(r1), "=r"(r2), "=r"(r3) : "r"(addr))

__device__ __forceinline__ void cp16(uint32_t dst, const void* src) {
    asm volatile("cp.async.cg.shared.global [%0], [%1], 16;\n" :: "r"(dst), "l"(src));
}
#define CP_COMMIT() asm volatile("cp.async.commit_group;\n" ::: "memory")
#define CP_WAIT2()  asm volatile("cp.async.wait_group 2;\n" ::: "memory")

// ================================================================
// split_kernel: fp32 -> fp16 2-term, vectorized
// ================================================================
__global__ __launch_bounds__(256)
void split_kernel(const float* __restrict__ src,
                  ushort_t* __restrict__ h1,
                  ushort_t* __restrict__ h2, int n)
{
    int i = (blockIdx.x * 256 + threadIdx.x) * 4;
    if (i >= n) return;
    float4 v = *(const float4*)(src + i);
    ushort4 a, b;
    split1h(v.x, a.x, b.x);
    split1h(v.y, a.y, b.y);
    split1h(v.z, a.z, b.z);
    split1h(v.w, a.w, b.w);
    *(ushort4*)(h1 + i) = a;
    *(ushort4*)(h2 + i) = b;
}

// ================================================================
// Batched split+transpose: W[K][N] fp32 -> WT[N][K] fp16 2-term
// ================================================================
struct TransJob { const float* W; ushort_t* h1; ushort_t* h2; };
struct TransJobs { TransJob j[4]; };

__global__ __launch_bounds__(256)
void split_transpose_b(TransJobs jobs, int K, int N)
{
    __shared__ float t[32][33];
    const TransJob jb = jobs.j[blockIdx.z];
    int k0 = blockIdx.y * 32, n0 = blockIdx.x * 32;
    int tx = threadIdx.x, ty = threadIdx.y;
#pragma unroll
    for (int i = 0; i < 32; i += 8)
        t[ty + i][tx] = jb.W[(size_t)(k0 + ty + i) * N + n0 + tx];
    __syncthreads();
#pragma unroll
    for (int i = 0; i < 32; i += 8) {
        float v = t[tx][ty + i];
        ushort_t a, b;
        split1h(v, a, b);
        jb.h1[(size_t)(n0 + ty + i) * K + k0 + tx] = a;
        jb.h2[(size_t)(n0 + ty + i) * K + k0 + tx] = b;
    }
}

// ================================================================
// Big GEMM (fp16 split, mma.sync), 512 threads, 16 warps, 32x32 warp.
// job.terms==3: A1B1 + A2B1 + A1B2 (err ~2^-22)
// job.terms==2: A1B1 + A2B1       (err ~2^-11 from B rounding)
// grid.z selects job (QKV fused in one launch).
// ================================================================
#define SKS 40
#define ARR_B (128 * SKS * 2)
#define GSTG (4 * ARR_B)
#define NSTAGE 3

struct GJob {
    const ushort_t *A1, *A2, *B1, *B2;
    const float* bias;
    float* C;
    ushort_t *C1, *C2;
    float alpha;
    int split_out;
    int terms;
};
struct GJobs { GJob j[3]; };

__global__ __launch_bounds__(512)
void mma_gemm7(GJobs jobs, int N, int K)
{
    extern __shared__ unsigned char smraw[];
    const uint32_t smb = (uint32_t)__cvta_generic_to_shared(smraw);

    const GJob job = jobs.j[blockIdx.z];
    const bool t3 = (job.terms == 3);

    const int tid  = threadIdx.x;
    const int wid  = tid >> 5;
    const int lane = tid & 31;
    const int gid  = lane >> 2;
    const int tig  = lane & 3;
    const int wm   = wid >> 2;
    const int wn   = wid & 3;
    const int m0   = blockIdx.y * 128;
    const int n0   = blockIdx.x * 128;

    const int lrow = tid >> 2;
    const int lcf  = (tid & 3) * 8;

    auto issue = [&](int s, int kt) {
        const int k0 = kt * 32;
        const uint32_t so = smb + s * GSTG;
        const uint32_t ro = (uint32_t)(lrow * SKS + lcf) * 2;
        const size_t ga = (size_t)(m0 + lrow) * K + k0 + lcf;
        const size_t gb = (size_t)(n0 + lrow) * K + k0 + lcf;
        cp16(so + ro,             job.A1 + ga);
        cp16(so + ARR_B + ro,     job.A2 + ga);
        cp16(so + 2 * ARR_B + ro, job.B1 + gb);
        if (t3) cp16(so + 3 * ARR_B + ro, job.B2 + gb);
    };

    float c[2][4][4];
#pragma unroll
    for (int i = 0; i < 2; i++)
#pragma unroll
        for (int j = 0; j < 4; j++)
#pragma unroll
            for (int l = 0; l < 4; l++) c[i][j][l] = 0.f;

    const int nk = K / 32;
    issue(0, 0); CP_COMMIT();
    issue(1, 1); CP_COMMIT();

    const int arow = lane & 15;
    const int acol = (lane >> 4) << 3;

    for (int kt = 0; kt < nk; kt++) {
        if (kt + 2 < nk) issue((kt + 2) % NSTAGE, kt + 2);
        CP_COMMIT();
        CP_WAIT2();
        __syncthreads();
        const uint32_t so = smb + (kt % NSTAGE) * GSTG;

#pragma unroll
        for (int kb = 0; kb < 32; kb += 16) {
            const uint32_t koff = (uint32_t)(kb + acol) * 2;
            uint32_t a1f[2][4], a2f[2][4];
#pragma unroll
            for (int mt = 0; mt < 2; mt++) {
                uint32_t ad = so + (uint32_t)((wm * 32 + mt * 16 + arow) * SKS) * 2 + koff;
                LDSM4(a1f[mt][0], a1f[mt][1], a1f[mt][2], a1f[mt][3], ad);
                LDSM4(a2f[mt][0], a2f[mt][1], a2f[mt][2], a2f[mt][3], ad + ARR_B);
            }
            uint32_t b1f[2][4], b2f[2][4];
#pragma unroll
            for (int p = 0; p < 2; p++) {
                uint32_t bd = so + 2 * ARR_B +
                              (uint32_t)((wn * 32 + p * 16 + arow) * SKS) * 2 + koff;
                LDSM4(b1f[p][0], b1f[p][1], b1f[p][2], b1f[p][3], bd);
                if (t3)
                    LDSM4(b2f[p][0], b2f[p][1], b2f[p][2], b2f[p][3], bd + ARR_B);
            }
#pragma unroll
            for (int mt = 0; mt < 2; mt++)
#pragma unroll
                for (int nt = 0; nt < 4; nt++) {
                    const int p = nt >> 1, q = nt & 1;
                    MMA_F16(c[mt][nt], a1f[mt], b1f[p][q], b1f[p][q + 2]);
                    MMA_F16(c[mt][nt], a2f[mt], b1f[p][q], b1f[p][q + 2]);
                    if (t3)
                        MMA_F16(c[mt][nt], a1f[mt], b2f[p][q], b2f[p][q + 2]);
                }
        }
        __syncthreads();
    }

#pragma unroll
    for (int mt = 0; mt < 2; mt++) {
        int row = m0 + wm * 32 + mt * 16 + gid;
#pragma unroll
        for (int nt = 0; nt < 4; nt++) {
            int col = n0 + wn * 32 + nt * 8 + tig * 2;
            float b0 = job.bias[col], b1 = job.bias[col + 1];
            float v00 = (c[mt][nt][0] + b0) * job.alpha;
            float v01 = (c[mt][nt][1] + b1) * job.alpha;
            float v10 = (c[mt][nt][2] + b0) * job.alpha;
            float v11 = (c[mt][nt][3] + b1) * job.alpha;
            if (job.split_out) {
                ushort2 h0, l0, h1, l1;
                split1h(v00, h0.x, l0.x); split1h(v01, h0.y, l0.y);
                split1h(v10, h1.x, l1.x); split1h(v11, h1.y, l1.y);
                *(ushort2*)(job.C1 + (size_t)row * N + col)       = h0;
                *(ushort2*)(job.C2 + (size_t)row * N + col)       = l0;
                *(ushort2*)(job.C1 + (size_t)(row + 8) * N + col) = h1;
                *(ushort2*)(job.C2 + (size_t)(row + 8) * N + col) = l1;
            } else {
                float2 o0 = {v00, v01}, o1 = {v10, v11};
                *(float2*)(job.C + (size_t)row * N + col)       = o0;
                *(float2*)(job.C + (size_t)(row + 8) * N + col) = o1;
            }
        }
    }
}

// ================================================================
// Projection MMA, fused K/V+batch. Per-job terms (3 for K, 2 for V).
// C[b][m][n] = sum_s ET[m][s] * X[b][s][n] + bias[m]
// grid (EMB/128, PROJK/64, 8): z>>2 = job, z&3 = batch
// ================================================================
#define PA_B (64 * SKS * 2)
#define PB_RS 272
#define PB_B (32 * PB_RS)
#define PSTG (2 * PA_B + 2 * PB_B)

struct PJob { const ushort_t *A1, *A2, *B1, *B2; const float* bias; float* C; int terms; };
struct PJobs { PJob j[2]; };

__global__ __launch_bounds__(256)
void proj_mma7(PJobs jobs)
{
    extern __shared__ unsigned char smraw[];
    const uint32_t smb = (uint32_t)__cvta_generic_to_shared(smraw);

    const int tid  = threadIdx.x;
    const int wid  = tid >> 5;
    const int lane = tid & 31;
    const int gid  = lane >> 2;
    const int tig  = lane & 3;
    const int wm   = wid >> 2;
    const int wn   = wid & 3;
    const int sel  = blockIdx.z >> 2;
    const int b    = blockIdx.z & 3;
    const int m0   = blockIdx.y * 64;
    const int n0   = blockIdx.x * 128;

    const PJob job = jobs.j[sel];
    const bool t3 = (job.terms == 3);
    const ushort_t* Xb1 = job.B1 + (size_t)b * SEQ * EMB;
    const ushort_t* Xb2 = job.B2 + (size_t)b * SEQ * EMB;

    auto issue = [&](int s, int kt) {
        const int k0 = kt * 32;
        const uint32_t so = smb + s * PSTG;
        {
            int row = tid >> 2, cf = (tid & 3);
            uint32_t sa = so + (uint32_t)(row * SKS) * 2 + cf * 16;
            size_t ga = (size_t)(m0 + row) * SEQ + k0 + cf * 8;
            cp16(sa,        job.A1 + ga);
            cp16(sa + PA_B, job.A2 + ga);
        }
#pragma unroll
        for (int half = 0; half < 2; half++) {
            int cidx = half * 256 + tid;
            int row = cidx >> 4, cf = cidx & 15;
            uint32_t sb = so + 2 * PA_B + (uint32_t)(row * PB_RS) + cf * 16;
            size_t gb = (size_t)(k0 + row) * EMB + n0 + cf * 8;
            cp16(sb, Xb1 + gb);
            if (t3) cp16(sb + PB_B, Xb2 + gb);
        }
    };

    float c[2][4][4];
#pragma unroll
    for (int i = 0; i < 2; i++)
#pragma unroll
        for (int j = 0; j < 4; j++)
#pragma unroll
            for (int l = 0; l < 4; l++) c[i][j][l] = 0.f;

    const int nk = SEQ / 32;
    issue(0, 0); CP_COMMIT();
    issue(1, 1); CP_COMMIT();

    const int arow = lane & 15;
    const int acol = (lane >> 4) << 3;

    for (int kt = 0; kt < nk; kt++) {
        if (kt + 2 < nk) issue((kt + 2) % NSTAGE, kt + 2);
        CP_COMMIT();
        CP_WAIT2();
        __syncthreads();
        const uint32_t so = smb + (kt % NSTAGE) * PSTG;

#pragma unroll
        for (int kb = 0; kb < 32; kb += 16) {
            uint32_t a1f[2][4], a2f[2][4];
#pragma unroll
            for (int mt = 0; mt < 2; mt++) {
                uint32_t ad = so + (uint32_t)((wm * 32 + mt * 16 + arow) * SKS) * 2
                              + (uint32_t)(kb + acol) * 2;
                LDSM4(a1f[mt][0], a1f[mt][1], a1f[mt][2], a1f[mt][3], ad);
                LDSM4(a2f[mt][0], a2f[mt][1], a2f[mt][2], a2f[mt][3], ad + PA_B);
            }
            uint32_t b1f[2][4], b2f[2][4];
#pragma unroll
            for (int p = 0; p < 2; p++) {
                uint32_t bd = so + 2 * PA_B
                              + (uint32_t)((kb + (lane & 15)) * PB_RS)
                              + (uint32_t)(wn * 32 + p * 16 + ((lane >> 4) << 3)) * 2;
                LDSM4T(b1f[p][0], b1f[p][1], b1f[p][2], b1f[p][3], bd);
                if (t3)
                    LDSM4T(b2f[p][0], b2f[p][1], b2f[p][2], b2f[p][3], bd + PB_B);
            }
#pragma unroll
            for (int mt = 0; mt < 2; mt++)
#pragma unroll
                for (int nt = 0; nt < 4; nt++) {
                    const int p = nt >> 1, q = (nt & 1) * 2;
                    MMA_F16(c[mt][nt], a1f[mt], b1f[p][q], b1f[p][q + 1]);
                    MMA_F16(c[mt][nt], a2f[mt], b1f[p][q], b1f[p][q + 1]);
                    if (t3)
                        MMA_F16(c[mt][nt], a1f[mt], b2f[p][q], b2f[p][q + 1]);
                }
        }
        __syncthreads();
    }

#pragma unroll
    for (int mt = 0; mt < 2; mt++) {
        int row = m0 + wm * 32 + mt * 16 + gid;
        float br0 = job.bias[row], br8 = job.bias[row + 8];
#pragma unroll
        for (int nt = 0; nt < 4; nt++) {
            int col = n0 + wn * 32 + nt * 8 + tig * 2;
            float2 o0 = {c[mt][nt][0] + br0, c[mt][nt][1] + br0};
            float2 o1 = {c[mt][nt][2] + br8, c[mt][nt][3] + br8};
            *(float2*)(job.C + ((size_t)b * PROJK + row) * EMB + col)     = o0;
            *(float2*)(job.C + ((size_t)b * PROJK + row + 8) * EMB + col) = o1;
        }
    }
}

// ================================================================
// Fused attention v2 (R11 winner, output fp16 2-term)
// ================================================================
#define KST 68
#define VTST 260
#define SM_K    0
#define SM_VT   (256 * KST)
#define SM_QV   (SM_VT + 64 * VTST)
#define ATTN_FLOATS (SM_QV + 8 * 2048)

__global__ __launch_bounds__(256)
void attn_kernel2(const float* __restrict__ q,
                  const float* __restrict__ kproj,
                  const float* __restrict__ vproj,
                  ushort_t* __restrict__ ctx_1,
                  ushort_t* __restrict__ ctx_2)
{
    extern __shared__ float sm[];
    float* sk  = sm + SM_K;
    float* svT = sm + SM_VT;
    float* sq  = sm + SM_QV;
    float* smyp = sm + SM_QV;

    const int b    = blockIdx.z;
    const int h    = blockIdx.y;
    const int s0   = blockIdx.x * 64;
    const int tid  = threadIdx.x;
    const int w    = tid >> 5;
    const int lane = tid & 31;

    const float* kpB = kproj + ((size_t)b * PROJK) * EMB + h * KDIM;
    const float* vpB = vproj + ((size_t)b * PROJK) * EMB + h * KDIM;
    const float* qB  = q + ((size_t)(b * SEQ + s0)) * EMB + h * KDIM;

    for (int i = tid; i < 256 * 16; i += 256) {
        int kp = i >> 4, d4 = (i & 15) * 4;
        float4 kv4 = *(const float4*)(kpB + (size_t)kp * EMB + d4);
        *(float4*)(sk + kp * KST + d4) = kv4;
        float4 vv4 = *(const float4*)(vpB + (size_t)kp * EMB + d4);
        svT[(d4 + 0) * VTST + kp] = vv4.x;
        svT[(d4 + 1) * VTST + kp] = vv4.y;
        svT[(d4 + 2) * VTST + kp] = vv4.z;
        svT[(d4 + 3) * VTST + kp] = vv4.w;
    }
    for (int i = tid; i < 64 * 16; i += 256) {
        int r = i >> 4, d4 = (i & 15) * 4;
        *(float4*)(sq + r * 64 + d4) = *(const float4*)(qB + (size_t)r * EMB + d4);
    }
    __syncthreads();

    const int rbase = w * 8;

    float s[8][8];
#pragma unroll
    for (int r = 0; r < 8; r++)
#pragma unroll
        for (int j = 0; j < 8; j++) s[r][j] = 0.f;

#pragma unroll 2
    for (int d4 = 0; d4 < 64; d4 += 4) {
        float4 kv[8];
#pragma unroll
        for (int j = 0; j < 8; j++)
            kv[j] = *(float4*)(sk + (lane + 32 * j) * KST + d4);
#pragma unroll
        for (int r = 0; r < 8; r++) {
            float4 q4 = *(float4*)(sq + (rbase + r) * 64 + d4);
#pragma unroll
            for (int j = 0; j < 8; j++) {
                s[r][j] = fmaf(q4.x, kv[j].x, s[r][j]);
                s[r][j] = fmaf(q4.y, kv[j].y, s[r][j]);
                s[r][j] = fmaf(q4.z, kv[j].z, s[r][j]);
                s[r][j] = fmaf(q4.w, kv[j].w, s[r][j]);
            }
        }
    }
    __syncthreads();

    float* myp = smyp + w * 2048;
    float inv[8];
#pragma unroll
    for (int r = 0; r < 8; r++) {
        float m = s[r][0];
#pragma unroll
        for (int j = 1; j < 8; j++) m = fmaxf(m, s[r][j]);
#pragma unroll
        for (int o = 16; o > 0; o >>= 1)
            m = fmaxf(m, __shfl_xor_sync(0xFFFFFFFFu, m, o));
        float sum = 0.f;
#pragma unroll
        for (int j = 0; j < 8; j++) {
            s[r][j] = __expf(s[r][j] - m);
            sum += s[r][j];
        }
#pragma unroll
        for (int o = 16; o > 0; o >>= 1)
            sum += __shfl_xor_sync(0xFFFFFFFFu, sum, o);
        inv[r] = 1.f / sum;
#pragma unroll
        for (int j = 0; j < 8; j++)
            myp[r * 256 + lane + 32 * j] = s[r][j];
    }
    __syncwarp();

    float acc[8][2];
#pragma unroll
    for (int r = 0; r < 8; r++) { acc[r][0] = 0.f; acc[r][1] = 0.f; }

    const float* vA = svT + lane * VTST;
    const float* vB = svT + (lane + 32) * VTST;
#pragma unroll 2
    for (int kp4 = 0; kp4 < 256; kp4 += 4) {
        float4 va = *(const float4*)(vA + kp4);
        float4 vb = *(const float4*)(vB + kp4);
#pragma unroll
        for (int r = 0; r < 8; r++) {
            float4 p4 = *(const float4*)(myp + r * 256 + kp4);
            acc[r][0] = fmaf(p4.x, va.x, acc[r][0]);
            acc[r][0] = fmaf(p4.y, va.y, acc[r][0]);
            acc[r][0] = fmaf(p4.z, va.z, acc[r][0]);
            acc[r][0] = fmaf(p4.w, va.w, acc[r][0]);
            acc[r][1] = fmaf(p4.x, vb.x, acc[r][1]);
            acc[r][1] = fmaf(p4.y, vb.y, acc[r][1]);
            acc[r][1] = fmaf(p4.z, vb.z, acc[r][1]);
            acc[r][1] = fmaf(p4.w, vb.w, acc[r][1]);
        }
    }

#pragma unroll
    for (int r = 0; r < 8; r++) {
        size_t row = (size_t)(b * SEQ + s0 + rbase + r);
        ushort_t h0, l0, h1, l1;
        split1h(acc[r][0] * inv[r], h0, l0);
        split1h(acc[r][1] * inv[r], h1, l1);
        size_t base = row * EMB + h * KDIM;
        ctx_1[base + lane]      = h0;
        ctx_2[base + lane]      = l0;
        ctx_1[base + lane + 32] = h1;
        ctx_2[base + lane + 32] = l1;
    }
}

// ================================================================
// Launch
// ================================================================
extern "C" void kernel_launch(void* const* d_in, const int* in_sizes, int n_in,
                              void* d_out, int out_size)
{
    const float* query = (const float*)d_in[0];
    const float* value = (const float*)d_in[1];
    const float* Wq    = (const float*)d_in[2];
    const float* bq    = (const float*)d_in[3];
    const float* Wk    = (const float*)d_in[4];
    const float* bk    = (const float*)d_in[5];
    const float* Wv    = (const float*)d_in[6];
    const float* bv    = (const float*)d_in[7];
    const float* Wo    = (const float*)d_in[8];
    const float* bo    = (const float*)d_in[9];
    const float* E     = (const float*)d_in[10];
    const float* Eb    = (const float*)d_in[11];
    const float* F     = (const float*)d_in[12];
    const float* Fb    = (const float*)d_in[13];
    float* out = (float*)d_out;

    float *gq, *gkp, *gvp;
    ushort_t *qa1, *qa2, *va1, *va2, *ct1, *ct2;
    ushort_t *kb1, *kb2, *vb1, *vb2;
    ushort_t *wq1, *wq2, *wk1, *wk2, *wv1, *wv2, *wo1, *wo2;
    ushort_t *et1, *et2, *ft1, *ft2;
    cudaGetSymbolAddress((void**)&gq,  g_q);
    cudaGetSymbolAddress((void**)&gkp, g_kp);
    cudaGetSymbolAddress((void**)&gvp, g_vp);
    cudaGetSymbolAddress((void**)&qa1, g_qA_1);
    cudaGetSymbolAddress((void**)&qa2, g_qA_2);
    cudaGetSymbolAddress((void**)&va1, g_vA_1);
    cudaGetSymbolAddress((void**)&va2, g_vA_2);
    cudaGetSymbolAddress((void**)&ct1, g_ctx_1);
    cudaGetSymbolAddress((void**)&ct2, g_ctx_2);
    cudaGetSymbolAddress((void**)&kb1, g_kb_1);
    cudaGetSymbolAddress((void**)&kb2, g_kb_2);
    cudaGetSymbolAddress((void**)&vb1, g_vb_1);
    cudaGetSymbolAddress((void**)&vb2, g_vb_2);
    cudaGetSymbolAddress((void**)&wq1, g_wqT_1);
    cudaGetSymbolAddress((void**)&wq2, g_wqT_2);
    cudaGetSymbolAddress((void**)&wk1, g_wkT_1);
    cudaGetSymbolAddress((void**)&wk2, g_wkT_2);
    cudaGetSymbolAddress((void**)&wv1, g_wvT_1);
    cudaGetSymbolAddress((void**)&wv2, g_wvT_2);
    cudaGetSymbolAddress((void**)&wo1, g_woT_1);
    cudaGetSymbolAddress((void**)&wo2, g_woT_2);
    cudaGetSymbolAddress((void**)&et1, g_ET1);
    cudaGetSymbolAddress((void**)&et2, g_ET2);
    cudaGetSymbolAddress((void**)&ft1, g_FT1);
    cudaGetSymbolAddress((void**)&ft2, g_FT2);

    const float scale = 1.0f / 8.0f;
    const int nbig = MROWS * EMB;

    // splits
    split_kernel<<<nbig / 1024, 256>>>(query, qa1, qa2, nbig);
    split_kernel<<<nbig / 1024, 256>>>(value, va1, va2, nbig);

    // batched transposes
    TransJobs wjobs;
    wjobs.j[0] = {Wq, wq1, wq2};
    wjobs.j[1] = {Wk, wk1, wk2};
    wjobs.j[2] = {Wv, wv1, wv2};
    wjobs.j[3] = {Wo, wo1, wo2};
    dim3 tb(32, 8);
    split_transpose_b<<<dim3(EMB / 32, EMB / 32, 4), tb>>>(wjobs, EMB, EMB);

    TransJobs ejobs;
    ejobs.j[0] = {E, et1, et2};
    ejobs.j[1] = {F, ft1, ft2};
    ejobs.j[2] = {E, et1, et2};
    ejobs.j[3] = {F, ft1, ft2};
    split_transpose_b<<<dim3(PROJK / 32, SEQ / 32, 2), tb>>>(ejobs, SEQ, PROJK);

    // fused Q+K+V GEMM: Q,K 3-term; V 2-term (softmax-safe path)
    GJobs qkv;
    qkv.j[0] = {qa1, qa2, wq1, wq2, bq, gq, 0, 0, scale, 0, 3};
    qkv.j[1] = {va1, va2, wk1, wk2, bk, 0, kb1, kb2, 1.0f, 1, 3};
    qkv.j[2] = {va1, va2, wv1, wv2, bv, 0, vb1, vb2, 1.0f, 1, 2};
    cudaFuncSetAttribute(mma_gemm7, cudaFuncAttributeMaxDynamicSharedMemorySize, NSTAGE * GSTG);
    dim3 g_qkv(EMB / 128, MROWS / 128, 3);
    mma_gemm7<<<g_qkv, 512, NSTAGE * GSTG>>>(qkv, EMB, EMB);

    // fused projections: K 3-term, V 2-term
    PJobs pj;
    pj.j[0] = {et1, et2, kb1, kb2, Eb, gkp, 3};
    pj.j[1] = {ft1, ft2, vb1, vb2, Fb, gvp, 2};
    cudaFuncSetAttribute(proj_mma7, cudaFuncAttributeMaxDynamicSharedMemorySize, NSTAGE * PSTG);
    dim3 g_proj(EMB / 128, PROJK / 64, 8);
    proj_mma7<<<g_proj, 256, NSTAGE * PSTG>>>(pj);

    // fused attention
    size_t attn_smem = (size_t)ATTN_FLOATS * sizeof(float);
    cudaFuncSetAttribute(attn_kernel2, cudaFuncAttributeMaxDynamicSharedMemorySize, (int)attn_smem);
    dim3 attn_grid(SEQ / 64, HEADS, BATCH);
    attn_kernel2<<<attn_grid, 256, attn_smem>>>(gq, gkp, gvp, ct1, ct2);

    // output projection (fp16 3-term)
    GJobs oj;
    oj.j[0] = {ct1, ct2, wo1, wo2, bo, out, 0, 0, 1.0f, 0, 3};
    oj.j[1] = oj.j[0];
    oj.j[2] = oj.j[0];
    dim3 g_out(EMB / 128, MROWS / 128, 1);
    mma_gemm7<<<g_out, 512, NSTAGE * GSTG>>>(oj, EMB, EMB);
}

// round 15
// speedup vs baseline: 2.5097x; 1.0188x over previous
#include <cuda_runtime.h>
#include <cuda_fp16.h>
#include <math.h>
#include <stdint.h>

// Problem constants
#define BATCH 4
#define SEQ   2048
#define EMB   1024     // H * Dk
#define HEADS 16
#define KDIM  64
#define PROJK 256
#define MROWS (BATCH * SEQ)   // 8192

typedef unsigned short ushort_t;

// ---------------- scratch (allocation-free) ----------------
__device__ float g_q [MROWS * EMB];
__device__ float g_kp[BATCH * PROJK * EMB];
__device__ float g_vp[BATCH * PROJK * EMB];
// fp16 2-term representations (h1 + h2 ~ fp32 to 2^-22)
__device__ ushort_t g_qA_1[MROWS * EMB], g_qA_2[MROWS * EMB];
__device__ ushort_t g_vA_1[MROWS * EMB], g_vA_2[MROWS * EMB];
__device__ ushort_t g_ctx_1[MROWS * EMB], g_ctx_2[MROWS * EMB];
__device__ ushort_t g_kb_1[MROWS * EMB], g_kb_2[MROWS * EMB];
__device__ ushort_t g_vb_1[MROWS * EMB], g_vb_2[MROWS * EMB];
__device__ ushort_t g_wqT_1[EMB * EMB], g_wqT_2[EMB * EMB];
__device__ ushort_t g_wkT_1[EMB * EMB], g_wkT_2[EMB * EMB];
__device__ ushort_t g_wvT_1[EMB * EMB], g_wvT_2[EMB * EMB];
__device__ ushort_t g_woT_1[EMB * EMB], g_woT_2[EMB * EMB];
__device__ ushort_t g_ET1[PROJK * SEQ], g_ET2[PROJK * SEQ];
__device__ ushort_t g_FT1[PROJK * SEQ], g_FT2[PROJK * SEQ];

// ---------------- helpers ----------------
__device__ __forceinline__ void split1h(float v, ushort_t& h, ushort_t& l) {
    __half a = __float2half_rn(v);
    __half b = __float2half_rn(v - __half2float(a));
    h = __half_as_ushort(a);
    l = __half_as_ushort(b);
}

#define MMA_F16(d, a, b0, b1) asm volatile( \
    "mma.sync.aligned.m16n8k16.row.col.f32.f16.f16.f32 " \
    "{%0,%1,%2,%3}, {%4,%5,%6,%7}, {%8,%9}, {%0,%1,%2,%3};\n" \
    : "+f"((d)[0]), "+f"((d)[1]), "+f"((d)[2]), "+f"((d)[3]) \
    : "r"((a)[0]), "r"((a)[1]), "r"((a)[2]), "r"((a)[3]), \
      "r"(b0), "r"(b1))

#define LDSM4(r0, r1, r2, r3, addr) asm volatile( \
    "ldmatrix.sync.aligned.m8n8.x4.shared.b16 {%0,%1,%2,%3}, [%4];\n" \
    : "=r"(r0), "=r"(r1), "=r"(r2), "=r"(r3) : "r"(addr))

#define LDSM4T(r0, r1, r2, r3, addr) asm volatile( \
    "ldmatrix.sync.aligned.m8n8.x4.trans.shared.b16 {%0,%1,%2,%3}, [%4];\n" \
    : "=r"(r0), "=r"(r1), "=r"(r2), "=r"(r3) : "r"(addr))

__device__ __forceinline__ void cp16(uint32_t dst, const void* src) {
    asm volatile("cp.async.cg.shared.global [%0], [%1], 16;\n" :: "r"(dst), "l"(src));
}
#define CP_COMMIT() asm volatile("cp.async.commit_group;\n" ::: "memory")
#define CP_WAIT2()  asm volatile("cp.async.wait_group 2;\n" ::: "memory")

// ================================================================
// split_kernel: fp32 -> fp16 2-term, vectorized
// ================================================================
__global__ __launch_bounds__(256)
void split_kernel(const float* __restrict__ src,
                  ushort_t* __restrict__ h1,
                  ushort_t* __restrict__ h2, int n)
{
    int i = (blockIdx.x * 256 + threadIdx.x) * 4;
    if (i >= n) return;
    float4 v = *(const float4*)(src + i);
    ushort4 a, b;
    split1h(v.x, a.x, b.x);
    split1h(v.y, a.y, b.y);
    split1h(v.z, a.z, b.z);
    split1h(v.w, a.w, b.w);
    *(ushort4*)(h1 + i) = a;
    *(ushort4*)(h2 + i) = b;
}

// ================================================================
// Batched split+transpose: W[K][N] fp32 -> WT[N][K] fp16 2-term
// ================================================================
struct TransJob { const float* W; ushort_t* h1; ushort_t* h2; };
struct TransJobs { TransJob j[4]; };

__global__ __launch_bounds__(256)
void split_transpose_b(TransJobs jobs, int K, int N)
{
    __shared__ float t[32][33];
    const TransJob jb = jobs.j[blockIdx.z];
    int k0 = blockIdx.y * 32, n0 = blockIdx.x * 32;
    int tx = threadIdx.x, ty = threadIdx.y;
#pragma unroll
    for (int i = 0; i < 32; i += 8)
        t[ty + i][tx] = jb.W[(size_t)(k0 + ty + i) * N + n0 + tx];
    __syncthreads();
#pragma unroll
    for (int i = 0; i < 32; i += 8) {
        float v = t[tx][ty + i];
        ushort_t a, b;
        split1h(v, a, b);
        jb.h1[(size_t)(n0 + ty + i) * K + k0 + tx] = a;
        jb.h2[(size_t)(n0 + ty + i) * K + k0 + tx] = b;
    }
}

// ================================================================
// Big GEMM (fp16 split, mma.sync), 512 threads, 16 warps, 32x32 warp.
// job.terms==3: A1B1 + A2B1 + A1B2 (err ~2^-22)
// job.terms==2: A1B1 + A2B1       (err ~2^-11 from B rounding)
// grid.z selects job (QKV fused in one launch).
// ================================================================
#define SKS 40
#define ARR_B (128 * SKS * 2)
#define GSTG (4 * ARR_B)
#define NSTAGE 3

struct GJob {
    const ushort_t *A1, *A2, *B1, *B2;
    const float* bias;
    float* C;
    ushort_t *C1, *C2;
    float alpha;
    int split_out;
    int terms;
};
struct GJobs { GJob j[3]; };

__global__ __launch_bounds__(512)
void mma_gemm7(GJobs jobs, int N, int K)
{
    extern __shared__ unsigned char smraw[];
    const uint32_t smb = (uint32_t)__cvta_generic_to_shared(smraw);

    const GJob job = jobs.j[blockIdx.z];
    const bool t3 = (job.terms == 3);

    const int tid  = threadIdx.x;
    const int wid  = tid >> 5;
    const int lane = tid & 31;
    const int gid  = lane >> 2;
    const int tig  = lane & 3;
    const int wm   = wid >> 2;
    const int wn   = wid & 3;
    const int m0   = blockIdx.y * 128;
    const int n0   = blockIdx.x * 128;

    const int lrow = tid >> 2;
    const int lcf  = (tid & 3) * 8;

    auto issue = [&](int s, int kt) {
        const int k0 = kt * 32;
        const uint32_t so = smb + s * GSTG;
        const uint32_t ro = (uint32_t)(lrow * SKS + lcf) * 2;
        const size_t ga = (size_t)(m0 + lrow) * K + k0 + lcf;
        const size_t gb = (size_t)(n0 + lrow) * K + k0 + lcf;
        cp16(so + ro,             job.A1 + ga);
        cp16(so + ARR_B + ro,     job.A2 + ga);
        cp16(so + 2 * ARR_B + ro, job.B1 + gb);
        if (t3) cp16(so + 3 * ARR_B + ro, job.B2 + gb);
    };

    float c[2][4][4];
#pragma unroll
    for (int i = 0; i < 2; i++)
#pragma unroll
        for (int j = 0; j < 4; j++)
#pragma unroll
            for (int l = 0; l < 4; l++) c[i][j][l] = 0.f;

    const int nk = K / 32;
    issue(0, 0); CP_COMMIT();
    issue(1, 1); CP_COMMIT();

    const int arow = lane & 15;
    const int acol = (lane >> 4) << 3;

    for (int kt = 0; kt < nk; kt++) {
        if (kt + 2 < nk) issue((kt + 2) % NSTAGE, kt + 2);
        CP_COMMIT();
        CP_WAIT2();
        __syncthreads();
        const uint32_t so = smb + (kt % NSTAGE) * GSTG;

#pragma unroll
        for (int kb = 0; kb < 32; kb += 16) {
            const uint32_t koff = (uint32_t)(kb + acol) * 2;
            uint32_t a1f[2][4], a2f[2][4];
#pragma unroll
            for (int mt = 0; mt < 2; mt++) {
                uint32_t ad = so + (uint32_t)((wm * 32 + mt * 16 + arow) * SKS) * 2 + koff;
                LDSM4(a1f[mt][0], a1f[mt][1], a1f[mt][2], a1f[mt][3], ad);
                LDSM4(a2f[mt][0], a2f[mt][1], a2f[mt][2], a2f[mt][3], ad + ARR_B);
            }
            uint32_t b1f[2][4], b2f[2][4];
#pragma unroll
            for (int p = 0; p < 2; p++) {
                uint32_t bd = so + 2 * ARR_B +
                              (uint32_t)((wn * 32 + p * 16 + arow) * SKS) * 2 + koff;
                LDSM4(b1f[p][0], b1f[p][1], b1f[p][2], b1f[p][3], bd);
                if (t3)
                    LDSM4(b2f[p][0], b2f[p][1], b2f[p][2], b2f[p][3], bd + ARR_B);
            }
#pragma unroll
            for (int mt = 0; mt < 2; mt++)
#pragma unroll
                for (int nt = 0; nt < 4; nt++) {
                    const int p = nt >> 1, q = nt & 1;
                    MMA_F16(c[mt][nt], a1f[mt], b1f[p][q], b1f[p][q + 2]);
                    MMA_F16(c[mt][nt], a2f[mt], b1f[p][q], b1f[p][q + 2]);
                    if (t3)
                        MMA_F16(c[mt][nt], a1f[mt], b2f[p][q], b2f[p][q + 2]);
                }
        }
        __syncthreads();
    }

#pragma unroll
    for (int mt = 0; mt < 2; mt++) {
        int row = m0 + wm * 32 + mt * 16 + gid;
#pragma unroll
        for (int nt = 0; nt < 4; nt++) {
            int col = n0 + wn * 32 + nt * 8 + tig * 2;
            float b0 = job.bias[col], b1 = job.bias[col + 1];
            float v00 = (c[mt][nt][0] + b0) * job.alpha;
            float v01 = (c[mt][nt][1] + b1) * job.alpha;
            float v10 = (c[mt][nt][2] + b0) * job.alpha;
            float v11 = (c[mt][nt][3] + b1) * job.alpha;
            if (job.split_out) {
                ushort2 h0, l0, h1, l1;
                split1h(v00, h0.x, l0.x); split1h(v01, h0.y, l0.y);
                split1h(v10, h1.x, l1.x); split1h(v11, h1.y, l1.y);
                *(ushort2*)(job.C1 + (size_t)row * N + col)       = h0;
                *(ushort2*)(job.C2 + (size_t)row * N + col)       = l0;
                *(ushort2*)(job.C1 + (size_t)(row + 8) * N + col) = h1;
                *(ushort2*)(job.C2 + (size_t)(row + 8) * N + col) = l1;
            } else {
                float2 o0 = {v00, v01}, o1 = {v10, v11};
                *(float2*)(job.C + (size_t)row * N + col)       = o0;
                *(float2*)(job.C + (size_t)(row + 8) * N + col) = o1;
            }
        }
    }
}

// ================================================================
// Projection MMA, fused K/V+batch. Per-job terms (3 for K, 2 for V).
// C[b][m][n] = sum_s ET[m][s] * X[b][s][n] + bias[m]
// grid (EMB/128, PROJK/64, 8): z>>2 = job, z&3 = batch
// ================================================================
#define PA_B (64 * SKS * 2)
#define PB_RS 272
#define PB_B (32 * PB_RS)
#define PSTG (2 * PA_B + 2 * PB_B)

struct PJob { const ushort_t *A1, *A2, *B1, *B2; const float* bias; float* C; int terms; };
struct PJobs { PJob j[2]; };

__global__ __launch_bounds__(256)
void proj_mma7(PJobs jobs)
{
    extern __shared__ unsigned char smraw[];
    const uint32_t smb = (uint32_t)__cvta_generic_to_shared(smraw);

    const int tid  = threadIdx.x;
    const int wid  = tid >> 5;
    const int lane = tid & 31;
    const int gid  = lane >> 2;
    const int tig  = lane & 3;
    const int wm   = wid >> 2;
    const int wn   = wid & 3;
    const int sel  = blockIdx.z >> 2;
    const int b    = blockIdx.z & 3;
    const int m0   = blockIdx.y * 64;
    const int n0   = blockIdx.x * 128;

    const PJob job = jobs.j[sel];
    const bool t3 = (job.terms == 3);
    const ushort_t* Xb1 = job.B1 + (size_t)b * SEQ * EMB;
    const ushort_t* Xb2 = job.B2 + (size_t)b * SEQ * EMB;

    auto issue = [&](int s, int kt) {
        const int k0 = kt * 32;
        const uint32_t so = smb + s * PSTG;
        {
            int row = tid >> 2, cf = (tid & 3);
            uint32_t sa = so + (uint32_t)(row * SKS) * 2 + cf * 16;
            size_t ga = (size_t)(m0 + row) * SEQ + k0 + cf * 8;
            cp16(sa,        job.A1 + ga);
            cp16(sa + PA_B, job.A2 + ga);
        }
#pragma unroll
        for (int half = 0; half < 2; half++) {
            int cidx = half * 256 + tid;
            int row = cidx >> 4, cf = cidx & 15;
            uint32_t sb = so + 2 * PA_B + (uint32_t)(row * PB_RS) + cf * 16;
            size_t gb = (size_t)(k0 + row) * EMB + n0 + cf * 8;
            cp16(sb, Xb1 + gb);
            if (t3) cp16(sb + PB_B, Xb2 + gb);
        }
    };

    float c[2][4][4];
#pragma unroll
    for (int i = 0; i < 2; i++)
#pragma unroll
        for (int j = 0; j < 4; j++)
#pragma unroll
            for (int l = 0; l < 4; l++) c[i][j][l] = 0.f;

    const int nk = SEQ / 32;
    issue(0, 0); CP_COMMIT();
    issue(1, 1); CP_COMMIT();

    const int arow = lane & 15;
    const int acol = (lane >> 4) << 3;

    for (int kt = 0; kt < nk; kt++) {
        if (kt + 2 < nk) issue((kt + 2) % NSTAGE, kt + 2);
        CP_COMMIT();
        CP_WAIT2();
        __syncthreads();
        const uint32_t so = smb + (kt % NSTAGE) * PSTG;

#pragma unroll
        for (int kb = 0; kb < 32; kb += 16) {
            uint32_t a1f[2][4], a2f[2][4];
#pragma unroll
            for (int mt = 0; mt < 2; mt++) {
                uint32_t ad = so + (uint32_t)((wm * 32 + mt * 16 + arow) * SKS) * 2
                              + (uint32_t)(kb + acol) * 2;
                LDSM4(a1f[mt][0], a1f[mt][1], a1f[mt][2], a1f[mt][3], ad);
                LDSM4(a2f[mt][0], a2f[mt][1], a2f[mt][2], a2f[mt][3], ad + PA_B);
            }
            uint32_t b1f[2][4], b2f[2][4];
#pragma unroll
            for (int p = 0; p < 2; p++) {
                uint32_t bd = so + 2 * PA_B
                              + (uint32_t)((kb + (lane & 15)) * PB_RS)
                              + (uint32_t)(wn * 32 + p * 16 + ((lane >> 4) << 3)) * 2;
                LDSM4T(b1f[p][0], b1f[p][1], b1f[p][2], b1f[p][3], bd);
                if (t3)
                    LDSM4T(b2f[p][0], b2f[p][1], b2f[p][2], b2f[p][3], bd + PB_B);
            }
#pragma unroll
            for (int mt = 0; mt < 2; mt++)
#pragma unroll
                for (int nt = 0; nt < 4; nt++) {
                    const int p = nt >> 1, q = (nt & 1) * 2;
                    MMA_F16(c[mt][nt], a1f[mt], b1f[p][q], b1f[p][q + 1]);
                    MMA_F16(c[mt][nt], a2f[mt], b1f[p][q], b1f[p][q + 1]);
                    if (t3)
                        MMA_F16(c[mt][nt], a1f[mt], b2f[p][q], b2f[p][q + 1]);
                }
        }
        __syncthreads();
    }

#pragma unroll
    for (int mt = 0; mt < 2; mt++) {
        int row = m0 + wm * 32 + mt * 16 + gid;
        float br0 = job.bias[row], br8 = job.bias[row + 8];
#pragma unroll
        for (int nt = 0; nt < 4; nt++) {
            int col = n0 + wn * 32 + nt * 8 + tig * 2;
            float2 o0 = {c[mt][nt][0] + br0, c[mt][nt][1] + br0};
            float2 o1 = {c[mt][nt][2] + br8, c[mt][nt][3] + br8};
            *(float2*)(job.C + ((size_t)b * PROJK + row) * EMB + col)     = o0;
            *(float2*)(job.C + ((size_t)b * PROJK + row + 8) * EMB + col) = o1;
        }
    }
}

// ================================================================
// Fused attention v2 (R11 winner, output fp16 2-term)
// ================================================================
#define KST 68
#define VTST 260
#define SM_K    0
#define SM_VT   (256 * KST)
#define SM_QV   (SM_VT + 64 * VTST)
#define ATTN_FLOATS (SM_QV + 8 * 2048)

__global__ __launch_bounds__(256)
void attn_kernel2(const float* __restrict__ q,
                  const float* __restrict__ kproj,
                  const float* __restrict__ vproj,
                  ushort_t* __restrict__ ctx_1,
                  ushort_t* __restrict__ ctx_2)
{
    extern __shared__ float sm[];
    float* sk  = sm + SM_K;
    float* svT = sm + SM_VT;
    float* sq  = sm + SM_QV;
    float* smyp = sm + SM_QV;

    const int b    = blockIdx.z;
    const int h    = blockIdx.y;
    const int s0   = blockIdx.x * 64;
    const int tid  = threadIdx.x;
    const int w    = tid >> 5;
    const int lane = tid & 31;

    const float* kpB = kproj + ((size_t)b * PROJK) * EMB + h * KDIM;
    const float* vpB = vproj + ((size_t)b * PROJK) * EMB + h * KDIM;
    const float* qB  = q + ((size_t)(b * SEQ + s0)) * EMB + h * KDIM;

    for (int i = tid; i < 256 * 16; i += 256) {
        int kp = i >> 4, d4 = (i & 15) * 4;
        float4 kv4 = *(const float4*)(kpB + (size_t)kp * EMB + d4);
        *(float4*)(sk + kp * KST + d4) = kv4;
        float4 vv4 = *(const float4*)(vpB + (size_t)kp * EMB + d4);
        svT[(d4 + 0) * VTST + kp] = vv4.x;
        svT[(d4 + 1) * VTST + kp] = vv4.y;
        svT[(d4 + 2) * VTST + kp] = vv4.z;
        svT[(d4 + 3) * VTST + kp] = vv4.w;
    }
    for (int i = tid; i < 64 * 16; i += 256) {
        int r = i >> 4, d4 = (i & 15) * 4;
        *(float4*)(sq + r * 64 + d4) = *(const float4*)(qB + (size_t)r * EMB + d4);
    }
    __syncthreads();

    const int rbase = w * 8;

    float s[8][8];
#pragma unroll
    for (int r = 0; r < 8; r++)
#pragma unroll
        for (int j = 0; j < 8; j++) s[r][j] = 0.f;

#pragma unroll 2
    for (int d4 = 0; d4 < 64; d4 += 4) {
        float4 kv[8];
#pragma unroll
        for (int j = 0; j < 8; j++)
            kv[j] = *(float4*)(sk + (lane + 32 * j) * KST + d4);
#pragma unroll
        for (int r = 0; r < 8; r++) {
            float4 q4 = *(float4*)(sq + (rbase + r) * 64 + d4);
#pragma unroll
            for (int j = 0; j < 8; j++) {
                s[r][j] = fmaf(q4.x, kv[j].x, s[r][j]);
                s[r][j] = fmaf(q4.y, kv[j].y, s[r][j]);
                s[r][j] = fmaf(q4.z, kv[j].z, s[r][j]);
                s[r][j] = fmaf(q4.w, kv[j].w, s[r][j]);
            }
        }
    }
    __syncthreads();

    float* myp = smyp + w * 2048;
    float inv[8];
#pragma unroll
    for (int r = 0; r < 8; r++) {
        float m = s[r][0];
#pragma unroll
        for (int j = 1; j < 8; j++) m = fmaxf(m, s[r][j]);
#pragma unroll
        for (int o = 16; o > 0; o >>= 1)
            m = fmaxf(m, __shfl_xor_sync(0xFFFFFFFFu, m, o));
        float sum = 0.f;
#pragma unroll
        for (int j = 0; j < 8; j++) {
            s[r][j] = __expf(s[r][j] - m);
            sum += s[r][j];
        }
#pragma unroll
        for (int o = 16; o > 0; o >>= 1)
            sum += __shfl_xor_sync(0xFFFFFFFFu, sum, o);
        inv[r] = 1.f / sum;
#pragma unroll
        for (int j = 0; j < 8; j++)
            myp[r * 256 + lane + 32 * j] = s[r][j];
    }
    __syncwarp();

    float acc[8][2];
#pragma unroll
    for (int r = 0; r < 8; r++) { acc[r][0] = 0.f; acc[r][1] = 0.f; }

    const float* vA = svT + lane * VTST;
    const float* vB = svT + (lane + 32) * VTST;
#pragma unroll 2
    for (int kp4 = 0; kp4 < 256; kp4 += 4) {
        float4 va = *(const float4*)(vA + kp4);
        float4 vb = *(const float4*)(vB + kp4);
#pragma unroll
        for (int r = 0; r < 8; r++) {
            float4 p4 = *(const float4*)(myp + r * 256 + kp4);
            acc[r][0] = fmaf(p4.x, va.x, acc[r][0]);
            acc[r][0] = fmaf(p4.y, va.y, acc[r][0]);
            acc[r][0] = fmaf(p4.z, va.z, acc[r][0]);
            acc[r][0] = fmaf(p4.w, va.w, acc[r][0]);
            acc[r][1] = fmaf(p4.x, vb.x, acc[r][1]);
            acc[r][1] = fmaf(p4.y, vb.y, acc[r][1]);
            acc[r][1] = fmaf(p4.z, vb.z, acc[r][1]);
            acc[r][1] = fmaf(p4.w, vb.w, acc[r][1]);
        }
    }

#pragma unroll
    for (int r = 0; r < 8; r++) {
        size_t row = (size_t)(b * SEQ + s0 + rbase + r);
        ushort_t h0, l0, h1, l1;
        split1h(acc[r][0] * inv[r], h0, l0);
        split1h(acc[r][1] * inv[r], h1, l1);
        size_t base = row * EMB + h * KDIM;
        ctx_1[base + lane]      = h0;
        ctx_2[base + lane]      = l0;
        ctx_1[base + lane + 32] = h1;
        ctx_2[base + lane + 32] = l1;
    }
}

// ================================================================
// Launch
// ================================================================
extern "C" void kernel_launch(void* const* d_in, const int* in_sizes, int n_in,
                              void* d_out, int out_size)
{
    const float* query = (const float*)d_in[0];
    const float* value = (const float*)d_in[1];
    const float* Wq    = (const float*)d_in[2];
    const float* bq    = (const float*)d_in[3];
    const float* Wk    = (const float*)d_in[4];
    const float* bk    = (const float*)d_in[5];
    const float* Wv    = (const float*)d_in[6];
    const float* bv    = (const float*)d_in[7];
    const float* Wo    = (const float*)d_in[8];
    const float* bo    = (const float*)d_in[9];
    const float* E     = (const float*)d_in[10];
    const float* Eb    = (const float*)d_in[11];
    const float* F     = (const float*)d_in[12];
    const float* Fb    = (const float*)d_in[13];
    float* out = (float*)d_out;

    float *gq, *gkp, *gvp;
    ushort_t *qa1, *qa2, *va1, *va2, *ct1, *ct2;
    ushort_t *kb1, *kb2, *vb1, *vb2;
    ushort_t *wq1, *wq2, *wk1, *wk2, *wv1, *wv2, *wo1, *wo2;
    ushort_t *et1, *et2, *ft1, *ft2;
    cudaGetSymbolAddress((void**)&gq,  g_q);
    cudaGetSymbolAddress((void**)&gkp, g_kp);
    cudaGetSymbolAddress((void**)&gvp, g_vp);
    cudaGetSymbolAddress((void**)&qa1, g_qA_1);
    cudaGetSymbolAddress((void**)&qa2, g_qA_2);
    cudaGetSymbolAddress((void**)&va1, g_vA_1);
    cudaGetSymbolAddress((void**)&va2, g_vA_2);
    cudaGetSymbolAddress((void**)&ct1, g_ctx_1);
    cudaGetSymbolAddress((void**)&ct2, g_ctx_2);
    cudaGetSymbolAddress((void**)&kb1, g_kb_1);
    cudaGetSymbolAddress((void**)&kb2, g_kb_2);
    cudaGetSymbolAddress((void**)&vb1, g_vb_1);
    cudaGetSymbolAddress((void**)&vb2, g_vb_2);
    cudaGetSymbolAddress((void**)&wq1, g_wqT_1);
    cudaGetSymbolAddress((void**)&wq2, g_wqT_2);
    cudaGetSymbolAddress((void**)&wk1, g_wkT_1);
    cudaGetSymbolAddress((void**)&wk2, g_wkT_2);
    cudaGetSymbolAddress((void**)&wv1, g_wvT_1);
    cudaGetSymbolAddress((void**)&wv2, g_wvT_2);
    cudaGetSymbolAddress((void**)&wo1, g_woT_1);
    cudaGetSymbolAddress((void**)&wo2, g_woT_2);
    cudaGetSymbolAddress((void**)&et1, g_ET1);
    cudaGetSymbolAddress((void**)&et2, g_ET2);
    cudaGetSymbolAddress((void**)&ft1, g_FT1);
    cudaGetSymbolAddress((void**)&ft2, g_FT2);

    const float scale = 1.0f / 8.0f;
    const int nbig = MROWS * EMB;

    // splits
    split_kernel<<<nbig / 1024, 256>>>(query, qa1, qa2, nbig);
    split_kernel<<<nbig / 1024, 256>>>(value, va1, va2, nbig);

    // batched transposes
    TransJobs wjobs;
    wjobs.j[0] = {Wq, wq1, wq2};
    wjobs.j[1] = {Wk, wk1, wk2};
    wjobs.j[2] = {Wv, wv1, wv2};
    wjobs.j[3] = {Wo, wo1, wo2};
    dim3 tb(32, 8);
    split_transpose_b<<<dim3(EMB / 32, EMB / 32, 4), tb>>>(wjobs, EMB, EMB);

    TransJobs ejobs;
    ejobs.j[0] = {E, et1, et2};
    ejobs.j[1] = {F, ft1, ft2};
    ejobs.j[2] = {E, et1, et2};
    ejobs.j[3] = {F, ft1, ft2};
    split_transpose_b<<<dim3(PROJK / 32, SEQ / 32, 2), tb>>>(ejobs, SEQ, PROJK);

    // fused Q+K+V GEMM: Q,K 3-term (softmax-amplified); V 2-term (linear path)
    GJobs qkv;
    qkv.j[0] = {qa1, qa2, wq1, wq2, bq, gq, 0, 0, scale, 0, 3};
    qkv.j[1] = {va1, va2, wk1, wk2, bk, 0, kb1, kb2, 1.0f, 1, 3};
    qkv.j[2] = {va1, va2, wv1, wv2, bv, 0, vb1, vb2, 1.0f, 1, 2};
    cudaFuncSetAttribute(mma_gemm7, cudaFuncAttributeMaxDynamicSharedMemorySize, NSTAGE * GSTG);
    dim3 g_qkv(EMB / 128, MROWS / 128, 3);
    mma_gemm7<<<g_qkv, 512, NSTAGE * GSTG>>>(qkv, EMB, EMB);

    // fused projections: K 3-term, V 2-term
    PJobs pj;
    pj.j[0] = {et1, et2, kb1, kb2, Eb, gkp, 3};
    pj.j[1] = {ft1, ft2, vb1, vb2, Fb, gvp, 2};
    cudaFuncSetAttribute(proj_mma7, cudaFuncAttributeMaxDynamicSharedMemorySize, NSTAGE * PSTG);
    dim3 g_proj(EMB / 128, PROJK / 64, 8);
    proj_mma7<<<g_proj, 256, NSTAGE * PSTG>>>(pj);

    // fused attention
    size_t attn_smem = (size_t)ATTN_FLOATS * sizeof(float);
    cudaFuncSetAttribute(attn_kernel2, cudaFuncAttributeMaxDynamicSharedMemorySize, (int)attn_smem);
    dim3 attn_grid(SEQ / 64, HEADS, BATCH);
    attn_kernel2<<<attn_grid, 256, attn_smem>>>(gq, gkp, gvp, ct1, ct2);

    // output projection: 2-term (post-softmax linear path — Wo-lo dropped)
    GJobs oj;
    oj.j[0] = {ct1, ct2, wo1, wo2, bo, out, 0, 0, 1.0f, 0, 2};
    oj.j[1] = oj.j[0];
    oj.j[2] = oj.j[0];
    dim3 g_out(EMB / 128, MROWS / 128, 1);
    mma_gemm7<<<g_out, 512, NSTAGE * GSTG>>>(oj, EMB, EMB);
}

// round 16
// speedup vs baseline: 2.6710x; 1.0643x over previous
#include <cuda_runtime.h>
#include <cuda_fp16.h>
#include <math.h>
#include <stdint.h>

// Problem constants
#define BATCH 4
#define SEQ   2048
#define EMB   1024     // H * Dk
#define HEADS 16
#define KDIM  64
#define PROJK 256
#define MROWS (BATCH * SEQ)   // 8192

typedef unsigned short ushort_t;

// ---------------- scratch (allocation-free) ----------------
__device__ float g_q [MROWS * EMB];
__device__ float g_kp[BATCH * PROJK * EMB];
__device__ float g_vp[BATCH * PROJK * EMB];
// fp16 2-term representations (h1 + h2 ~ fp32 to 2^-22)
__device__ ushort_t g_qA_1[MROWS * EMB], g_qA_2[MROWS * EMB];
__device__ ushort_t g_vA_1[MROWS * EMB], g_vA_2[MROWS * EMB];
__device__ ushort_t g_ctx_1[MROWS * EMB];
__device__ ushort_t g_kb_1[MROWS * EMB], g_kb_2[MROWS * EMB];
__device__ ushort_t g_vb_1[MROWS * EMB];
__device__ ushort_t g_vb_2[MROWS * EMB];   // unused (V split_out=2) — kept for layout
__device__ ushort_t g_wqT_1[EMB * EMB], g_wqT_2[EMB * EMB];
__device__ ushort_t g_wkT_1[EMB * EMB], g_wkT_2[EMB * EMB];
__device__ ushort_t g_wvT_1[EMB * EMB], g_wvT_2[EMB * EMB];
__device__ ushort_t g_woT_1[EMB * EMB], g_woT_2[EMB * EMB];
__device__ ushort_t g_ET1[PROJK * SEQ], g_ET2[PROJK * SEQ];
__device__ ushort_t g_FT1[PROJK * SEQ], g_FT2[PROJK * SEQ];

// ---------------- helpers ----------------
__device__ __forceinline__ void split1h(float v, ushort_t& h, ushort_t& l) {
    __half a = __float2half_rn(v);
    __half b = __float2half_rn(v - __half2float(a));
    h = __half_as_ushort(a);
    l = __half_as_ushort(b);
}

#define MMA_F16(d, a, b0, b1) asm volatile( \
    "mma.sync.aligned.m16n8k16.row.col.f32.f16.f16.f32 " \
    "{%0,%1,%2,%3}, {%4,%5,%6,%7}, {%8,%9}, {%0,%1,%2,%3};\n" \
    : "+f"((d)[0]), "+f"((d)[1]), "+f"((d)[2]), "+f"((d)[3]) \
    : "r"((a)[0]), "r"((a)[1]), "r"((a)[2]), "r"((a)[3]), \
      "r"(b0), "r"(b1))

#define LDSM4(r0, r1, r2, r3, addr) asm volatile( \
    "ldmatrix.sync.aligned.m8n8.x4.shared.b16 {%0,%1,%2,%3}, [%4];\n" \
    : "=r"(r0), "=r"(r1), "=r"(r2), "=r"(r3) : "r"(addr))

#define LDSM4T(r0, r1, r2, r3, addr) asm volatile( \
    "ldmatrix.sync.aligned.m8n8.x4.trans.shared.b16 {%0,%1,%2,%3}, [%4];\n" \
    : "=r"(r0), "=r"(r1), "=r"(r2), "=r"(r3) : "r"(addr))

__device__ __forceinline__ void cp16(uint32_t dst, const void* src) {
    asm volatile("cp.async.cg.shared.global [%0], [%1], 16;\n" :: "r"(dst), "l"(src));
}
#define CP_COMMIT() asm volatile("cp.async.commit_group;\n" ::: "memory")
#define CP_WAIT2()  asm volatile("cp.async.wait_group 2;\n" ::: "memory")

// ================================================================
// split_kernel: fp32 -> fp16 2-term, vectorized
// ================================================================
__global__ __launch_bounds__(256)
void split_kernel(const float* __restrict__ src,
                  ushort_t* __restrict__ h1,
                  ushort_t* __restrict__ h2, int n)
{
    int i = (blockIdx.x * 256 + threadIdx.x) * 4;
    if (i >= n) return;
    float4 v = *(const float4*)(src + i);
    ushort4 a, b;
    split1h(v.x, a.x, b.x);
    split1h(v.y, a.y, b.y);
    split1h(v.z, a.z, b.z);
    split1h(v.w, a.w, b.w);
    *(ushort4*)(h1 + i) = a;
    *(ushort4*)(h2 + i) = b;
}

// ================================================================
// Batched split+transpose: W[K][N] fp32 -> WT[N][K] fp16 2-term
// ================================================================
struct TransJob { const float* W; ushort_t* h1; ushort_t* h2; };
struct TransJobs { TransJob j[4]; };

__global__ __launch_bounds__(256)
void split_transpose_b(TransJobs jobs, int K, int N)
{
    __shared__ float t[32][33];
    const TransJob jb = jobs.j[blockIdx.z];
    int k0 = blockIdx.y * 32, n0 = blockIdx.x * 32;
    int tx = threadIdx.x, ty = threadIdx.y;
#pragma unroll
    for (int i = 0; i < 32; i += 8)
        t[ty + i][tx] = jb.W[(size_t)(k0 + ty + i) * N + n0 + tx];
    __syncthreads();
#pragma unroll
    for (int i = 0; i < 32; i += 8) {
        float v = t[tx][ty + i];
        ushort_t a, b;
        split1h(v, a, b);
        jb.h1[(size_t)(n0 + ty + i) * K + k0 + tx] = a;
        jb.h2[(size_t)(n0 + ty + i) * K + k0 + tx] = b;
    }
}

// ================================================================
// Big GEMM (fp16 split, mma.sync), 512 threads, 16 warps, 32x32 warp.
// terms==3: A1B1 + A2B1 + A1B2   (err ~2^-22)
// terms==2: A1B1 + A2B1          (err ~2^-11, B rounding)
// terms==1: A1B1                 (err ~2^-10.5, A+B rounding)
// split_out: 0 = fp32 C; 1 = C1+C2 split; 2 = C1 only (fp16 round)
// grid.z selects job (QKV fused in one launch).
// ================================================================
#define SKS 40
#define ARR_B (128 * SKS * 2)
#define GSTG (4 * ARR_B)
#define NSTAGE 3

struct GJob {
    const ushort_t *A1, *A2, *B1, *B2;
    const float* bias;
    float* C;
    ushort_t *C1, *C2;
    float alpha;
    int split_out;
    int terms;
};
struct GJobs { GJob j[3]; };

__global__ __launch_bounds__(512)
void mma_gemm7(GJobs jobs, int N, int K)
{
    extern __shared__ unsigned char smraw[];
    const uint32_t smb = (uint32_t)__cvta_generic_to_shared(smraw);

    const GJob job = jobs.j[blockIdx.z];
    const bool t3 = (job.terms == 3);
    const bool t2 = (job.terms >= 2);

    const int tid  = threadIdx.x;
    const int wid  = tid >> 5;
    const int lane = tid & 31;
    const int gid  = lane >> 2;
    const int tig  = lane & 3;
    const int wm   = wid >> 2;
    const int wn   = wid & 3;
    const int m0   = blockIdx.y * 128;
    const int n0   = blockIdx.x * 128;

    const int lrow = tid >> 2;
    const int lcf  = (tid & 3) * 8;

    auto issue = [&](int s, int kt) {
        const int k0 = kt * 32;
        const uint32_t so = smb + s * GSTG;
        const uint32_t ro = (uint32_t)(lrow * SKS + lcf) * 2;
        const size_t ga = (size_t)(m0 + lrow) * K + k0 + lcf;
        const size_t gb = (size_t)(n0 + lrow) * K + k0 + lcf;
        cp16(so + ro,             job.A1 + ga);
        if (t2) cp16(so + ARR_B + ro, job.A2 + ga);
        cp16(so + 2 * ARR_B + ro, job.B1 + gb);
        if (t3) cp16(so + 3 * ARR_B + ro, job.B2 + gb);
    };

    float c[2][4][4];
#pragma unroll
    for (int i = 0; i < 2; i++)
#pragma unroll
        for (int j = 0; j < 4; j++)
#pragma unroll
            for (int l = 0; l < 4; l++) c[i][j][l] = 0.f;

    const int nk = K / 32;
    issue(0, 0); CP_COMMIT();
    issue(1, 1); CP_COMMIT();

    const int arow = lane & 15;
    const int acol = (lane >> 4) << 3;

    for (int kt = 0; kt < nk; kt++) {
        if (kt + 2 < nk) issue((kt + 2) % NSTAGE, kt + 2);
        CP_COMMIT();
        CP_WAIT2();
        __syncthreads();
        const uint32_t so = smb + (kt % NSTAGE) * GSTG;

#pragma unroll
        for (int kb = 0; kb < 32; kb += 16) {
            const uint32_t koff = (uint32_t)(kb + acol) * 2;
            uint32_t a1f[2][4], a2f[2][4];
#pragma unroll
            for (int mt = 0; mt < 2; mt++) {
                uint32_t ad = so + (uint32_t)((wm * 32 + mt * 16 + arow) * SKS) * 2 + koff;
                LDSM4(a1f[mt][0], a1f[mt][1], a1f[mt][2], a1f[mt][3], ad);
                if (t2)
                    LDSM4(a2f[mt][0], a2f[mt][1], a2f[mt][2], a2f[mt][3], ad + ARR_B);
            }
            uint32_t b1f[2][4], b2f[2][4];
#pragma unroll
            for (int p = 0; p < 2; p++) {
                uint32_t bd = so + 2 * ARR_B +
                              (uint32_t)((wn * 32 + p * 16 + arow) * SKS) * 2 + koff;
                LDSM4(b1f[p][0], b1f[p][1], b1f[p][2], b1f[p][3], bd);
                if (t3)
                    LDSM4(b2f[p][0], b2f[p][1], b2f[p][2], b2f[p][3], bd + ARR_B);
            }
#pragma unroll
            for (int mt = 0; mt < 2; mt++)
#pragma unroll
                for (int nt = 0; nt < 4; nt++) {
                    const int p = nt >> 1, q = nt & 1;
                    MMA_F16(c[mt][nt], a1f[mt], b1f[p][q], b1f[p][q + 2]);
                    if (t2)
                        MMA_F16(c[mt][nt], a2f[mt], b1f[p][q], b1f[p][q + 2]);
                    if (t3)
                        MMA_F16(c[mt][nt], a1f[mt], b2f[p][q], b2f[p][q + 2]);
                }
        }
        __syncthreads();
    }

#pragma unroll
    for (int mt = 0; mt < 2; mt++) {
        int row = m0 + wm * 32 + mt * 16 + gid;
#pragma unroll
        for (int nt = 0; nt < 4; nt++) {
            int col = n0 + wn * 32 + nt * 8 + tig * 2;
            float b0 = job.bias[col], b1 = job.bias[col + 1];
            float v00 = (c[mt][nt][0] + b0) * job.alpha;
            float v01 = (c[mt][nt][1] + b1) * job.alpha;
            float v10 = (c[mt][nt][2] + b0) * job.alpha;
            float v11 = (c[mt][nt][3] + b1) * job.alpha;
            if (job.split_out == 1) {
                ushort2 h0, l0, h1, l1;
                split1h(v00, h0.x, l0.x); split1h(v01, h0.y, l0.y);
                split1h(v10, h1.x, l1.x); split1h(v11, h1.y, l1.y);
                *(ushort2*)(job.C1 + (size_t)row * N + col)       = h0;
                *(ushort2*)(job.C2 + (size_t)row * N + col)       = l0;
                *(ushort2*)(job.C1 + (size_t)(row + 8) * N + col) = h1;
                *(ushort2*)(job.C2 + (size_t)(row + 8) * N + col) = l1;
            } else if (job.split_out == 2) {
                ushort2 h0, h1;
                h0.x = __half_as_ushort(__float2half_rn(v00));
                h0.y = __half_as_ushort(__float2half_rn(v01));
                h1.x = __half_as_ushort(__float2half_rn(v10));
                h1.y = __half_as_ushort(__float2half_rn(v11));
                *(ushort2*)(job.C1 + (size_t)row * N + col)       = h0;
                *(ushort2*)(job.C1 + (size_t)(row + 8) * N + col) = h1;
            } else {
                float2 o0 = {v00, v01}, o1 = {v10, v11};
                *(float2*)(job.C + (size_t)row * N + col)       = o0;
                *(float2*)(job.C + (size_t)(row + 8) * N + col) = o1;
            }
        }
    }
}

// ================================================================
// Projection MMA, fused K/V+batch. Per-job terms (3 for K, 2 for V).
// C[b][m][n] = sum_s ET[m][s] * X[b][s][n] + bias[m]
// grid (EMB/128, PROJK/64, 8): z>>2 = job, z&3 = batch
// ================================================================
#define PA_B (64 * SKS * 2)
#define PB_RS 272
#define PB_B (32 * PB_RS)
#define PSTG (2 * PA_B + 2 * PB_B)

struct PJob { const ushort_t *A1, *A2, *B1, *B2; const float* bias; float* C; int terms; };
struct PJobs { PJob j[2]; };

__global__ __launch_bounds__(256)
void proj_mma7(PJobs jobs)
{
    extern __shared__ unsigned char smraw[];
    const uint32_t smb = (uint32_t)__cvta_generic_to_shared(smraw);

    const int tid  = threadIdx.x;
    const int wid  = tid >> 5;
    const int lane = tid & 31;
    const int gid  = lane >> 2;
    const int tig  = lane & 3;
    const int wm   = wid >> 2;
    const int wn   = wid & 3;
    const int sel  = blockIdx.z >> 2;
    const int b    = blockIdx.z & 3;
    const int m0   = blockIdx.y * 64;
    const int n0   = blockIdx.x * 128;

    const PJob job = jobs.j[sel];
    const bool t3 = (job.terms == 3);
    const ushort_t* Xb1 = job.B1 + (size_t)b * SEQ * EMB;
    const ushort_t* Xb2 = job.B2 + (size_t)b * SEQ * EMB;

    auto issue = [&](int s, int kt) {
        const int k0 = kt * 32;
        const uint32_t so = smb + s * PSTG;
        {
            int row = tid >> 2, cf = (tid & 3);
            uint32_t sa = so + (uint32_t)(row * SKS) * 2 + cf * 16;
            size_t ga = (size_t)(m0 + row) * SEQ + k0 + cf * 8;
            cp16(sa,        job.A1 + ga);
            cp16(sa + PA_B, job.A2 + ga);
        }
#pragma unroll
        for (int half = 0; half < 2; half++) {
            int cidx = half * 256 + tid;
            int row = cidx >> 4, cf = cidx & 15;
            uint32_t sb = so + 2 * PA_B + (uint32_t)(row * PB_RS) + cf * 16;
            size_t gb = (size_t)(k0 + row) * EMB + n0 + cf * 8;
            cp16(sb, Xb1 + gb);
            if (t3) cp16(sb + PB_B, Xb2 + gb);
        }
    };

    float c[2][4][4];
#pragma unroll
    for (int i = 0; i < 2; i++)
#pragma unroll
        for (int j = 0; j < 4; j++)
#pragma unroll
            for (int l = 0; l < 4; l++) c[i][j][l] = 0.f;

    const int nk = SEQ / 32;
    issue(0, 0); CP_COMMIT();
    issue(1, 1); CP_COMMIT();

    const int arow = lane & 15;
    const int acol = (lane >> 4) << 3;

    for (int kt = 0; kt < nk; kt++) {
        if (kt + 2 < nk) issue((kt + 2) % NSTAGE, kt + 2);
        CP_COMMIT();
        CP_WAIT2();
        __syncthreads();
        const uint32_t so = smb + (kt % NSTAGE) * PSTG;

#pragma unroll
        for (int kb = 0; kb < 32; kb += 16) {
            uint32_t a1f[2][4], a2f[2][4];
#pragma unroll
            for (int mt = 0; mt < 2; mt++) {
                uint32_t ad = so + (uint32_t)((wm * 32 + mt * 16 + arow) * SKS) * 2
                              + (uint32_t)(kb + acol) * 2;
                LDSM4(a1f[mt][0], a1f[mt][1], a1f[mt][2], a1f[mt][3], ad);
                LDSM4(a2f[mt][0], a2f[mt][1], a2f[mt][2], a2f[mt][3], ad + PA_B);
            }
            uint32_t b1f[2][4], b2f[2][4];
#pragma unroll
            for (int p = 0; p < 2; p++) {
                uint32_t bd = so + 2 * PA_B
                              + (uint32_t)((kb + (lane & 15)) * PB_RS)
                              + (uint32_t)(wn * 32 + p * 16 + ((lane >> 4) << 3)) * 2;
                LDSM4T(b1f[p][0], b1f[p][1], b1f[p][2], b1f[p][3], bd);
                if (t3)
                    LDSM4T(b2f[p][0], b2f[p][1], b2f[p][2], b2f[p][3], bd + PB_B);
            }
#pragma unroll
            for (int mt = 0; mt < 2; mt++)
#pragma unroll
                for (int nt = 0; nt < 4; nt++) {
                    const int p = nt >> 1, q = (nt & 1) * 2;
                    MMA_F16(c[mt][nt], a1f[mt], b1f[p][q], b1f[p][q + 1]);
                    MMA_F16(c[mt][nt], a2f[mt], b1f[p][q], b1f[p][q + 1]);
                    if (t3)
                        MMA_F16(c[mt][nt], a1f[mt], b2f[p][q], b2f[p][q + 1]);
                }
        }
        __syncthreads();
    }

#pragma unroll
    for (int mt = 0; mt < 2; mt++) {
        int row = m0 + wm * 32 + mt * 16 + gid;
        float br0 = job.bias[row], br8 = job.bias[row + 8];
#pragma unroll
        for (int nt = 0; nt < 4; nt++) {
            int col = n0 + wn * 32 + nt * 8 + tig * 2;
            float2 o0 = {c[mt][nt][0] + br0, c[mt][nt][1] + br0};
            float2 o1 = {c[mt][nt][2] + br8, c[mt][nt][3] + br8};
            *(float2*)(job.C + ((size_t)b * PROJK + row) * EMB + col)     = o0;
            *(float2*)(job.C + ((size_t)b * PROJK + row + 8) * EMB + col) = o1;
        }
    }
}

// ================================================================
// Fused attention v2 — output single fp16 (ctx_1 only)
// ================================================================
#define KST 68
#define VTST 260
#define SM_K    0
#define SM_VT   (256 * KST)
#define SM_QV   (SM_VT + 64 * VTST)
#define ATTN_FLOATS (SM_QV + 8 * 2048)

__global__ __launch_bounds__(256)
void attn_kernel2(const float* __restrict__ q,
                  const float* __restrict__ kproj,
                  const float* __restrict__ vproj,
                  ushort_t* __restrict__ ctx_1)
{
    extern __shared__ float sm[];
    float* sk  = sm + SM_K;
    float* svT = sm + SM_VT;
    float* sq  = sm + SM_QV;
    float* smyp = sm + SM_QV;

    const int b    = blockIdx.z;
    const int h    = blockIdx.y;
    const int s0   = blockIdx.x * 64;
    const int tid  = threadIdx.x;
    const int w    = tid >> 5;
    const int lane = tid & 31;

    const float* kpB = kproj + ((size_t)b * PROJK) * EMB + h * KDIM;
    const float* vpB = vproj + ((size_t)b * PROJK) * EMB + h * KDIM;
    const float* qB  = q + ((size_t)(b * SEQ + s0)) * EMB + h * KDIM;

    for (int i = tid; i < 256 * 16; i += 256) {
        int kp = i >> 4, d4 = (i & 15) * 4;
        float4 kv4 = *(const float4*)(kpB + (size_t)kp * EMB + d4);
        *(float4*)(sk + kp * KST + d4) = kv4;
        float4 vv4 = *(const float4*)(vpB + (size_t)kp * EMB + d4);
        svT[(d4 + 0) * VTST + kp] = vv4.x;
        svT[(d4 + 1) * VTST + kp] = vv4.y;
        svT[(d4 + 2) * VTST + kp] = vv4.z;
        svT[(d4 + 3) * VTST + kp] = vv4.w;
    }
    for (int i = tid; i < 64 * 16; i += 256) {
        int r = i >> 4, d4 = (i & 15) * 4;
        *(float4*)(sq + r * 64 + d4) = *(const float4*)(qB + (size_t)r * EMB + d4);
    }
    __syncthreads();

    const int rbase = w * 8;

    float s[8][8];
#pragma unroll
    for (int r = 0; r < 8; r++)
#pragma unroll
        for (int j = 0; j < 8; j++) s[r][j] = 0.f;

#pragma unroll 2
    for (int d4 = 0; d4 < 64; d4 += 4) {
        float4 kv[8];
#pragma unroll
        for (int j = 0; j < 8; j++)
            kv[j] = *(float4*)(sk + (lane + 32 * j) * KST + d4);
#pragma unroll
        for (int r = 0; r < 8; r++) {
            float4 q4 = *(float4*)(sq + (rbase + r) * 64 + d4);
#pragma unroll
            for (int j = 0; j < 8; j++) {
                s[r][j] = fmaf(q4.x, kv[j].x, s[r][j]);
                s[r][j] = fmaf(q4.y, kv[j].y, s[r][j]);
                s[r][j] = fmaf(q4.z, kv[j].z, s[r][j]);
                s[r][j] = fmaf(q4.w, kv[j].w, s[r][j]);
            }
        }
    }
    __syncthreads();

    float* myp = smyp + w * 2048;
    float inv[8];
#pragma unroll
    for (int r = 0; r < 8; r++) {
        float m = s[r][0];
#pragma unroll
        for (int j = 1; j < 8; j++) m = fmaxf(m, s[r][j]);
#pragma unroll
        for (int o = 16; o > 0; o >>= 1)
            m = fmaxf(m, __shfl_xor_sync(0xFFFFFFFFu, m, o));
        float sum = 0.f;
#pragma unroll
        for (int j = 0; j < 8; j++) {
            s[r][j] = __expf(s[r][j] - m);
            sum += s[r][j];
        }
#pragma unroll
        for (int o = 16; o > 0; o >>= 1)
            sum += __shfl_xor_sync(0xFFFFFFFFu, sum, o);
        inv[r] = 1.f / sum;
#pragma unroll
        for (int j = 0; j < 8; j++)
            myp[r * 256 + lane + 32 * j] = s[r][j];
    }
    __syncwarp();

    float acc[8][2];
#pragma unroll
    for (int r = 0; r < 8; r++) { acc[r][0] = 0.f; acc[r][1] = 0.f; }

    const float* vA = svT + lane * VTST;
    const float* vB = svT + (lane + 32) * VTST;
#pragma unroll 2
    for (int kp4 = 0; kp4 < 256; kp4 += 4) {
        float4 va = *(const float4*)(vA + kp4);
        float4 vb = *(const float4*)(vB + kp4);
#pragma unroll
        for (int r = 0; r < 8; r++) {
            float4 p4 = *(const float4*)(myp + r * 256 + kp4);
            acc[r][0] = fmaf(p4.x, va.x, acc[r][0]);
            acc[r][0] = fmaf(p4.y, va.y, acc[r][0]);
            acc[r][0] = fmaf(p4.z, va.z, acc[r][0]);
            acc[r][0] = fmaf(p4.w, va.w, acc[r][0]);
            acc[r][1] = fmaf(p4.x, vb.x, acc[r][1]);
            acc[r][1] = fmaf(p4.y, vb.y, acc[r][1]);
            acc[r][1] = fmaf(p4.z, vb.z, acc[r][1]);
            acc[r][1] = fmaf(p4.w, vb.w, acc[r][1]);
        }
    }

#pragma unroll
    for (int r = 0; r < 8; r++) {
        size_t row = (size_t)(b * SEQ + s0 + rbase + r);
        size_t base = row * EMB + h * KDIM;
        ctx_1[base + lane]      = __half_as_ushort(__float2half_rn(acc[r][0] * inv[r]));
        ctx_1[base + lane + 32] = __half_as_ushort(__float2half_rn(acc[r][1] * inv[r]));
    }
}

// ================================================================
// Launch
// ================================================================
extern "C" void kernel_launch(void* const* d_in, const int* in_sizes, int n_in,
                              void* d_out, int out_size)
{
    const float* query = (const float*)d_in[0];
    const float* value = (const float*)d_in[1];
    const float* Wq    = (const float*)d_in[2];
    const float* bq    = (const float*)d_in[3];
    const float* Wk    = (const float*)d_in[4];
    const float* bk    = (const float*)d_in[5];
    const float* Wv    = (const float*)d_in[6];
    const float* bv    = (const float*)d_in[7];
    const float* Wo    = (const float*)d_in[8];
    const float* bo    = (const float*)d_in[9];
    const float* E     = (const float*)d_in[10];
    const float* Eb    = (const float*)d_in[11];
    const float* F     = (const float*)d_in[12];
    const float* Fb    = (const float*)d_in[13];
    float* out = (float*)d_out;

    float *gq, *gkp, *gvp;
    ushort_t *qa1, *qa2, *va1, *va2, *ct1;
    ushort_t *kb1, *kb2, *vb1;
    ushort_t *wq1, *wq2, *wk1, *wk2, *wv1, *wv2, *wo1, *wo2;
    ushort_t *et1, *et2, *ft1, *ft2;
    cudaGetSymbolAddress((void**)&gq,  g_q);
    cudaGetSymbolAddress((void**)&gkp, g_kp);
    cudaGetSymbolAddress((void**)&gvp, g_vp);
    cudaGetSymbolAddress((void**)&qa1, g_qA_1);
    cudaGetSymbolAddress((void**)&qa2, g_qA_2);
    cudaGetSymbolAddress((void**)&va1, g_vA_1);
    cudaGetSymbolAddress((void**)&va2, g_vA_2);
    cudaGetSymbolAddress((void**)&ct1, g_ctx_1);
    cudaGetSymbolAddress((void**)&kb1, g_kb_1);
    cudaGetSymbolAddress((void**)&kb2, g_kb_2);
    cudaGetSymbolAddress((void**)&vb1, g_vb_1);
    cudaGetSymbolAddress((void**)&wq1, g_wqT_1);
    cudaGetSymbolAddress((void**)&wq2, g_wqT_2);
    cudaGetSymbolAddress((void**)&wk1, g_wkT_1);
    cudaGetSymbolAddress((void**)&wk2, g_wkT_2);
    cudaGetSymbolAddress((void**)&wv1, g_wvT_1);
    cudaGetSymbolAddress((void**)&wv2, g_wvT_2);
    cudaGetSymbolAddress((void**)&wo1, g_woT_1);
    cudaGetSymbolAddress((void**)&wo2, g_woT_2);
    cudaGetSymbolAddress((void**)&et1, g_ET1);
    cudaGetSymbolAddress((void**)&et2, g_ET2);
    cudaGetSymbolAddress((void**)&ft1, g_FT1);
    cudaGetSymbolAddress((void**)&ft2, g_FT2);

    const float scale = 1.0f / 8.0f;
    const int nbig = MROWS * EMB;

    // splits
    split_kernel<<<nbig / 1024, 256>>>(query, qa1, qa2, nbig);
    split_kernel<<<nbig / 1024, 256>>>(value, va1, va2, nbig);

    // batched transposes
    TransJobs wjobs;
    wjobs.j[0] = {Wq, wq1, wq2};
    wjobs.j[1] = {Wk, wk1, wk2};
    wjobs.j[2] = {Wv, wv1, wv2};
    wjobs.j[3] = {Wo, wo1, wo2};
    dim3 tb(32, 8);
    split_transpose_b<<<dim3(EMB / 32, EMB / 32, 4), tb>>>(wjobs, EMB, EMB);

    TransJobs ejobs;
    ejobs.j[0] = {E, et1, et2};
    ejobs.j[1] = {F, ft1, ft2};
    ejobs.j[2] = {E, et1, et2};
    ejobs.j[3] = {F, ft1, ft2};
    split_transpose_b<<<dim3(PROJK / 32, SEQ / 32, 2), tb>>>(ejobs, SEQ, PROJK);

    // fused Q+K+V GEMM: Q,K 3-term (amplified path); V 1-term (linear path)
    GJobs qkv;
    qkv.j[0] = {qa1, qa2, wq1, wq2, bq, gq, 0, 0, scale, 0, 3};
    qkv.j[1] = {va1, va2, wk1, wk2, bk, 0, kb1, kb2, 1.0f, 1, 3};
    qkv.j[2] = {va1, va2, wv1, wv2, bv, 0, vb1, 0,  1.0f, 2, 1};
    cudaFuncSetAttribute(mma_gemm7, cudaFuncAttributeMaxDynamicSharedMemorySize, NSTAGE * GSTG);
    dim3 g_qkv(EMB / 128, MROWS / 128, 3);
    mma_gemm7<<<g_qkv, 512, NSTAGE * GSTG>>>(qkv, EMB, EMB);

    // fused projections: K 3-term (amplified), V 2-term (linear)
    PJobs pj;
    pj.j[0] = {et1, et2, kb1, kb2, Eb, gkp, 3};
    pj.j[1] = {ft1, ft2, vb1, 0,   Fb, gvp, 2};
    cudaFuncSetAttribute(proj_mma7, cudaFuncAttributeMaxDynamicSharedMemorySize, NSTAGE * PSTG);
    dim3 g_proj(EMB / 128, PROJK / 64, 8);
    proj_mma7<<<g_proj, 256, NSTAGE * PSTG>>>(pj);

    // fused attention (ctx -> single fp16)
    size_t attn_smem = (size_t)ATTN_FLOATS * sizeof(float);
    cudaFuncSetAttribute(attn_kernel2, cudaFuncAttributeMaxDynamicSharedMemorySize, (int)attn_smem);
    dim3 attn_grid(SEQ / 64, HEADS, BATCH);
    attn_kernel2<<<attn_grid, 256, attn_smem>>>(gq, gkp, gvp, ct1);

    // output projection: 1-term fp16 (post-softmax linear path)
    GJobs oj;
    oj.j[0] = {ct1, ct1, wo1, wo2, bo, out, 0, 0, 1.0f, 0, 1};
    oj.j[1] = oj.j[0];
    oj.j[2] = oj.j[0];
    dim3 g_out(EMB / 128, MROWS / 128, 1);
    mma_gemm7<<<g_out, 512, NSTAGE * GSTG>>>(oj, EMB, EMB);
}

// round 17
// speedup vs baseline: 3.2732x; 1.2254x over previous
#include <cuda_runtime.h>
#include <cuda_fp16.h>
#include <math.h>
#include <stdint.h>

// Problem constants
#define BATCH 4
#define SEQ   2048
#define EMB   1024     // H * Dk
#define HEADS 16
#define KDIM  64
#define PROJK 256
#define MROWS (BATCH * SEQ)   // 8192

typedef unsigned short ushort_t;

// ---------------- scratch (allocation-free) ----------------
__device__ float g_q [MROWS * EMB];           // hosts qo1+qo2 halves (32MB)
__device__ float g_kp[BATCH * PROJK * EMB];   // hosts kp1+kp2 halves (4MB)
__device__ float g_vp[BATCH * PROJK * EMB];   // hosts vp1 halves (2MB used)
__device__ ushort_t g_qA_1[MROWS * EMB], g_qA_2[MROWS * EMB];
__device__ ushort_t g_vA_1[MROWS * EMB], g_vA_2[MROWS * EMB];
__device__ ushort_t g_ctx_1[MROWS * EMB];
__device__ ushort_t g_kb_1[MROWS * EMB], g_kb_2[MROWS * EMB];
__device__ ushort_t g_vb_1[MROWS * EMB];
__device__ ushort_t g_wqT_1[EMB * EMB], g_wqT_2[EMB * EMB];
__device__ ushort_t g_wkT_1[EMB * EMB], g_wkT_2[EMB * EMB];
__device__ ushort_t g_wvT_1[EMB * EMB], g_wvT_2[EMB * EMB];
__device__ ushort_t g_woT_1[EMB * EMB], g_woT_2[EMB * EMB];
__device__ ushort_t g_ET1[PROJK * SEQ], g_ET2[PROJK * SEQ];
__device__ ushort_t g_FT1[PROJK * SEQ], g_FT2[PROJK * SEQ];

// ---------------- helpers ----------------
__device__ __forceinline__ void split1h(float v, ushort_t& h, ushort_t& l) {
    __half a = __float2half_rn(v);
    __half b = __float2half_rn(v - __half2float(a));
    h = __half_as_ushort(a);
    l = __half_as_ushort(b);
}

#define MMA_F16(d, a, b0, b1) asm volatile( \
    "mma.sync.aligned.m16n8k16.row.col.f32.f16.f16.f32 " \
    "{%0,%1,%2,%3}, {%4,%5,%6,%7}, {%8,%9}, {%0,%1,%2,%3};\n" \
    : "+f"((d)[0]), "+f"((d)[1]), "+f"((d)[2]), "+f"((d)[3]) \
    : "r"((a)[0]), "r"((a)[1]), "r"((a)[2]), "r"((a)[3]), \
      "r"(b0), "r"(b1))

#define LDSM4(r0, r1, r2, r3, addr) asm volatile( \
    "ldmatrix.sync.aligned.m8n8.x4.shared.b16 {%0,%1,%2,%3}, [%4];\n" \
    : "=r"(r0), "=r"(r1), "=r"(r2), "=r"(r3) : "r"(addr))

#define LDSM4T(r0, r1, r2, r3, addr) asm volatile( \
    "ldmatrix.sync.aligned.m8n8.x4.trans.shared.b16 {%0,%1,%2,%3}, [%4];\n" \
    : "=r"(r0), "=r"(r1), "=r"(r2), "=r"(r3) : "r"(addr))

__device__ __forceinline__ void cp16(uint32_t dst, const void* src) {
    asm volatile("cp.async.cg.shared.global [%0], [%1], 16;\n" :: "r"(dst), "l"(src));
}
#define CP_COMMIT() asm volatile("cp.async.commit_group;\n" ::: "memory")
#define CP_WAIT0()  asm volatile("cp.async.wait_group 0;\n" ::: "memory")
#define CP_WAIT2()  asm volatile("cp.async.wait_group 2;\n" ::: "memory")

// ================================================================
// split_kernel: fp32 -> fp16 2-term, vectorized
// ================================================================
__global__ __launch_bounds__(256)
void split_kernel(const float* __restrict__ src,
                  ushort_t* __restrict__ h1,
                  ushort_t* __restrict__ h2, int n)
{
    int i = (blockIdx.x * 256 + threadIdx.x) * 4;
    if (i >= n) return;
    float4 v = *(const float4*)(src + i);
    ushort4 a, b;
    split1h(v.x, a.x, b.x);
    split1h(v.y, a.y, b.y);
    split1h(v.z, a.z, b.z);
    split1h(v.w, a.w, b.w);
    *(ushort4*)(h1 + i) = a;
    *(ushort4*)(h2 + i) = b;
}

// ================================================================
// Batched split+transpose: W[K][N] fp32 -> WT[N][K] fp16 2-term
// ================================================================
struct TransJob { const float* W; ushort_t* h1; ushort_t* h2; };
struct TransJobs { TransJob j[4]; };

__global__ __launch_bounds__(256)
void split_transpose_b(TransJobs jobs, int K, int N)
{
    __shared__ float t[32][33];
    const TransJob jb = jobs.j[blockIdx.z];
    int k0 = blockIdx.y * 32, n0 = blockIdx.x * 32;
    int tx = threadIdx.x, ty = threadIdx.y;
#pragma unroll
    for (int i = 0; i < 32; i += 8)
        t[ty + i][tx] = jb.W[(size_t)(k0 + ty + i) * N + n0 + tx];
    __syncthreads();
#pragma unroll
    for (int i = 0; i < 32; i += 8) {
        float v = t[tx][ty + i];
        ushort_t a, b;
        split1h(v, a, b);
        jb.h1[(size_t)(n0 + ty + i) * K + k0 + tx] = a;
        jb.h2[(size_t)(n0 + ty + i) * K + k0 + tx] = b;
    }
}

// ================================================================
// Big GEMM (fp16 split, mma.sync), 512 threads, 16 warps, 32x32 warp.
// terms: 3/2/1 as before. split_out: 0 fp32; 1 C1+C2 split; 2 C1 only.
// ================================================================
#define SKS 40
#define ARR_B (128 * SKS * 2)
#define GSTG (4 * ARR_B)
#define NSTAGE 3

struct GJob {
    const ushort_t *A1, *A2, *B1, *B2;
    const float* bias;
    float* C;
    ushort_t *C1, *C2;
    float alpha;
    int split_out;
    int terms;
};
struct GJobs { GJob j[3]; };

__global__ __launch_bounds__(512)
void mma_gemm7(GJobs jobs, int N, int K)
{
    extern __shared__ unsigned char smraw[];
    const uint32_t smb = (uint32_t)__cvta_generic_to_shared(smraw);

    const GJob job = jobs.j[blockIdx.z];
    const bool t3 = (job.terms == 3);
    const bool t2 = (job.terms >= 2);

    const int tid  = threadIdx.x;
    const int wid  = tid >> 5;
    const int lane = tid & 31;
    const int gid  = lane >> 2;
    const int tig  = lane & 3;
    const int wm   = wid >> 2;
    const int wn   = wid & 3;
    const int m0   = blockIdx.y * 128;
    const int n0   = blockIdx.x * 128;

    const int lrow = tid >> 2;
    const int lcf  = (tid & 3) * 8;

    auto issue = [&](int s, int kt) {
        const int k0 = kt * 32;
        const uint32_t so = smb + s * GSTG;
        const uint32_t ro = (uint32_t)(lrow * SKS + lcf) * 2;
        const size_t ga = (size_t)(m0 + lrow) * K + k0 + lcf;
        const size_t gb = (size_t)(n0 + lrow) * K + k0 + lcf;
        cp16(so + ro,             job.A1 + ga);
        if (t2) cp16(so + ARR_B + ro, job.A2 + ga);
        cp16(so + 2 * ARR_B + ro, job.B1 + gb);
        if (t3) cp16(so + 3 * ARR_B + ro, job.B2 + gb);
    };

    float c[2][4][4];
#pragma unroll
    for (int i = 0; i < 2; i++)
#pragma unroll
        for (int j = 0; j < 4; j++)
#pragma unroll
            for (int l = 0; l < 4; l++) c[i][j][l] = 0.f;

    const int nk = K / 32;
    issue(0, 0); CP_COMMIT();
    issue(1, 1); CP_COMMIT();

    const int arow = lane & 15;
    const int acol = (lane >> 4) << 3;

    for (int kt = 0; kt < nk; kt++) {
        if (kt + 2 < nk) issue((kt + 2) % NSTAGE, kt + 2);
        CP_COMMIT();
        CP_WAIT2();
        __syncthreads();
        const uint32_t so = smb + (kt % NSTAGE) * GSTG;

#pragma unroll
        for (int kb = 0; kb < 32; kb += 16) {
            const uint32_t koff = (uint32_t)(kb + acol) * 2;
            uint32_t a1f[2][4], a2f[2][4];
#pragma unroll
            for (int mt = 0; mt < 2; mt++) {
                uint32_t ad = so + (uint32_t)((wm * 32 + mt * 16 + arow) * SKS) * 2 + koff;
                LDSM4(a1f[mt][0], a1f[mt][1], a1f[mt][2], a1f[mt][3], ad);
                if (t2)
                    LDSM4(a2f[mt][0], a2f[mt][1], a2f[mt][2], a2f[mt][3], ad + ARR_B);
            }
            uint32_t b1f[2][4], b2f[2][4];
#pragma unroll
            for (int p = 0; p < 2; p++) {
                uint32_t bd = so + 2 * ARR_B +
                              (uint32_t)((wn * 32 + p * 16 + arow) * SKS) * 2 + koff;
                LDSM4(b1f[p][0], b1f[p][1], b1f[p][2], b1f[p][3], bd);
                if (t3)
                    LDSM4(b2f[p][0], b2f[p][1], b2f[p][2], b2f[p][3], bd + ARR_B);
            }
#pragma unroll
            for (int mt = 0; mt < 2; mt++)
#pragma unroll
                for (int nt = 0; nt < 4; nt++) {
                    const int p = nt >> 1, q = nt & 1;
                    MMA_F16(c[mt][nt], a1f[mt], b1f[p][q], b1f[p][q + 2]);
                    if (t2)
                        MMA_F16(c[mt][nt], a2f[mt], b1f[p][q], b1f[p][q + 2]);
                    if (t3)
                        MMA_F16(c[mt][nt], a1f[mt], b2f[p][q], b2f[p][q + 2]);
                }
        }
        __syncthreads();
    }

#pragma unroll
    for (int mt = 0; mt < 2; mt++) {
        int row = m0 + wm * 32 + mt * 16 + gid;
#pragma unroll
        for (int nt = 0; nt < 4; nt++) {
            int col = n0 + wn * 32 + nt * 8 + tig * 2;
            float b0 = job.bias[col], b1 = job.bias[col + 1];
            float v00 = (c[mt][nt][0] + b0) * job.alpha;
            float v01 = (c[mt][nt][1] + b1) * job.alpha;
            float v10 = (c[mt][nt][2] + b0) * job.alpha;
            float v11 = (c[mt][nt][3] + b1) * job.alpha;
            if (job.split_out == 1) {
                ushort2 h0, l0, h1, l1;
                split1h(v00, h0.x, l0.x); split1h(v01, h0.y, l0.y);
                split1h(v10, h1.x, l1.x); split1h(v11, h1.y, l1.y);
                *(ushort2*)(job.C1 + (size_t)row * N + col)       = h0;
                *(ushort2*)(job.C2 + (size_t)row * N + col)       = l0;
                *(ushort2*)(job.C1 + (size_t)(row + 8) * N + col) = h1;
                *(ushort2*)(job.C2 + (size_t)(row + 8) * N + col) = l1;
            } else if (job.split_out == 2) {
                ushort2 h0, h1;
                h0.x = __half_as_ushort(__float2half_rn(v00));
                h0.y = __half_as_ushort(__float2half_rn(v01));
                h1.x = __half_as_ushort(__float2half_rn(v10));
                h1.y = __half_as_ushort(__float2half_rn(v11));
                *(ushort2*)(job.C1 + (size_t)row * N + col)       = h0;
                *(ushort2*)(job.C1 + (size_t)(row + 8) * N + col) = h1;
            } else {
                float2 o0 = {v00, v01}, o1 = {v10, v11};
                *(float2*)(job.C + (size_t)row * N + col)       = o0;
                *(float2*)(job.C + (size_t)(row + 8) * N + col) = o1;
            }
        }
    }
}

// ================================================================
// Projection MMA, fused K/V+batch. Per-job terms + split output.
// split_out: 1 = fp16 2-term (C1,C2); 2 = fp16 single (C1)
// ================================================================
#define PA_B (64 * SKS * 2)
#define PB_RS 272
#define PB_B (32 * PB_RS)
#define PSTG (2 * PA_B + 2 * PB_B)

struct PJob {
    const ushort_t *A1, *A2, *B1, *B2;
    const float* bias;
    ushort_t *C1, *C2;
    int terms;
    int split_out;
};
struct PJobs { PJob j[2]; };

__global__ __launch_bounds__(256)
void proj_mma7(PJobs jobs)
{
    extern __shared__ unsigned char smraw[];
    const uint32_t smb = (uint32_t)__cvta_generic_to_shared(smraw);

    const int tid  = threadIdx.x;
    const int wid  = tid >> 5;
    const int lane = tid & 31;
    const int gid  = lane >> 2;
    const int tig  = lane & 3;
    const int wm   = wid >> 2;
    const int wn   = wid & 3;
    const int sel  = blockIdx.z >> 2;
    const int b    = blockIdx.z & 3;
    const int m0   = blockIdx.y * 64;
    const int n0   = blockIdx.x * 128;

    const PJob job = jobs.j[sel];
    const bool t3 = (job.terms == 3);
    const ushort_t* Xb1 = job.B1 + (size_t)b * SEQ * EMB;
    const ushort_t* Xb2 = job.B2 + (size_t)b * SEQ * EMB;

    auto issue = [&](int s, int kt) {
        const int k0 = kt * 32;
        const uint32_t so = smb + s * PSTG;
        {
            int row = tid >> 2, cf = (tid & 3);
            uint32_t sa = so + (uint32_t)(row * SKS) * 2 + cf * 16;
            size_t ga = (size_t)(m0 + row) * SEQ + k0 + cf * 8;
            cp16(sa,        job.A1 + ga);
            cp16(sa + PA_B, job.A2 + ga);
        }
#pragma unroll
        for (int half = 0; half < 2; half++) {
            int cidx = half * 256 + tid;
            int row = cidx >> 4, cf = cidx & 15;
            uint32_t sb = so + 2 * PA_B + (uint32_t)(row * PB_RS) + cf * 16;
            size_t gb = (size_t)(k0 + row) * EMB + n0 + cf * 8;
            cp16(sb, Xb1 + gb);
            if (t3) cp16(sb + PB_B, Xb2 + gb);
        }
    };

    float c[2][4][4];
#pragma unroll
    for (int i = 0; i < 2; i++)
#pragma unroll
        for (int j = 0; j < 4; j++)
#pragma unroll
            for (int l = 0; l < 4; l++) c[i][j][l] = 0.f;

    const int nk = SEQ / 32;
    issue(0, 0); CP_COMMIT();
    issue(1, 1); CP_COMMIT();

    const int arow = lane & 15;
    const int acol = (lane >> 4) << 3;

    for (int kt = 0; kt < nk; kt++) {
        if (kt + 2 < nk) issue((kt + 2) % NSTAGE, kt + 2);
        CP_COMMIT();
        CP_WAIT2();
        __syncthreads();
        const uint32_t so = smb + (kt % NSTAGE) * PSTG;

#pragma unroll
        for (int kb = 0; kb < 32; kb += 16) {
            uint32_t a1f[2][4], a2f[2][4];
#pragma unroll
            for (int mt = 0; mt < 2; mt++) {
                uint32_t ad = so + (uint32_t)((wm * 32 + mt * 16 + arow) * SKS) * 2
                              + (uint32_t)(kb + acol) * 2;
                LDSM4(a1f[mt][0], a1f[mt][1], a1f[mt][2], a1f[mt][3], ad);
                LDSM4(a2f[mt][0], a2f[mt][1], a2f[mt][2], a2f[mt][3], ad + PA_B);
            }
            uint32_t b1f[2][4], b2f[2][4];
#pragma unroll
            for (int p = 0; p < 2; p++) {
                uint32_t bd = so + 2 * PA_B
                              + (uint32_t)((kb + (lane & 15)) * PB_RS)
                              + (uint32_t)(wn * 32 + p * 16 + ((lane >> 4) << 3)) * 2;
                LDSM4T(b1f[p][0], b1f[p][1], b1f[p][2], b1f[p][3], bd);
                if (t3)
                    LDSM4T(b2f[p][0], b2f[p][1], b2f[p][2], b2f[p][3], bd + PB_B);
            }
#pragma unroll
            for (int mt = 0; mt < 2; mt++)
#pragma unroll
                for (int nt = 0; nt < 4; nt++) {
                    const int p = nt >> 1, q = (nt & 1) * 2;
                    MMA_F16(c[mt][nt], a1f[mt], b1f[p][q], b1f[p][q + 1]);
                    MMA_F16(c[mt][nt], a2f[mt], b1f[p][q], b1f[p][q + 1]);
                    if (t3)
                        MMA_F16(c[mt][nt], a1f[mt], b2f[p][q], b2f[p][q + 1]);
                }
        }
        __syncthreads();
    }

#pragma unroll
    for (int mt = 0; mt < 2; mt++) {
        int row = m0 + wm * 32 + mt * 16 + gid;
        float br0 = job.bias[row], br8 = job.bias[row + 8];
#pragma unroll
        for (int nt = 0; nt < 4; nt++) {
            int col = n0 + wn * 32 + nt * 8 + tig * 2;
            float v00 = c[mt][nt][0] + br0, v01 = c[mt][nt][1] + br0;
            float v10 = c[mt][nt][2] + br8, v11 = c[mt][nt][3] + br8;
            size_t o0 = ((size_t)b * PROJK + row) * EMB + col;
            size_t o1 = ((size_t)b * PROJK + row + 8) * EMB + col;
            if (job.split_out == 1) {
                ushort2 h0, l0, h1, l1;
                split1h(v00, h0.x, l0.x); split1h(v01, h0.y, l0.y);
                split1h(v10, h1.x, l1.x); split1h(v11, h1.y, l1.y);
                *(ushort2*)(job.C1 + o0) = h0;
                *(ushort2*)(job.C2 + o0) = l0;
                *(ushort2*)(job.C1 + o1) = h1;
                *(ushort2*)(job.C2 + o1) = l1;
            } else {
                ushort2 h0, h1;
                h0.x = __half_as_ushort(__float2half_rn(v00));
                h0.y = __half_as_ushort(__float2half_rn(v01));
                h1.x = __half_as_ushort(__float2half_rn(v10));
                h1.y = __half_as_ushort(__float2half_rn(v11));
                *(ushort2*)(job.C1 + o0) = h0;
                *(ushort2*)(job.C1 + o1) = h1;
            }
        }
    }
}

// ================================================================
// Tensor-core attention: scores 3-term fp16 mma, fp32 softmax,
// ctx 1-term fp16 mma. 256 threads / 8 warps, 1 CTA per (b,h,s64).
// smem halves tiles stride AST=72 (144B rows, ldmatrix-safe);
// p tile stride 264 halves (528B, ldmatrix-safe).
// ================================================================
#define AST 72
#define PST 264
#define SQ1H 0
#define SQ2H 4608
#define SK1H 9216
#define SK2H 27648
#define SVH  46080
#define SPH  64512
#define HALVES_TOT (SPH + 64 * PST)          // 81408 halves
#define REDMAX_B (HALVES_TOT * 2)            // 162816
#define REDSUM_B (REDMAX_B + 256 * 4)
#define RINV_B   (REDSUM_B + 256 * 4)
#define ATTN_SMEM (RINV_B + 64 * 4)          // 165120 bytes

__global__ __launch_bounds__(256)
void attn_mma(const ushort_t* __restrict__ q1g,
              const ushort_t* __restrict__ q2g,
              const ushort_t* __restrict__ k1g,
              const ushort_t* __restrict__ k2g,
              const ushort_t* __restrict__ v1g,
              ushort_t* __restrict__ ctx_1)
{
    extern __shared__ __align__(16) unsigned char smraw[];
    const uint32_t smb = (uint32_t)__cvta_generic_to_shared(smraw);
    float* redmax = (float*)(smraw + REDMAX_B);   // [64][4]
    float* redsum = (float*)(smraw + REDSUM_B);   // [64][4]
    float* rinv   = (float*)(smraw + RINV_B);     // [64]

    const int b    = blockIdx.z;
    const int h    = blockIdx.y;
    const int s0   = blockIdx.x * 64;
    const int tid  = threadIdx.x;
    const int wid  = tid >> 5;
    const int lane = tid & 31;
    const int gid  = lane >> 2;
    const int tig  = lane & 3;
    const int arow = lane & 15;
    const int acol = (lane >> 4) << 3;

    // ---- load q (2 arrays, 64 rows), k (2 arrays, 256 rows), v (256 rows) ----
    {
        const size_t qbase = (size_t)(b * SEQ + s0) * EMB + h * KDIM;
#pragma unroll
        for (int i = 0; i < 2; i++) {
            int idx = i * 256 + tid;          // 0..511
            int row = idx >> 3, cf = (idx & 7) * 8;
            uint32_t dof = (uint32_t)(row * AST + cf) * 2;
            cp16(smb + SQ1H * 2 + dof, q1g + qbase + (size_t)row * EMB + cf);
            cp16(smb + SQ2H * 2 + dof, q2g + qbase + (size_t)row * EMB + cf);
        }
        const size_t kvbase = ((size_t)b * PROJK) * EMB + h * KDIM;
#pragma unroll
        for (int i = 0; i < 8; i++) {
            int idx = i * 256 + tid;          // 0..2047
            int row = idx >> 3, cf = (idx & 7) * 8;
            uint32_t dof = (uint32_t)(row * AST + cf) * 2;
            size_t g = kvbase + (size_t)row * EMB + cf;
            cp16(smb + SK1H * 2 + dof, k1g + g);
            cp16(smb + SK2H * 2 + dof, k2g + g);
            cp16(smb + SVH * 2 + dof,  v1g + g);
        }
    }
    CP_COMMIT();
    CP_WAIT0();
    __syncthreads();

    // ================= scores: S[64][256] = q @ k^T (3-term) =================
    // warps: wm(2) x wn(4); warp tile 32m x 64n
    const int wm = wid >> 2;
    const int wn = wid & 3;

    float c[2][8][4];
#pragma unroll
    for (int i = 0; i < 2; i++)
#pragma unroll
        for (int j = 0; j < 8; j++)
#pragma unroll
            for (int l = 0; l < 4; l++) c[i][j][l] = 0.f;

#pragma unroll
    for (int kb = 0; kb < 64; kb += 16) {
        const uint32_t koff = (uint32_t)(kb + acol) * 2;
        uint32_t a1f[2][4], a2f[2][4];
#pragma unroll
        for (int mt = 0; mt < 2; mt++) {
            uint32_t ad = smb + (uint32_t)((SQ1H + (wm * 32 + mt * 16 + arow) * AST) * 2) + koff;
            LDSM4(a1f[mt][0], a1f[mt][1], a1f[mt][2], a1f[mt][3], ad);
            LDSM4(a2f[mt][0], a2f[mt][1], a2f[mt][2], a2f[mt][3],
                  ad + (uint32_t)(SQ2H - SQ1H) * 2);
        }
        uint32_t b1f[4][4], b2f[4][4];
#pragma unroll
        for (int p = 0; p < 4; p++) {
            uint32_t bd = smb + (uint32_t)((SK1H + (wn * 64 + p * 16 + arow) * AST) * 2) + koff;
            LDSM4(b1f[p][0], b1f[p][1], b1f[p][2], b1f[p][3], bd);
            LDSM4(b2f[p][0], b2f[p][1], b2f[p][2], b2f[p][3],
                  bd + (uint32_t)(SK2H - SK1H) * 2);
        }
#pragma unroll
        for (int mt = 0; mt < 2; mt++)
#pragma unroll
            for (int nt = 0; nt < 8; nt++) {
                const int p = nt >> 1, q = nt & 1;
                MMA_F16(c[mt][nt], a1f[mt], b1f[p][q], b1f[p][q + 2]);
                MMA_F16(c[mt][nt], a2f[mt], b1f[p][q], b1f[p][q + 2]);
                MMA_F16(c[mt][nt], a1f[mt], b2f[p][q], b2f[p][q + 2]);
            }
    }

    // ================= softmax (fp32 on fragments) =================
    // rows: r(mt,hh) = wm*32 + mt*16 + gid + hh*8
    float lm[2][2];
#pragma unroll
    for (int mt = 0; mt < 2; mt++) {
        lm[mt][0] = c[mt][0][0];
        lm[mt][1] = c[mt][0][2];
#pragma unroll
        for (int nt = 0; nt < 8; nt++) {
            lm[mt][0] = fmaxf(lm[mt][0], fmaxf(c[mt][nt][0], c[mt][nt][1]));
            lm[mt][1] = fmaxf(lm[mt][1], fmaxf(c[mt][nt][2], c[mt][nt][3]));
        }
#pragma unroll
        for (int o = 1; o <= 2; o <<= 1) {
            lm[mt][0] = fmaxf(lm[mt][0], __shfl_xor_sync(0xFFFFFFFFu, lm[mt][0], o));
            lm[mt][1] = fmaxf(lm[mt][1], __shfl_xor_sync(0xFFFFFFFFu, lm[mt][1], o));
        }
        if (tig == 0) {
            redmax[(wm * 32 + mt * 16 + gid) * 4 + wn]     = lm[mt][0];
            redmax[(wm * 32 + mt * 16 + gid + 8) * 4 + wn] = lm[mt][1];
        }
    }
    __syncthreads();

    float gm[2][2], ls[2][2];
#pragma unroll
    for (int mt = 0; mt < 2; mt++)
#pragma unroll
        for (int hh = 0; hh < 2; hh++) {
            int r = wm * 32 + mt * 16 + gid + hh * 8;
            float m = fmaxf(fmaxf(redmax[r * 4], redmax[r * 4 + 1]),
                            fmaxf(redmax[r * 4 + 2], redmax[r * 4 + 3]));
            gm[mt][hh] = m;
            ls[mt][hh] = 0.f;
        }

    // exp + write p (fp16) + local sums
#pragma unroll
    for (int mt = 0; mt < 2; mt++) {
        int r0 = wm * 32 + mt * 16 + gid;
#pragma unroll
        for (int nt = 0; nt < 8; nt++) {
            int col = wn * 64 + nt * 8 + tig * 2;
            float e0 = __expf(c[mt][nt][0] - gm[mt][0]);
            float e1 = __expf(c[mt][nt][1] - gm[mt][0]);
            float e2 = __expf(c[mt][nt][2] - gm[mt][1]);
            float e3 = __expf(c[mt][nt][3] - gm[mt][1]);
            ls[mt][0] += e0 + e1;
            ls[mt][1] += e2 + e3;
            __half2* p0 = (__half2*)(smraw + (SPH + r0 * PST + col) * 2);
            __half2* p1 = (__half2*)(smraw + (SPH + (r0 + 8) * PST + col) * 2);
            *p0 = __floats2half2_rn(e0, e1);
            *p1 = __floats2half2_rn(e2, e3);
        }
#pragma unroll
        for (int o = 1; o <= 2; o <<= 1) {
            ls[mt][0] += __shfl_xor_sync(0xFFFFFFFFu, ls[mt][0], o);
            ls[mt][1] += __shfl_xor_sync(0xFFFFFFFFu, ls[mt][1], o);
        }
        if (tig == 0) {
            redsum[r0 * 4 + wn]       = ls[mt][0];
            redsum[(r0 + 8) * 4 + wn] = ls[mt][1];
        }
    }
    __syncthreads();

    if (wn == 0 && tig == 0) {
#pragma unroll
        for (int mt = 0; mt < 2; mt++)
#pragma unroll
            for (int hh = 0; hh < 2; hh++) {
                int r = wm * 32 + mt * 16 + gid + hh * 8;
                float t = redsum[r * 4] + redsum[r * 4 + 1]
                        + redsum[r * 4 + 2] + redsum[r * 4 + 3];
                rinv[r] = 1.f / t;
            }
    }
    __syncthreads();

    // ================= ctx: C[64][64] = P @ V (1-term) =================
    // warps: wm4(4) x wn2(2); warp tile 16m x 32n; K loop over 256 kp
    const int wm4 = wid >> 1;
    const int wn2 = wid & 1;

    float cc[4][4];
#pragma unroll
    for (int j = 0; j < 4; j++)
#pragma unroll
        for (int l = 0; l < 4; l++) cc[j][l] = 0.f;

#pragma unroll 4
    for (int kc = 0; kc < 256; kc += 16) {
        uint32_t af[4];
        uint32_t ad = smb + (uint32_t)((SPH + (wm4 * 16 + arow) * PST + kc + acol) * 2);
        LDSM4(af[0], af[1], af[2], af[3], ad);
        uint32_t bf[2][4];
#pragma unroll
        for (int p = 0; p < 2; p++) {
            uint32_t bd = smb + (uint32_t)((SVH + (kc + arow) * AST
                          + wn2 * 32 + p * 16 + acol) * 2);
            LDSM4T(bf[p][0], bf[p][1], bf[p][2], bf[p][3], bd);
        }
#pragma unroll
        for (int nt = 0; nt < 4; nt++) {
            const int p = nt >> 1, q = (nt & 1) * 2;
            MMA_F16(cc[nt], af, bf[p][q], bf[p][q + 1]);
        }
    }

    // epilogue: * rinv, fp16 store
    {
        int r0 = wm4 * 16 + gid;
        float i0 = rinv[r0], i1 = rinv[r0 + 8];
        size_t base0 = ((size_t)(b * SEQ + s0 + r0)) * EMB + h * KDIM;
        size_t base1 = base0 + (size_t)8 * EMB;
#pragma unroll
        for (int nt = 0; nt < 4; nt++) {
            int col = wn2 * 32 + nt * 8 + tig * 2;
            ushort2 o0, o1;
            o0.x = __half_as_ushort(__float2half_rn(cc[nt][0] * i0));
            o0.y = __half_as_ushort(__float2half_rn(cc[nt][1] * i0));
            o1.x = __half_as_ushort(__float2half_rn(cc[nt][2] * i1));
            o1.y = __half_as_ushort(__float2half_rn(cc[nt][3] * i1));
            *(ushort2*)(ctx_1 + base0 + col) = o0;
            *(ushort2*)(ctx_1 + base1 + col) = o1;
        }
    }
}

// ================================================================
// Launch
// ================================================================
extern "C" void kernel_launch(void* const* d_in, const int* in_sizes, int n_in,
                              void* d_out, int out_size)
{
    const float* query = (const float*)d_in[0];
    const float* value = (const float*)d_in[1];
    const float* Wq    = (const float*)d_in[2];
    const float* bq    = (const float*)d_in[3];
    const float* Wk    = (const float*)d_in[4];
    const float* bk    = (const float*)d_in[5];
    const float* Wv    = (const float*)d_in[6];
    const float* bv    = (const float*)d_in[7];
    const float* Wo    = (const float*)d_in[8];
    const float* bo    = (const float*)d_in[9];
    const float* E     = (const float*)d_in[10];
    const float* Eb    = (const float*)d_in[11];
    const float* F     = (const float*)d_in[12];
    const float* Fb    = (const float*)d_in[13];
    float* out = (float*)d_out;

    float *gq, *gkp, *gvp;
    ushort_t *qa1, *qa2, *va1, *va2, *ct1;
    ushort_t *kb1, *kb2, *vb1;
    ushort_t *wq1, *wq2, *wk1, *wk2, *wv1, *wv2, *wo1, *wo2;
    ushort_t *et1, *et2, *ft1, *ft2;
    cudaGetSymbolAddress((void**)&gq,  g_q);
    cudaGetSymbolAddress((void**)&gkp, g_kp);
    cudaGetSymbolAddress((void**)&gvp, g_vp);
    cudaGetSymbolAddress((void**)&qa1, g_qA_1);
    cudaGetSymbolAddress((void**)&qa2, g_qA_2);
    cudaGetSymbolAddress((void**)&va1, g_vA_1);
    cudaGetSymbolAddress((void**)&va2, g_vA_2);
    cudaGetSymbolAddress((void**)&ct1, g_ctx_1);
    cudaGetSymbolAddress((void**)&kb1, g_kb_1);
    cudaGetSymbolAddress((void**)&kb2, g_kb_2);
    cudaGetSymbolAddress((void**)&vb1, g_vb_1);
    cudaGetSymbolAddress((void**)&wq1, g_wqT_1);
    cudaGetSymbolAddress((void**)&wq2, g_wqT_2);
    cudaGetSymbolAddress((void**)&wk1, g_wkT_1);
    cudaGetSymbolAddress((void**)&wk2, g_wkT_2);
    cudaGetSymbolAddress((void**)&wv1, g_wvT_1);
    cudaGetSymbolAddress((void**)&wv2, g_wvT_2);
    cudaGetSymbolAddress((void**)&wo1, g_woT_1);
    cudaGetSymbolAddress((void**)&wo2, g_woT_2);
    cudaGetSymbolAddress((void**)&et1, g_ET1);
    cudaGetSymbolAddress((void**)&et2, g_ET2);
    cudaGetSymbolAddress((void**)&ft1, g_FT1);
    cudaGetSymbolAddress((void**)&ft2, g_FT2);

    // fp16 views over fp32 scratch
    ushort_t* qo1 = (ushort_t*)gq;
    ushort_t* qo2 = qo1 + (size_t)MROWS * EMB;
    ushort_t* kp1 = (ushort_t*)gkp;
    ushort_t* kp2 = kp1 + (size_t)BATCH * PROJK * EMB;
    ushort_t* vp1 = (ushort_t*)gvp;

    const float scale = 1.0f / 8.0f;
    const int nbig = MROWS * EMB;

    // splits
    split_kernel<<<nbig / 1024, 256>>>(query, qa1, qa2, nbig);
    split_kernel<<<nbig / 1024, 256>>>(value, va1, va2, nbig);

    // batched transposes
    TransJobs wjobs;
    wjobs.j[0] = {Wq, wq1, wq2};
    wjobs.j[1] = {Wk, wk1, wk2};
    wjobs.j[2] = {Wv, wv1, wv2};
    wjobs.j[3] = {Wo, wo1, wo2};
    dim3 tb(32, 8);
    split_transpose_b<<<dim3(EMB / 32, EMB / 32, 4), tb>>>(wjobs, EMB, EMB);

    TransJobs ejobs;
    ejobs.j[0] = {E, et1, et2};
    ejobs.j[1] = {F, ft1, ft2};
    ejobs.j[2] = {E, et1, et2};
    ejobs.j[3] = {F, ft1, ft2};
    split_transpose_b<<<dim3(PROJK / 32, SEQ / 32, 2), tb>>>(ejobs, SEQ, PROJK);

    // fused Q+K+V GEMM: Q 3-term -> fp16 split; K 3-term -> split; V 1-term -> fp16
    GJobs qkv;
    qkv.j[0] = {qa1, qa2, wq1, wq2, bq, 0, qo1, qo2, scale, 1, 3};
    qkv.j[1] = {va1, va2, wk1, wk2, bk, 0, kb1, kb2, 1.0f, 1, 3};
    qkv.j[2] = {va1, va2, wv1, wv2, bv, 0, vb1, 0,  1.0f, 2, 1};
    cudaFuncSetAttribute(mma_gemm7, cudaFuncAttributeMaxDynamicSharedMemorySize, NSTAGE * GSTG);
    dim3 g_qkv(EMB / 128, MROWS / 128, 3);
    mma_gemm7<<<g_qkv, 512, NSTAGE * GSTG>>>(qkv, EMB, EMB);

    // fused projections: K 3-term -> fp16 split; V 2-term -> fp16 single
    PJobs pj;
    pj.j[0] = {et1, et2, kb1, kb2, Eb, kp1, kp2, 3, 1};
    pj.j[1] = {ft1, ft2, vb1, 0,   Fb, vp1, 0,   2, 2};
    cudaFuncSetAttribute(proj_mma7, cudaFuncAttributeMaxDynamicSharedMemorySize, NSTAGE * PSTG);
    dim3 g_proj(EMB / 128, PROJK / 64, 8);
    proj_mma7<<<g_proj, 256, NSTAGE * PSTG>>>(pj);

    // tensor-core attention
    cudaFuncSetAttribute(attn_mma, cudaFuncAttributeMaxDynamicSharedMemorySize, ATTN_SMEM);
    dim3 attn_grid(SEQ / 64, HEADS, BATCH);
    attn_mma<<<attn_grid, 256, ATTN_SMEM>>>(qo1, qo2, kp1, kp2, vp1, ct1);

    // output projection: 1-term fp16 (post-softmax linear path)
    GJobs oj;
    oj.j[0] = {ct1, ct1, wo1, wo2, bo, out, 0, 0, 1.0f, 0, 1};
    oj.j[1] = oj.j[0];
    oj.j[2] = oj.j[0];
    dim3 g_out(EMB / 128, MROWS / 128, 1);
    mma_gemm7<<<g_out, 512, NSTAGE * GSTG>>>(oj, EMB, EMB);
}